// round 3
// baseline (speedup 1.0000x reference)
#include <cuda_runtime.h>

#define Cc 256
#define Hf 128
#define Wf 128
#define Bn 4
#define Nroi 512
#define Pp 4
#define NTOK (Nroi*49)              // 25088
#define FSZ (Bn*Cc*Hf*Wf)           // 16777216

// ---- scratch (device globals: allocation-free) ----
__device__ float g_ft[FSZ];         // features transposed to [b][h*W+w][c]
__device__ float g_smix[NTOK*Cc];   // attn-mixed samples
__device__ float g_tmp2[Cc*NTOK];   // GEMM output [g][b]
__device__ float g_Mk[Cc*Cc];
__device__ float g_Mv[Cc*Cc];
__device__ float g_M [Cc*Cc];
__device__ float g_Qb[49*Cc];
__device__ float g_Qk[49*Cc];
__device__ float g_cv[Cc];
__device__ float g_bias[Cc];

// ---------- precompute stage 1: Mk = Wk@w_proj, Mv = Wv@w_proj ----------
__global__ void pre1(const float* __restrict__ in_proj_w,
                     const float* __restrict__ w_proj) {
    int i = blockIdx.x;           // 0..511
    int j = threadIdx.x;          // 0..255
    const float* A = (i < Cc) ? (in_proj_w + Cc*Cc + i*Cc)
                              : (in_proj_w + 2*Cc*Cc + (i-Cc)*Cc);
    float a0=0.f,a1=0.f,a2=0.f,a3=0.f;
    #pragma unroll 4
    for (int k = 0; k < Cc; k += 4) {
        a0 += A[k+0]*w_proj[(k+0)*Cc+j];
        a1 += A[k+1]*w_proj[(k+1)*Cc+j];
        a2 += A[k+2]*w_proj[(k+2)*Cc+j];
        a3 += A[k+3]*w_proj[(k+3)*Cc+j];
    }
    float acc = (a0+a1)+(a2+a3);
    if (i < Cc) g_Mk[i*Cc+j] = acc; else g_Mv[(i-Cc)*Cc+j] = acc;
}

// ---------- precompute stage 2: M = Wo@Mv, cv = Wv@b_proj+bv, Qb ----------
__global__ void pre2(const float* __restrict__ in_proj_w,
                     const float* __restrict__ in_proj_b,
                     const float* __restrict__ out_proj_w,
                     const float* __restrict__ b_proj,
                     const float* __restrict__ queries) {
    int i = blockIdx.x;           // 0..305
    int j = threadIdx.x;
    if (i < Cc) {                 // M row
        const float* A = out_proj_w + i*Cc;
        float a0=0.f,a1=0.f,a2=0.f,a3=0.f;
        #pragma unroll 4
        for (int k = 0; k < Cc; k += 4) {
            a0 += A[k+0]*g_Mv[(k+0)*Cc+j];
            a1 += A[k+1]*g_Mv[(k+1)*Cc+j];
            a2 += A[k+2]*g_Mv[(k+2)*Cc+j];
            a3 += A[k+3]*g_Mv[(k+3)*Cc+j];
        }
        g_M[i*Cc+j] = (a0+a1)+(a2+a3);
    } else if (i == Cc) {         // cv[j]
        const float* Wv = in_proj_w + 2*Cc*Cc;
        float acc = 0.f;
        for (int k = 0; k < Cc; k++) acc += Wv[j*Cc+k]*b_proj[k];
        g_cv[j] = acc + in_proj_b[2*Cc + j];
    } else {                      // Qb row pos = i-257
        int pos = i - Cc - 1;
        const float* q  = queries + pos*Cc;
        const float* Wq = in_proj_w;  // [e][d]
        float acc = 0.f;
        for (int k = 0; k < Cc; k++) acc += q[k]*Wq[j*Cc+k];
        g_Qb[pos*Cc+j] = acc + in_proj_b[j];
    }
}

// ---------- precompute stage 3: bias = Wo@cv+bo, Qk = (1/16) Qb@Mk ----------
__global__ void pre3(const float* __restrict__ out_proj_w,
                     const float* __restrict__ out_proj_b) {
    int i = blockIdx.x;           // 0..49
    int j = threadIdx.x;
    if (i == 0) {
        float acc = 0.f;
        for (int k = 0; k < Cc; k++) acc += out_proj_w[j*Cc+k]*g_cv[k];
        g_bias[j] = acc + out_proj_b[j];
    } else {
        int pos = i - 1;
        float a0=0.f,a1=0.f,a2=0.f,a3=0.f;
        #pragma unroll 4
        for (int k = 0; k < Cc; k += 4) {
            a0 += g_Qb[pos*Cc+k+0]*g_Mk[(k+0)*Cc+j];
            a1 += g_Qb[pos*Cc+k+1]*g_Mk[(k+1)*Cc+j];
            a2 += g_Qb[pos*Cc+k+2]*g_Mk[(k+2)*Cc+j];
            a3 += g_Qb[pos*Cc+k+3]*g_Mk[(k+3)*Cc+j];
        }
        g_Qk[pos*Cc+j] = ((a0+a1)+(a2+a3)) * 0.0625f;   // d^-0.5, d=256
    }
}

// ---------- features (B,C,H,W) -> (B,H*W,C) ----------
__global__ void transpose_feat(const float* __restrict__ feat) {
    __shared__ float tile[32][33];
    int b   = blockIdx.z;
    int hw0 = blockIdx.x * 32;
    int c0  = blockIdx.y * 32;
    int tx = threadIdx.x, ty = threadIdx.y;
    const float* src = feat + (size_t)b*Cc*Hf*Wf;
    float*       dst = g_ft + (size_t)b*Hf*Wf*Cc;
    #pragma unroll
    for (int u = 0; u < 4; u++)
        tile[ty+u*8][tx] = src[(size_t)(c0+ty+u*8)*(Hf*Wf) + hw0+tx];
    __syncthreads();
    #pragma unroll
    for (int u = 0; u < 4; u++)
        dst[(size_t)(hw0+ty+u*8)*Cc + c0+tx] = tile[tx][ty+u*8];
}

// ---------- fused sampling + scores + softmax + mix ----------
__global__ void __launch_bounds__(256) sample_attn(const float* __restrict__ rois,
                                                   const float* __restrict__ offs) {
    int b = blockIdx.x;               // token 0..25087
    int c = threadIdx.x;              // channel
    int n = b / 49, pos = b - n*49;
    int oi = pos / 7, oj = pos - oi*7;

    const float* roi = rois + n*5;
    int   bidx = (int)roi[0];
    float x1 = roi[1]*0.0625f - 0.5f;
    float y1 = roi[2]*0.0625f - 0.5f;
    float rw = roi[3]*0.0625f - 0.5f - x1;
    float rh = roi[4]*0.0625f - 0.5f - y1;
    float bw = rw * (1.0f/7.0f);
    float bh = rh * (1.0f/7.0f);
    const float* fb = g_ft + (size_t)bidx*(Hf*Wf*Cc);

    float qk = g_Qk[pos*Cc + c];
    float vals[Pp];
    float sc[Pp];
    #pragma unroll
    for (int p = 0; p < Pp; p++) {
        float odw = offs[((p*7+oi)*7+oj)*2 + 0];
        float odh = offs[((p*7+oi)*7+oj)*2 + 1];
        float x = x1 + (oj + 0.5f)*bw + 0.1f*rw*odw;
        float y = y1 + (oi + 0.5f)*bh + 0.1f*rh*odh;
        bool valid = (y > -1.0f) && (y < (float)Hf) && (x > -1.0f) && (x < (float)Wf);
        float yc = fminf(fmaxf(y, 0.f), (float)(Hf-1));
        float xc = fminf(fmaxf(x, 0.f), (float)(Wf-1));
        int y0 = (int)floorf(yc), x0 = (int)floorf(xc);
        int y1i = min(y0+1, Hf-1), x1i = min(x0+1, Wf-1);
        float ly = yc - (float)y0, lx = xc - (float)x0;
        float hy = 1.f - ly,       hx = 1.f - lx;
        const float* p00 = fb + ((size_t)(y0 *Wf + x0 ))*Cc + c;
        const float* p01 = fb + ((size_t)(y0 *Wf + x1i))*Cc + c;
        const float* p10 = fb + ((size_t)(y1i*Wf + x0 ))*Cc + c;
        const float* p11 = fb + ((size_t)(y1i*Wf + x1i))*Cc + c;
        float v = hy*hx*(*p00) + hy*lx*(*p01) + ly*hx*(*p10) + ly*lx*(*p11);
        v = valid ? v : 0.f;
        vals[p] = v;
        sc[p] = qk * v;
    }
    // block-reduce the 4 score dot-products
    #pragma unroll
    for (int off = 16; off; off >>= 1) {
        #pragma unroll
        for (int p = 0; p < Pp; p++) sc[p] += __shfl_down_sync(0xffffffffu, sc[p], off);
    }
    __shared__ float red[8][Pp];
    int wid = c >> 5, lid = c & 31;
    if (lid == 0) {
        #pragma unroll
        for (int p = 0; p < Pp; p++) red[wid][p] = sc[p];
    }
    __syncthreads();
    float s[Pp];
    #pragma unroll
    for (int p = 0; p < Pp; p++) {
        float a = 0.f;
        #pragma unroll
        for (int w = 0; w < 8; w++) a += red[w][p];
        s[p] = a;
    }
    float m = fmaxf(fmaxf(s[0], s[1]), fmaxf(s[2], s[3]));
    float e[Pp], sum = 0.f;
    #pragma unroll
    for (int p = 0; p < Pp; p++) { e[p] = __expf(s[p]-m); sum += e[p]; }
    float inv = 1.f/sum;
    float mix = 0.f;
    #pragma unroll
    for (int p = 0; p < Pp; p++) mix += (e[p]*inv)*vals[p];
    g_smix[(size_t)b*Cc + c] = mix;
}

// ---------- tmp2[g][b] = sum_c M[g,c]*smix[b,c] + bias[g] ----------
// BM=64 (g) x BN=128 (b) x BK=16, 256 threads, 4x8 micro-tile
__global__ void __launch_bounds__(256) gemm_out() {
    __shared__ float As[16][68];
    __shared__ float Bs[16][136];
    int b0 = blockIdx.x * 128;
    int g0 = blockIdx.y * 64;
    int t  = threadIdx.x;
    int tx = t & 15;       // b micro
    int ty = t >> 4;       // g micro
    float acc[4][8];
    #pragma unroll
    for (int j = 0; j < 4; j++)
        #pragma unroll
        for (int i = 0; i < 8; i++) acc[j][i] = 0.f;

    int lr = t >> 2;             // 0..63
    int lc = (t & 3) << 2;       // 0,4,8,12
    const float* Ap  = g_M    + (size_t)(g0 + lr)*Cc + lc;
    const float* Bp0 = g_smix + (size_t)(b0 + lr)*Cc + lc;
    const float* Bp1 = g_smix + (size_t)(b0 + 64 + lr)*Cc + lc;

    for (int k0 = 0; k0 < Cc; k0 += 16) {
        float4 a  = *(const float4*)(Ap  + k0);
        float4 v0 = *(const float4*)(Bp0 + k0);
        float4 v1 = *(const float4*)(Bp1 + k0);
        As[lc+0][lr]=a.x;  As[lc+1][lr]=a.y;  As[lc+2][lr]=a.z;  As[lc+3][lr]=a.w;
        Bs[lc+0][lr]=v0.x; Bs[lc+1][lr]=v0.y; Bs[lc+2][lr]=v0.z; Bs[lc+3][lr]=v0.w;
        Bs[lc+0][64+lr]=v1.x; Bs[lc+1][64+lr]=v1.y; Bs[lc+2][64+lr]=v1.z; Bs[lc+3][64+lr]=v1.w;
        __syncthreads();
        #pragma unroll
        for (int k = 0; k < 16; k++) {
            float ra[4], rb[8];
            #pragma unroll
            for (int j = 0; j < 4; j++) ra[j] = As[k][ty*4+j];
            #pragma unroll
            for (int i = 0; i < 8; i++) rb[i] = Bs[k][tx*8+i];
            #pragma unroll
            for (int j = 0; j < 4; j++)
                #pragma unroll
                for (int i = 0; i < 8; i++) acc[j][i] += ra[j]*rb[i];
        }
        __syncthreads();
    }
    #pragma unroll
    for (int j = 0; j < 4; j++) {
        int g = g0 + ty*4 + j;
        float bb = g_bias[g];
        float* o = g_tmp2 + (size_t)g*NTOK + b0 + tx*8;
        float4 o0 = make_float4(acc[j][0]+bb, acc[j][1]+bb, acc[j][2]+bb, acc[j][3]+bb);
        float4 o1 = make_float4(acc[j][4]+bb, acc[j][5]+bb, acc[j][6]+bb, acc[j][7]+bb);
        *(float4*)(o)     = o0;
        *(float4*)(o + 4) = o1;
    }
}

// ---------- tmp2[g][n*49+pos] -> out[((n*C+g)*49)+pos] ----------
__global__ void reorder(float* __restrict__ out) {
    int idx = blockIdx.x*256 + threadIdx.x;
    int pos = idx % 49;
    int t   = idx / 49;
    int g   = t % Cc;
    int n   = t / Cc;
    out[idx] = g_tmp2[(size_t)g*NTOK + n*49 + pos];
}

extern "C" void kernel_launch(void* const* d_in, const int* in_sizes, int n_in,
                              void* d_out, int out_size) {
    const float* features   = (const float*)d_in[0];
    const float* rois       = (const float*)d_in[1];
    const float* offs       = (const float*)d_in[2];
    const float* queries    = (const float*)d_in[3];
    const float* w_proj     = (const float*)d_in[4];
    const float* b_proj     = (const float*)d_in[5];
    const float* in_proj_w  = (const float*)d_in[6];
    const float* in_proj_b  = (const float*)d_in[7];
    const float* out_proj_w = (const float*)d_in[8];
    const float* out_proj_b = (const float*)d_in[9];
    float* out = (float*)d_out;

    pre1<<<512, 256>>>(in_proj_w, w_proj);
    pre2<<<306, 256>>>(in_proj_w, in_proj_b, out_proj_w, b_proj, queries);
    pre3<<<50, 256>>>(out_proj_w, out_proj_b);
    transpose_feat<<<dim3(Hf*Wf/32, Cc/32, Bn), dim3(32, 8)>>>(features);
    sample_attn<<<NTOK, 256>>>(rois, offs);
    gemm_out<<<dim3(NTOK/128, Cc/64), 256>>>();
    reorder<<<NTOK, 256>>>(out);
}

// round 5
// speedup vs baseline: 1.1059x; 1.1059x over previous
#include <cuda_runtime.h>

#define Cc 256
#define Hf 128
#define Wf 128
#define Bn 4
#define Nroi 512
#define Pp 4
#define NTOK (Nroi*49)              // 25088
#define FSZ (Bn*Cc*Hf*Wf)           // 16777216

// ---- scratch (device globals: allocation-free) ----
__device__ float g_ft[FSZ];         // features transposed to [b][h*W+w][c]
__device__ float g_smix[NTOK*Cc];   // attn-mixed samples [b][c]
__device__ float g_Mk[Cc*Cc];
__device__ float g_Mv[Cc*Cc];
__device__ float g_M [Cc*Cc];
__device__ float g_Qb[49*Cc];
__device__ float g_Qk[49*Cc];
__device__ float g_cv[Cc];
__device__ float g_bias[Cc];

// ---------- precompute stage 1: Mk = Wk@w_proj, Mv = Wv@w_proj ----------
__global__ void pre1(const float* __restrict__ in_proj_w,
                     const float* __restrict__ w_proj) {
    int i = blockIdx.x;           // 0..511
    int j = threadIdx.x;          // 0..255
    const float* A = (i < Cc) ? (in_proj_w + Cc*Cc + i*Cc)
                              : (in_proj_w + 2*Cc*Cc + (i-Cc)*Cc);
    float a0=0.f,a1=0.f,a2=0.f,a3=0.f;
    #pragma unroll 4
    for (int k = 0; k < Cc; k += 4) {
        a0 += A[k+0]*w_proj[(k+0)*Cc+j];
        a1 += A[k+1]*w_proj[(k+1)*Cc+j];
        a2 += A[k+2]*w_proj[(k+2)*Cc+j];
        a3 += A[k+3]*w_proj[(k+3)*Cc+j];
    }
    float acc = (a0+a1)+(a2+a3);
    if (i < Cc) g_Mk[i*Cc+j] = acc; else g_Mv[(i-Cc)*Cc+j] = acc;
}

// ---------- precompute stage 2: M = Wo@Mv, cv = Wv@b_proj+bv, Qb ----------
__global__ void pre2(const float* __restrict__ in_proj_w,
                     const float* __restrict__ in_proj_b,
                     const float* __restrict__ out_proj_w,
                     const float* __restrict__ b_proj,
                     const float* __restrict__ queries) {
    int i = blockIdx.x;           // 0..305
    int j = threadIdx.x;
    if (i < Cc) {                 // M row
        const float* A = out_proj_w + i*Cc;
        float a0=0.f,a1=0.f,a2=0.f,a3=0.f;
        #pragma unroll 4
        for (int k = 0; k < Cc; k += 4) {
            a0 += A[k+0]*g_Mv[(k+0)*Cc+j];
            a1 += A[k+1]*g_Mv[(k+1)*Cc+j];
            a2 += A[k+2]*g_Mv[(k+2)*Cc+j];
            a3 += A[k+3]*g_Mv[(k+3)*Cc+j];
        }
        g_M[i*Cc+j] = (a0+a1)+(a2+a3);
    } else if (i == Cc) {         // cv[j]
        const float* Wv = in_proj_w + 2*Cc*Cc;
        float acc = 0.f;
        for (int k = 0; k < Cc; k++) acc += Wv[j*Cc+k]*b_proj[k];
        g_cv[j] = acc + in_proj_b[2*Cc + j];
    } else {                      // Qb row pos = i-257
        int pos = i - Cc - 1;
        const float* q  = queries + pos*Cc;
        const float* Wq = in_proj_w;  // [e][d]
        float acc = 0.f;
        for (int k = 0; k < Cc; k++) acc += q[k]*Wq[j*Cc+k];
        g_Qb[pos*Cc+j] = acc + in_proj_b[j];
    }
}

// ---------- precompute stage 3: bias = Wo@cv+bo, Qk = (1/16) Qb@Mk ----------
__global__ void pre3(const float* __restrict__ out_proj_w,
                     const float* __restrict__ out_proj_b) {
    int i = blockIdx.x;           // 0..49
    int j = threadIdx.x;
    if (i == 0) {
        float acc = 0.f;
        for (int k = 0; k < Cc; k++) acc += out_proj_w[j*Cc+k]*g_cv[k];
        g_bias[j] = acc + out_proj_b[j];
    } else {
        int pos = i - 1;
        float a0=0.f,a1=0.f,a2=0.f,a3=0.f;
        #pragma unroll 4
        for (int k = 0; k < Cc; k += 4) {
            a0 += g_Qb[pos*Cc+k+0]*g_Mk[(k+0)*Cc+j];
            a1 += g_Qb[pos*Cc+k+1]*g_Mk[(k+1)*Cc+j];
            a2 += g_Qb[pos*Cc+k+2]*g_Mk[(k+2)*Cc+j];
            a3 += g_Qb[pos*Cc+k+3]*g_Mk[(k+3)*Cc+j];
        }
        g_Qk[pos*Cc+j] = ((a0+a1)+(a2+a3)) * 0.0625f;   // d^-0.5, d=256
    }
}

// ---------- features (B,C,H,W) -> (B,H*W,C) ----------
__global__ void transpose_feat(const float* __restrict__ feat) {
    __shared__ float tile[32][33];
    int b   = blockIdx.z;
    int hw0 = blockIdx.x * 32;
    int c0  = blockIdx.y * 32;
    int tx = threadIdx.x, ty = threadIdx.y;
    const float* src = feat + (size_t)b*Cc*Hf*Wf;
    float*       dst = g_ft + (size_t)b*Hf*Wf*Cc;
    #pragma unroll
    for (int u = 0; u < 4; u++)
        tile[ty+u*8][tx] = src[(size_t)(c0+ty+u*8)*(Hf*Wf) + hw0+tx];
    __syncthreads();
    #pragma unroll
    for (int u = 0; u < 4; u++)
        dst[(size_t)(hw0+ty+u*8)*Cc + c0+tx] = tile[tx][ty+u*8];
}

// ---------- fused sampling + scores + softmax + mix ----------
__global__ void __launch_bounds__(256) sample_attn(const float* __restrict__ rois,
                                                   const float* __restrict__ offs) {
    int b = blockIdx.x;               // token 0..25087
    int c = threadIdx.x;              // channel
    int n = b / 49, pos = b - n*49;
    int oi = pos / 7, oj = pos - oi*7;

    const float* roi = rois + n*5;
    int   bidx = (int)roi[0];
    float x1 = roi[1]*0.0625f - 0.5f;
    float y1 = roi[2]*0.0625f - 0.5f;
    float rw = roi[3]*0.0625f - 0.5f - x1;
    float rh = roi[4]*0.0625f - 0.5f - y1;
    float bw = rw * (1.0f/7.0f);
    float bh = rh * (1.0f/7.0f);
    const float* fb = g_ft + (size_t)bidx*(Hf*Wf*Cc);

    float qk = g_Qk[pos*Cc + c];
    float vals[Pp];
    float sc[Pp];
    #pragma unroll
    for (int p = 0; p < Pp; p++) {
        float odw = offs[((p*7+oi)*7+oj)*2 + 0];
        float odh = offs[((p*7+oi)*7+oj)*2 + 1];
        float x = x1 + (oj + 0.5f)*bw + 0.1f*rw*odw;
        float y = y1 + (oi + 0.5f)*bh + 0.1f*rh*odh;
        bool valid = (y > -1.0f) && (y < (float)Hf) && (x > -1.0f) && (x < (float)Wf);
        float yc = fminf(fmaxf(y, 0.f), (float)(Hf-1));
        float xc = fminf(fmaxf(x, 0.f), (float)(Wf-1));
        int y0 = (int)floorf(yc), x0 = (int)floorf(xc);
        int y1i = min(y0+1, Hf-1), x1i = min(x0+1, Wf-1);
        float ly = yc - (float)y0, lx = xc - (float)x0;
        float hy = 1.f - ly,       hx = 1.f - lx;
        const float* p00 = fb + ((size_t)(y0 *Wf + x0 ))*Cc + c;
        const float* p01 = fb + ((size_t)(y0 *Wf + x1i))*Cc + c;
        const float* p10 = fb + ((size_t)(y1i*Wf + x0 ))*Cc + c;
        const float* p11 = fb + ((size_t)(y1i*Wf + x1i))*Cc + c;
        float v = hy*hx*(*p00) + hy*lx*(*p01) + ly*hx*(*p10) + ly*lx*(*p11);
        v = valid ? v : 0.f;
        vals[p] = v;
        sc[p] = qk * v;
    }
    // block-reduce the 4 score dot-products
    #pragma unroll
    for (int off = 16; off; off >>= 1) {
        #pragma unroll
        for (int p = 0; p < Pp; p++) sc[p] += __shfl_down_sync(0xffffffffu, sc[p], off);
    }
    __shared__ float red[8][Pp];
    int wid = c >> 5, lid = c & 31;
    if (lid == 0) {
        #pragma unroll
        for (int p = 0; p < Pp; p++) red[wid][p] = sc[p];
    }
    __syncthreads();
    float s[Pp];
    #pragma unroll
    for (int p = 0; p < Pp; p++) {
        float a = 0.f;
        #pragma unroll
        for (int w = 0; w < 8; w++) a += red[w][p];
        s[p] = a;
    }
    float m = fmaxf(fmaxf(s[0], s[1]), fmaxf(s[2], s[3]));
    float e[Pp], sum = 0.f;
    #pragma unroll
    for (int p = 0; p < Pp; p++) { e[p] = __expf(s[p]-m); sum += e[p]; }
    float inv = 1.f/sum;
    float mix = 0.f;
    #pragma unroll
    for (int p = 0; p < Pp; p++) mix += (e[p]*inv)*vals[p];
    g_smix[(size_t)b*Cc + c] = mix;
}

// ---------- out[n][g][pos] = sum_c M[g,c]*smix[b,c] + bias[g],  b=n*49+pos ----------
// 128x128x8 double-buffered SGEMM, 256 threads, 8x8 micro-tile, fused reorder epilogue
__global__ void __launch_bounds__(256) gemm_out(float* __restrict__ out) {
    __shared__ float As[2][8][132];
    __shared__ float Bs[2][8][132];
    int b0 = blockIdx.x * 128;      // token tile
    int g0 = blockIdx.y * 128;      // output-channel tile
    int t  = threadIdx.x;
    int tx = t & 15;                // b micro (8 tokens)
    int ty = t >> 4;                // g micro (8 channels)

    // gmem load mapping: 2 threads per row, float4 each (8 k per row-pair)
    int lr = t >> 1;                // 0..127 row in tile
    int lk = (t & 1) * 4;           // 0 or 4
    const float* Ap = g_M    + (size_t)(g0 + lr)*Cc + lk;
    const float* Bp = g_smix + (size_t)(b0 + lr)*Cc + lk;

    float acc[8][8];
    #pragma unroll
    for (int j = 0; j < 8; j++)
        #pragma unroll
        for (int i = 0; i < 8; i++) acc[j][i] = 0.f;

    // prologue: load k-tile 0
    float4 pa = *(const float4*)(Ap);
    float4 pb = *(const float4*)(Bp);
    As[0][lk+0][lr]=pa.x; As[0][lk+1][lr]=pa.y; As[0][lk+2][lr]=pa.z; As[0][lk+3][lr]=pa.w;
    Bs[0][lk+0][lr]=pb.x; Bs[0][lk+1][lr]=pb.y; Bs[0][lk+2][lr]=pb.z; Bs[0][lk+3][lr]=pb.w;
    __syncthreads();

    int buf = 0;
    #pragma unroll 1
    for (int k0 = 0; k0 < Cc; k0 += 8) {
        bool more = (k0 + 8) < Cc;
        if (more) {
            pa = *(const float4*)(Ap + k0 + 8);
            pb = *(const float4*)(Bp + k0 + 8);
        }
        #pragma unroll
        for (int k = 0; k < 8; k++) {
            float4 a0 = *(const float4*)&As[buf][k][ty*8];
            float4 a1 = *(const float4*)&As[buf][k][ty*8+4];
            float4 v0 = *(const float4*)&Bs[buf][k][tx*8];
            float4 v1 = *(const float4*)&Bs[buf][k][tx*8+4];
            float ra[8] = {a0.x,a0.y,a0.z,a0.w,a1.x,a1.y,a1.z,a1.w};
            float rb[8] = {v0.x,v0.y,v0.z,v0.w,v1.x,v1.y,v1.z,v1.w};
            #pragma unroll
            for (int j = 0; j < 8; j++)
                #pragma unroll
                for (int i = 0; i < 8; i++) acc[j][i] += ra[j]*rb[i];
        }
        if (more) {
            int nb = buf ^ 1;
            As[nb][lk+0][lr]=pa.x; As[nb][lk+1][lr]=pa.y; As[nb][lk+2][lr]=pa.z; As[nb][lk+3][lr]=pa.w;
            Bs[nb][lk+0][lr]=pb.x; Bs[nb][lk+1][lr]=pb.y; Bs[nb][lk+2][lr]=pb.z; Bs[nb][lk+3][lr]=pb.w;
            __syncthreads();
            buf = nb;
        }
    }

    // fused epilogue: bias + reorder to out[((n*Cc+g)*49)+pos]
    int bbase = b0 + tx*8;
    int n0   = bbase / 49;
    int pos0 = bbase - n0*49;
    #pragma unroll
    for (int j = 0; j < 8; j++) {
        int g = g0 + ty*8 + j;
        float bb = g_bias[g];
        size_t base = (size_t)n0*(Cc*49) + (size_t)g*49;
        int pos = pos0;
        #pragma unroll
        for (int i = 0; i < 8; i++) {
            out[base + pos] = acc[j][i] + bb;
            if (++pos == 49) { pos = 0; base += (size_t)Cc*49; }
        }
    }
}

extern "C" void kernel_launch(void* const* d_in, const int* in_sizes, int n_in,
                              void* d_out, int out_size) {
    const float* features   = (const float*)d_in[0];
    const float* rois       = (const float*)d_in[1];
    const float* offs       = (const float*)d_in[2];
    const float* queries    = (const float*)d_in[3];
    const float* w_proj     = (const float*)d_in[4];
    const float* b_proj     = (const float*)d_in[5];
    const float* in_proj_w  = (const float*)d_in[6];
    const float* in_proj_b  = (const float*)d_in[7];
    const float* out_proj_w = (const float*)d_in[8];
    const float* out_proj_b = (const float*)d_in[9];
    float* out = (float*)d_out;

    pre1<<<512, 256>>>(in_proj_w, w_proj);
    pre2<<<306, 256>>>(in_proj_w, in_proj_b, out_proj_w, b_proj, queries);
    pre3<<<50, 256>>>(out_proj_w, out_proj_b);
    transpose_feat<<<dim3(Hf*Wf/32, Cc/32, Bn), dim3(32, 8)>>>(features);
    sample_attn<<<NTOK, 256>>>(rois, offs);
    gemm_out<<<dim3(NTOK/128, Cc/128), 256>>>(out);
}

// round 7
// speedup vs baseline: 1.3916x; 1.2584x over previous
#include <cuda_runtime.h>
#include <cuda_bf16.h>
#include <cstdint>

#define Cc 256
#define Hf 128
#define Wf 128
#define Bn 4
#define Nroi 512
#define Pp 4
#define NTOK (Nroi*49)              // 25088
#define FSZ (Bn*Cc*Hf*Wf)           // 16777216

// ---- scratch (device globals: allocation-free) ----
__device__ float g_ft[FSZ];                  // features transposed to [b][h*W+w][c]
__device__ __nv_bfloat16 g_sh[NTOK*Cc];      // smix hi
__device__ __nv_bfloat16 g_sl[NTOK*Cc];      // smix lo
__device__ __nv_bfloat16 g_Mhi[Cc*Cc];
__device__ __nv_bfloat16 g_Mlo[Cc*Cc];
__device__ float g_Mk[Cc*Cc];
__device__ float g_Mv[Cc*Cc];
__device__ float g_Qb[49*Cc];
__device__ float g_Qk[49*Cc];
__device__ float g_cv[Cc];
__device__ float g_bias[Cc];

__device__ __forceinline__ uint32_t smem_u32(const void* p) {
    uint32_t a;
    asm("{ .reg .u64 t; cvta.to.shared.u64 t, %1; cvt.u32.u64 %0, t; }" : "=r"(a) : "l"(p));
    return a;
}
__device__ __forceinline__ void ldsm4(uint32_t* r, uint32_t addr) {
    asm volatile("ldmatrix.sync.aligned.m8n8.x4.shared.b16 {%0,%1,%2,%3}, [%4];"
        : "=r"(r[0]), "=r"(r[1]), "=r"(r[2]), "=r"(r[3]) : "r"(addr));
}
__device__ __forceinline__ void mma16816(float* c, const uint32_t* a, uint32_t b0, uint32_t b1) {
    asm volatile("mma.sync.aligned.m16n8k16.row.col.f32.bf16.bf16.f32 "
        "{%0,%1,%2,%3}, {%4,%5,%6,%7}, {%8,%9}, {%0,%1,%2,%3};"
        : "+f"(c[0]), "+f"(c[1]), "+f"(c[2]), "+f"(c[3])
        : "r"(a[0]), "r"(a[1]), "r"(a[2]), "r"(a[3]), "r"(b0), "r"(b1));
}

#define TSTRIDE 136                         // bf16 per row (128 + 8 pad)
#define TILE_BYTES (128*TSTRIDE*2)          // 34816
#define SMEM_DYN (4*TILE_BYTES)             // 139264

// ---------- precompute stage 1: Mk = Wk@w_proj, Mv = Wv@w_proj ----------
__global__ void pre1(const float* __restrict__ in_proj_w,
                     const float* __restrict__ w_proj) {
    int i = blockIdx.x;           // 0..511
    int j = threadIdx.x;          // 0..255
    const float* A = (i < Cc) ? (in_proj_w + Cc*Cc + i*Cc)
                              : (in_proj_w + 2*Cc*Cc + (i-Cc)*Cc);
    float a0=0.f,a1=0.f,a2=0.f,a3=0.f;
    #pragma unroll 4
    for (int k = 0; k < Cc; k += 4) {
        a0 += A[k+0]*w_proj[(k+0)*Cc+j];
        a1 += A[k+1]*w_proj[(k+1)*Cc+j];
        a2 += A[k+2]*w_proj[(k+2)*Cc+j];
        a3 += A[k+3]*w_proj[(k+3)*Cc+j];
    }
    float acc = (a0+a1)+(a2+a3);
    if (i < Cc) g_Mk[i*Cc+j] = acc; else g_Mv[(i-Cc)*Cc+j] = acc;
}

// ---------- precompute stage 2: M = Wo@Mv (hi/lo bf16), cv, Qb ----------
__global__ void pre2(const float* __restrict__ in_proj_w,
                     const float* __restrict__ in_proj_b,
                     const float* __restrict__ out_proj_w,
                     const float* __restrict__ b_proj,
                     const float* __restrict__ queries) {
    int i = blockIdx.x;           // 0..305
    int j = threadIdx.x;
    if (i < Cc) {                 // M row -> hi/lo split
        const float* A = out_proj_w + i*Cc;
        float a0=0.f,a1=0.f,a2=0.f,a3=0.f;
        #pragma unroll 4
        for (int k = 0; k < Cc; k += 4) {
            a0 += A[k+0]*g_Mv[(k+0)*Cc+j];
            a1 += A[k+1]*g_Mv[(k+1)*Cc+j];
            a2 += A[k+2]*g_Mv[(k+2)*Cc+j];
            a3 += A[k+3]*g_Mv[(k+3)*Cc+j];
        }
        float acc = (a0+a1)+(a2+a3);
        __nv_bfloat16 h = __float2bfloat16(acc);
        g_Mhi[i*Cc+j] = h;
        g_Mlo[i*Cc+j] = __float2bfloat16(acc - __bfloat162float(h));
    } else if (i == Cc) {         // cv[j]
        const float* Wv = in_proj_w + 2*Cc*Cc;
        float acc = 0.f;
        for (int k = 0; k < Cc; k++) acc += Wv[j*Cc+k]*b_proj[k];
        g_cv[j] = acc + in_proj_b[2*Cc + j];
    } else {                      // Qb row pos = i-257
        int pos = i - Cc - 1;
        const float* q  = queries + pos*Cc;
        const float* Wq = in_proj_w;
        float acc = 0.f;
        for (int k = 0; k < Cc; k++) acc += q[k]*Wq[j*Cc+k];
        g_Qb[pos*Cc+j] = acc + in_proj_b[j];
    }
}

// ---------- precompute stage 3: bias = Wo@cv+bo, Qk = (1/16) Qb@Mk ----------
__global__ void pre3(const float* __restrict__ out_proj_w,
                     const float* __restrict__ out_proj_b) {
    int i = blockIdx.x;           // 0..49
    int j = threadIdx.x;
    if (i == 0) {
        float acc = 0.f;
        for (int k = 0; k < Cc; k++) acc += out_proj_w[j*Cc+k]*g_cv[k];
        g_bias[j] = acc + out_proj_b[j];
    } else {
        int pos = i - 1;
        float a0=0.f,a1=0.f,a2=0.f,a3=0.f;
        #pragma unroll 4
        for (int k = 0; k < Cc; k += 4) {
            a0 += g_Qb[pos*Cc+k+0]*g_Mk[(k+0)*Cc+j];
            a1 += g_Qb[pos*Cc+k+1]*g_Mk[(k+1)*Cc+j];
            a2 += g_Qb[pos*Cc+k+2]*g_Mk[(k+2)*Cc+j];
            a3 += g_Qb[pos*Cc+k+3]*g_Mk[(k+3)*Cc+j];
        }
        g_Qk[pos*Cc+j] = ((a0+a1)+(a2+a3)) * 0.0625f;
    }
}

// ---------- features (B,C,H,W) -> (B,H*W,C) ----------
__global__ void transpose_feat(const float* __restrict__ feat) {
    __shared__ float tile[32][33];
    int b   = blockIdx.z;
    int hw0 = blockIdx.x * 32;
    int c0  = blockIdx.y * 32;
    int tx = threadIdx.x, ty = threadIdx.y;
    const float* src = feat + (size_t)b*Cc*Hf*Wf;
    float*       dst = g_ft + (size_t)b*Hf*Wf*Cc;
    #pragma unroll
    for (int u = 0; u < 4; u++)
        tile[ty+u*8][tx] = src[(size_t)(c0+ty+u*8)*(Hf*Wf) + hw0+tx];
    __syncthreads();
    #pragma unroll
    for (int u = 0; u < 4; u++)
        dst[(size_t)(hw0+ty+u*8)*Cc + c0+tx] = tile[tx][ty+u*8];
}

// ---------- fused sampling + scores + softmax + mix (bf16 hi/lo output) ----------
__global__ void __launch_bounds__(256) sample_attn(const float* __restrict__ rois,
                                                   const float* __restrict__ offs) {
    int b = blockIdx.x;               // token 0..25087
    int c = threadIdx.x;              // channel
    int n = b / 49, pos = b - n*49;
    int oi = pos / 7, oj = pos - oi*7;

    const float* roi = rois + n*5;
    int   bidx = (int)roi[0];
    float x1 = roi[1]*0.0625f - 0.5f;
    float y1 = roi[2]*0.0625f - 0.5f;
    float rw = roi[3]*0.0625f - 0.5f - x1;
    float rh = roi[4]*0.0625f - 0.5f - y1;
    float bw = rw * (1.0f/7.0f);
    float bh = rh * (1.0f/7.0f);
    const float* fb = g_ft + (size_t)bidx*(Hf*Wf*Cc);

    float qk = g_Qk[pos*Cc + c];
    float vals[Pp];
    float sc[Pp];
    #pragma unroll
    for (int p = 0; p < Pp; p++) {
        float odw = offs[((p*7+oi)*7+oj)*2 + 0];
        float odh = offs[((p*7+oi)*7+oj)*2 + 1];
        float x = x1 + (oj + 0.5f)*bw + 0.1f*rw*odw;
        float y = y1 + (oi + 0.5f)*bh + 0.1f*rh*odh;
        bool valid = (y > -1.0f) && (y < (float)Hf) && (x > -1.0f) && (x < (float)Wf);
        float yc = fminf(fmaxf(y, 0.f), (float)(Hf-1));
        float xc = fminf(fmaxf(x, 0.f), (float)(Wf-1));
        int y0 = (int)floorf(yc), x0 = (int)floorf(xc);
        int y1i = min(y0+1, Hf-1), x1i = min(x0+1, Wf-1);
        float ly = yc - (float)y0, lx = xc - (float)x0;
        float hy = 1.f - ly,       hx = 1.f - lx;
        const float* p00 = fb + ((size_t)(y0 *Wf + x0 ))*Cc + c;
        const float* p01 = fb + ((size_t)(y0 *Wf + x1i))*Cc + c;
        const float* p10 = fb + ((size_t)(y1i*Wf + x0 ))*Cc + c;
        const float* p11 = fb + ((size_t)(y1i*Wf + x1i))*Cc + c;
        float v = hy*hx*(*p00) + hy*lx*(*p01) + ly*hx*(*p10) + ly*lx*(*p11);
        v = valid ? v : 0.f;
        vals[p] = v;
        sc[p] = qk * v;
    }
    #pragma unroll
    for (int off = 16; off; off >>= 1) {
        #pragma unroll
        for (int p = 0; p < Pp; p++) sc[p] += __shfl_down_sync(0xffffffffu, sc[p], off);
    }
    __shared__ float red[8][Pp];
    int wid = c >> 5, lid = c & 31;
    if (lid == 0) {
        #pragma unroll
        for (int p = 0; p < Pp; p++) red[wid][p] = sc[p];
    }
    __syncthreads();
    float s[Pp];
    #pragma unroll
    for (int p = 0; p < Pp; p++) {
        float a = 0.f;
        #pragma unroll
        for (int w = 0; w < 8; w++) a += red[w][p];
        s[p] = a;
    }
    float m = fmaxf(fmaxf(s[0], s[1]), fmaxf(s[2], s[3]));
    float e[Pp], sum = 0.f;
    #pragma unroll
    for (int p = 0; p < Pp; p++) { e[p] = __expf(s[p]-m); sum += e[p]; }
    float inv = 1.f/sum;
    float mix = 0.f;
    #pragma unroll
    for (int p = 0; p < Pp; p++) mix += (e[p]*inv)*vals[p];
    __nv_bfloat16 h = __float2bfloat16(mix);
    g_sh[(size_t)b*Cc + c] = h;
    g_sl[(size_t)b*Cc + c] = __float2bfloat16(mix - __bfloat162float(h));
}

// ---------- mma.sync GEMM: out[n][g][pos] = sum_c M[g,c]*smix[b,c] + bias[g] ----------
// 128(g) x 128(tok) x 256, bf16 hi/lo 3-term, 8 warps (4 m x 2 n), warp = 32x64.
__global__ void __launch_bounds__(256) gemm_mma(float* __restrict__ out) {
    extern __shared__ char dyn[];
    __nv_bfloat16* tiles = (__nv_bfloat16*)dyn;          // 4 tiles [128][TSTRIDE]
    uint32_t sbase = smem_u32(dyn);

    int t = threadIdx.x;
    int wid = t >> 5, lane = t & 31;
    int warp_m = wid & 3;        // g quadrant (32 rows)
    int warp_n = wid >> 2;       // token half (64 cols)
    int b0 = blockIdx.x * 128;
    int g0 = blockIdx.y * 128;

    const __nv_bfloat16* srcs[4] = {
        g_Mhi + (size_t)g0*Cc, g_Mlo + (size_t)g0*Cc,
        g_sh  + (size_t)b0*Cc, g_sl  + (size_t)b0*Cc };

    float acc[2][8][4];
    #pragma unroll
    for (int mt = 0; mt < 2; mt++)
        #pragma unroll
        for (int nt = 0; nt < 8; nt++)
            #pragma unroll
            for (int r = 0; r < 4; r++) acc[mt][nt][r] = 0.f;

    // per-lane ldmatrix byte-address bases (within a tile)
    uint32_t aRow = (uint32_t)(warp_m*32 + (lane & 15));
    uint32_t aCol = (uint32_t)((lane >> 4) << 3);
    uint32_t aOff = (aRow*TSTRIDE + aCol) * 2;
    uint32_t bRow = (uint32_t)(warp_n*64 + (lane & 7) + ((lane >> 4) << 3));
    uint32_t bCol = (uint32_t)(((lane >> 3) & 1) << 3);
    uint32_t bOff = (bRow*TSTRIDE + bCol) * 2;

    for (int kc = 0; kc < 2; kc++) {
        // load 4 tiles: 128 rows x 128 bf16 of this K-chunk
        #pragma unroll
        for (int m = 0; m < 4; m++) {
            const __nv_bfloat16* src = srcs[m] + kc*128;
            __nv_bfloat16* dst = tiles + m*(128*TSTRIDE);
            #pragma unroll
            for (int it = 0; it < 8; it++) {
                int idx  = it*256 + t;
                int row  = idx >> 4;
                int col8 = (idx & 15) << 3;
                uint4 v = *(const uint4*)(src + (size_t)row*Cc + col8);
                *(uint4*)(dst + row*TSTRIDE + col8) = v;
            }
        }
        __syncthreads();

        #pragma unroll
        for (int ks = 0; ks < 8; ks++) {
            uint32_t kByte = (uint32_t)(ks*16*2);
            uint32_t ahi[2][4], alo[2][4];
            #pragma unroll
            for (int mt = 0; mt < 2; mt++) {
                uint32_t ad = sbase + aOff + (uint32_t)(mt*16*TSTRIDE*2) + kByte;
                ldsm4(ahi[mt], ad);
                ldsm4(alo[mt], ad + TILE_BYTES);
            }
            uint32_t bhi[4][4], blo[4][4];
            #pragma unroll
            for (int ng = 0; ng < 4; ng++) {
                uint32_t bd = sbase + 2*TILE_BYTES + bOff + (uint32_t)(ng*16*TSTRIDE*2) + kByte;
                ldsm4(bhi[ng], bd);
                ldsm4(blo[ng], bd + TILE_BYTES);
            }
            #pragma unroll
            for (int mt = 0; mt < 2; mt++)
                #pragma unroll
                for (int ng = 0; ng < 4; ng++)
                    #pragma unroll
                    for (int jj = 0; jj < 2; jj++) {
                        int nt = ng*2 + jj;
                        mma16816(acc[mt][nt], ahi[mt], bhi[ng][2*jj], bhi[ng][2*jj+1]);
                        mma16816(acc[mt][nt], ahi[mt], blo[ng][2*jj], blo[ng][2*jj+1]);
                        mma16816(acc[mt][nt], alo[mt], bhi[ng][2*jj], bhi[ng][2*jj+1]);
                    }
        }
        __syncthreads();
    }

    // epilogue: acc -> smem stage [g][130 tok] -> coalesced reordered stores
    float* stage = (float*)dyn;                 // 128*130*4 = 66560 <= SMEM_DYN
    #pragma unroll
    for (int mt = 0; mt < 2; mt++) {
        int gr = warp_m*32 + mt*16 + (lane >> 2);
        #pragma unroll
        for (int nt = 0; nt < 8; nt++) {
            int tok = warp_n*64 + nt*8 + (lane & 3)*2;
            *(float2*)&stage[(size_t)gr*130 + tok]     = make_float2(acc[mt][nt][0], acc[mt][nt][1]);
            *(float2*)&stage[(size_t)(gr+8)*130 + tok] = make_float2(acc[mt][nt][2], acc[mt][nt][3]);
        }
    }
    __syncthreads();
    #pragma unroll 4
    for (int j = 0; j < 64; j++) {
        int f  = j*256 + t;
        int gl = f >> 7;
        int tl = f & 127;
        int g  = g0 + gl;
        int token = b0 + tl;
        int n   = token / 49;
        int pos = token - n*49;
        out[(size_t)n*(Cc*49) + (size_t)g*49 + pos] = stage[(size_t)gl*130 + tl] + g_bias[g];
    }
}

extern "C" void kernel_launch(void* const* d_in, const int* in_sizes, int n_in,
                              void* d_out, int out_size) {
    const float* features   = (const float*)d_in[0];
    const float* rois       = (const float*)d_in[1];
    const float* offs       = (const float*)d_in[2];
    const float* queries    = (const float*)d_in[3];
    const float* w_proj     = (const float*)d_in[4];
    const float* b_proj     = (const float*)d_in[5];
    const float* in_proj_w  = (const float*)d_in[6];
    const float* in_proj_b  = (const float*)d_in[7];
    const float* out_proj_w = (const float*)d_in[8];
    const float* out_proj_b = (const float*)d_in[9];
    float* out = (float*)d_out;

    cudaFuncSetAttribute(gemm_mma, cudaFuncAttributeMaxDynamicSharedMemorySize, SMEM_DYN);

    pre1<<<512, 256>>>(in_proj_w, w_proj);
    pre2<<<306, 256>>>(in_proj_w, in_proj_b, out_proj_w, b_proj, queries);
    pre3<<<50, 256>>>(out_proj_w, out_proj_b);
    transpose_feat<<<dim3(Hf*Wf/32, Cc/32, Bn), dim3(32, 8)>>>(features);
    sample_attn<<<NTOK, 256>>>(rois, offs);
    gemm_mma<<<dim3(NTOK/128, Cc/128), 256, SMEM_DYN>>>(out);
}

// round 8
// speedup vs baseline: 1.7592x; 1.2642x over previous
#include <cuda_runtime.h>
#include <cuda_bf16.h>
#include <cstdint>

#define Cc 256
#define Hf 128
#define Wf 128
#define Bn 4
#define Nroi 512
#define Pp 4
#define NTOK (Nroi*49)              // 25088
#define FSZ (Bn*Cc*Hf*Wf)           // 16777216

// ---- scratch (device globals: allocation-free) ----
__device__ float g_ft[FSZ];                  // features transposed to [b][h*W+w][c]
__device__ __nv_bfloat16 g_sh[NTOK*Cc];      // smix hi
__device__ __nv_bfloat16 g_sl[NTOK*Cc];      // smix lo
__device__ __nv_bfloat16 g_Mhi[Cc*Cc];
__device__ __nv_bfloat16 g_Mlo[Cc*Cc];
__device__ float g_Mk[Cc*Cc];
__device__ float g_Mv[Cc*Cc];
__device__ float g_Qb[49*Cc];
__device__ float g_Qk[49*Cc];
__device__ float g_cv[Cc];
__device__ float g_bias[Cc];

__device__ __forceinline__ uint32_t smem_u32(const void* p) {
    uint32_t a;
    asm("{ .reg .u64 t; cvta.to.shared.u64 t, %1; cvt.u32.u64 %0, t; }" : "=r"(a) : "l"(p));
    return a;
}
__device__ __forceinline__ void ldsm4(uint32_t* r, uint32_t addr) {
    asm volatile("ldmatrix.sync.aligned.m8n8.x4.shared.b16 {%0,%1,%2,%3}, [%4];"
        : "=r"(r[0]), "=r"(r[1]), "=r"(r[2]), "=r"(r[3]) : "r"(addr));
}
__device__ __forceinline__ void mma16816(float* c, const uint32_t* a, uint32_t b0, uint32_t b1) {
    asm volatile("mma.sync.aligned.m16n8k16.row.col.f32.bf16.bf16.f32 "
        "{%0,%1,%2,%3}, {%4,%5,%6,%7}, {%8,%9}, {%0,%1,%2,%3};"
        : "+f"(c[0]), "+f"(c[1]), "+f"(c[2]), "+f"(c[3])
        : "r"(a[0]), "r"(a[1]), "r"(a[2]), "r"(a[3]), "r"(b0), "r"(b1));
}

#define TSTRIDE 136                         // bf16 per row (128 + 8 pad)
#define TILE_BYTES (128*TSTRIDE*2)          // 34816
#define SMEM_DYN (4*TILE_BYTES)             // 139264

// ---------- precompute stage 1: Mk = Wk@w_proj, Mv = Wv@w_proj ----------
__global__ void pre1(const float* __restrict__ in_proj_w,
                     const float* __restrict__ w_proj) {
    int i = blockIdx.x;           // 0..511
    int j = threadIdx.x;          // 0..255
    const float* A = (i < Cc) ? (in_proj_w + Cc*Cc + i*Cc)
                              : (in_proj_w + 2*Cc*Cc + (i-Cc)*Cc);
    float a0=0.f,a1=0.f,a2=0.f,a3=0.f;
    #pragma unroll 4
    for (int k = 0; k < Cc; k += 4) {
        a0 += A[k+0]*w_proj[(k+0)*Cc+j];
        a1 += A[k+1]*w_proj[(k+1)*Cc+j];
        a2 += A[k+2]*w_proj[(k+2)*Cc+j];
        a3 += A[k+3]*w_proj[(k+3)*Cc+j];
    }
    float acc = (a0+a1)+(a2+a3);
    if (i < Cc) g_Mk[i*Cc+j] = acc; else g_Mv[(i-Cc)*Cc+j] = acc;
}

// ---------- precompute stage 2: M = Wo@Mv (hi/lo bf16), cv, Qb ----------
__global__ void pre2(const float* __restrict__ in_proj_w,
                     const float* __restrict__ in_proj_b,
                     const float* __restrict__ out_proj_w,
                     const float* __restrict__ b_proj,
                     const float* __restrict__ queries) {
    int i = blockIdx.x;           // 0..305
    int j = threadIdx.x;
    if (i < Cc) {                 // M row -> hi/lo split
        const float* A = out_proj_w + i*Cc;
        float a0=0.f,a1=0.f,a2=0.f,a3=0.f;
        #pragma unroll 4
        for (int k = 0; k < Cc; k += 4) {
            a0 += A[k+0]*g_Mv[(k+0)*Cc+j];
            a1 += A[k+1]*g_Mv[(k+1)*Cc+j];
            a2 += A[k+2]*g_Mv[(k+2)*Cc+j];
            a3 += A[k+3]*g_Mv[(k+3)*Cc+j];
        }
        float acc = (a0+a1)+(a2+a3);
        __nv_bfloat16 h = __float2bfloat16(acc);
        g_Mhi[i*Cc+j] = h;
        g_Mlo[i*Cc+j] = __float2bfloat16(acc - __bfloat162float(h));
    } else if (i == Cc) {         // cv[j]
        const float* Wv = in_proj_w + 2*Cc*Cc;
        float acc = 0.f;
        for (int k = 0; k < Cc; k++) acc += Wv[j*Cc+k]*b_proj[k];
        g_cv[j] = acc + in_proj_b[2*Cc + j];
    } else {                      // Qb row pos = i-257
        int pos = i - Cc - 1;
        const float* q  = queries + pos*Cc;
        const float* Wq = in_proj_w;
        float acc = 0.f;
        for (int k = 0; k < Cc; k++) acc += q[k]*Wq[j*Cc+k];
        g_Qb[pos*Cc+j] = acc + in_proj_b[j];
    }
}

// ---------- precompute stage 3: bias = Wo@cv+bo, Qk = (1/16) Qb@Mk ----------
__global__ void pre3(const float* __restrict__ out_proj_w,
                     const float* __restrict__ out_proj_b) {
    int i = blockIdx.x;           // 0..49
    int j = threadIdx.x;
    if (i == 0) {
        float acc = 0.f;
        for (int k = 0; k < Cc; k++) acc += out_proj_w[j*Cc+k]*g_cv[k];
        g_bias[j] = acc + out_proj_b[j];
    } else {
        int pos = i - 1;
        float a0=0.f,a1=0.f,a2=0.f,a3=0.f;
        #pragma unroll 4
        for (int k = 0; k < Cc; k += 4) {
            a0 += g_Qb[pos*Cc+k+0]*g_Mk[(k+0)*Cc+j];
            a1 += g_Qb[pos*Cc+k+1]*g_Mk[(k+1)*Cc+j];
            a2 += g_Qb[pos*Cc+k+2]*g_Mk[(k+2)*Cc+j];
            a3 += g_Qb[pos*Cc+k+3]*g_Mk[(k+3)*Cc+j];
        }
        g_Qk[pos*Cc+j] = ((a0+a1)+(a2+a3)) * 0.0625f;
    }
}

// ---------- features (B,C,H,W) -> (B,H*W,C) ----------
__global__ void transpose_feat(const float* __restrict__ feat) {
    __shared__ float tile[32][33];
    int b   = blockIdx.z;
    int hw0 = blockIdx.x * 32;
    int c0  = blockIdx.y * 32;
    int tx = threadIdx.x, ty = threadIdx.y;
    const float* src = feat + (size_t)b*Cc*Hf*Wf;
    float*       dst = g_ft + (size_t)b*Hf*Wf*Cc;
    #pragma unroll
    for (int u = 0; u < 4; u++)
        tile[ty+u*8][tx] = src[(size_t)(c0+ty+u*8)*(Hf*Wf) + hw0+tx];
    __syncthreads();
    #pragma unroll
    for (int u = 0; u < 4; u++)
        dst[(size_t)(hw0+ty+u*8)*Cc + c0+tx] = tile[tx][ty+u*8];
}

// ---------- fused sampling + scores + softmax + mix (vectorized float4) ----------
// 4 tokens per 256-thread block; 64 threads per token; 4 channels (float4) per thread.
__global__ void __launch_bounds__(256) sample_attn(const float* __restrict__ rois,
                                                   const float* __restrict__ offs) {
    int grp = threadIdx.x >> 6;       // token group 0..3
    int tid = threadIdx.x & 63;       // 0..63 within token
    int b = blockIdx.x*4 + grp;       // token 0..25087
    int c4 = tid * 4;                 // channel base
    int n = b / 49, pos = b - n*49;
    int oi = pos / 7, oj = pos - oi*7;

    const float* roi = rois + n*5;
    int   bidx = (int)roi[0];
    float x1 = roi[1]*0.0625f - 0.5f;
    float y1 = roi[2]*0.0625f - 0.5f;
    float rw = roi[3]*0.0625f - 0.5f - x1;
    float rh = roi[4]*0.0625f - 0.5f - y1;
    float bw = rw * (1.0f/7.0f);
    float bh = rh * (1.0f/7.0f);
    const float* fb = g_ft + (size_t)bidx*(Hf*Wf*Cc);

    float4 qk = *(const float4*)(g_Qk + pos*Cc + c4);
    float4 vals[Pp];
    float sc[Pp];
    #pragma unroll
    for (int p = 0; p < Pp; p++) {
        float odw = offs[((p*7+oi)*7+oj)*2 + 0];
        float odh = offs[((p*7+oi)*7+oj)*2 + 1];
        float x = x1 + (oj + 0.5f)*bw + 0.1f*rw*odw;
        float y = y1 + (oi + 0.5f)*bh + 0.1f*rh*odh;
        bool valid = (y > -1.0f) && (y < (float)Hf) && (x > -1.0f) && (x < (float)Wf);
        float yc = fminf(fmaxf(y, 0.f), (float)(Hf-1));
        float xc = fminf(fmaxf(x, 0.f), (float)(Wf-1));
        int y0 = (int)floorf(yc), x0 = (int)floorf(xc);
        int y1i = min(y0+1, Hf-1), x1i = min(x0+1, Wf-1);
        float ly = yc - (float)y0, lx = xc - (float)x0;
        float hy = 1.f - ly,       hx = 1.f - lx;
        float4 v00 = *(const float4*)(fb + ((size_t)(y0 *Wf + x0 ))*Cc + c4);
        float4 v01 = *(const float4*)(fb + ((size_t)(y0 *Wf + x1i))*Cc + c4);
        float4 v10 = *(const float4*)(fb + ((size_t)(y1i*Wf + x0 ))*Cc + c4);
        float4 v11 = *(const float4*)(fb + ((size_t)(y1i*Wf + x1i))*Cc + c4);
        float w00 = hy*hx, w01 = hy*lx, w10 = ly*hx, w11 = ly*lx;
        float4 v;
        v.x = w00*v00.x + w01*v01.x + w10*v10.x + w11*v11.x;
        v.y = w00*v00.y + w01*v01.y + w10*v10.y + w11*v11.y;
        v.z = w00*v00.z + w01*v01.z + w10*v10.z + w11*v11.z;
        v.w = w00*v00.w + w01*v01.w + w10*v10.w + w11*v11.w;
        if (!valid) v = make_float4(0.f, 0.f, 0.f, 0.f);
        vals[p] = v;
        sc[p] = qk.x*v.x + qk.y*v.y + qk.z*v.z + qk.w*v.w;
    }
    // warp reduce, then combine the token's 2 warps via smem
    #pragma unroll
    for (int off = 16; off; off >>= 1) {
        #pragma unroll
        for (int p = 0; p < Pp; p++) sc[p] += __shfl_down_sync(0xffffffffu, sc[p], off);
    }
    __shared__ float red[8][Pp];
    int wid = threadIdx.x >> 5, lid = threadIdx.x & 31;
    if (lid == 0) {
        #pragma unroll
        for (int p = 0; p < Pp; p++) red[wid][p] = sc[p];
    }
    __syncthreads();
    float s[Pp];
    #pragma unroll
    for (int p = 0; p < Pp; p++) s[p] = red[grp*2][p] + red[grp*2+1][p];

    float m = fmaxf(fmaxf(s[0], s[1]), fmaxf(s[2], s[3]));
    float e[Pp], sum = 0.f;
    #pragma unroll
    for (int p = 0; p < Pp; p++) { e[p] = __expf(s[p]-m); sum += e[p]; }
    float inv = 1.f/sum;
    float4 mix = make_float4(0.f, 0.f, 0.f, 0.f);
    #pragma unroll
    for (int p = 0; p < Pp; p++) {
        float w = e[p]*inv;
        mix.x += w*vals[p].x; mix.y += w*vals[p].y;
        mix.z += w*vals[p].z; mix.w += w*vals[p].w;
    }
    // hi/lo bf16 split, packed stores (4 bf16 = 8B each)
    float mv[4] = {mix.x, mix.y, mix.z, mix.w};
    __nv_bfloat16 hb[4], lb[4];
    #pragma unroll
    for (int q = 0; q < 4; q++) {
        hb[q] = __float2bfloat16(mv[q]);
        lb[q] = __float2bfloat16(mv[q] - __bfloat162float(hb[q]));
    }
    *(uint2*)(g_sh + (size_t)b*Cc + c4) = *(const uint2*)hb;
    *(uint2*)(g_sl + (size_t)b*Cc + c4) = *(const uint2*)lb;
}

// ---------- mma.sync GEMM: out[n][g][pos] = sum_c M[g,c]*smix[b,c] + bias[g] ----------
// 128(g) x 128(tok) x 256, bf16 hi/lo 3-term, 8 warps (4 m x 2 n), warp = 32x64.
__global__ void __launch_bounds__(256) gemm_mma(float* __restrict__ out) {
    extern __shared__ char dyn[];
    __nv_bfloat16* tiles = (__nv_bfloat16*)dyn;          // 4 tiles [128][TSTRIDE]
    uint32_t sbase = smem_u32(dyn);

    int t = threadIdx.x;
    int wid = t >> 5, lane = t & 31;
    int warp_m = wid & 3;        // g quadrant (32 rows)
    int warp_n = wid >> 2;       // token half (64 cols)
    int b0 = blockIdx.x * 128;
    int g0 = blockIdx.y * 128;

    const __nv_bfloat16* srcs[4] = {
        g_Mhi + (size_t)g0*Cc, g_Mlo + (size_t)g0*Cc,
        g_sh  + (size_t)b0*Cc, g_sl  + (size_t)b0*Cc };

    float acc[2][8][4];
    #pragma unroll
    for (int mt = 0; mt < 2; mt++)
        #pragma unroll
        for (int nt = 0; nt < 8; nt++)
            #pragma unroll
            for (int r = 0; r < 4; r++) acc[mt][nt][r] = 0.f;

    // per-lane ldmatrix byte-address bases (within a tile)
    uint32_t aRow = (uint32_t)(warp_m*32 + (lane & 15));
    uint32_t aCol = (uint32_t)((lane >> 4) << 3);
    uint32_t aOff = (aRow*TSTRIDE + aCol) * 2;
    uint32_t bRow = (uint32_t)(warp_n*64 + (lane & 7) + ((lane >> 4) << 3));
    uint32_t bCol = (uint32_t)(((lane >> 3) & 1) << 3);
    uint32_t bOff = (bRow*TSTRIDE + bCol) * 2;

    for (int kc = 0; kc < 2; kc++) {
        // load 4 tiles: 128 rows x 128 bf16 of this K-chunk
        #pragma unroll
        for (int m = 0; m < 4; m++) {
            const __nv_bfloat16* src = srcs[m] + kc*128;
            __nv_bfloat16* dst = tiles + m*(128*TSTRIDE);
            #pragma unroll
            for (int it = 0; it < 8; it++) {
                int idx  = it*256 + t;
                int row  = idx >> 4;
                int col8 = (idx & 15) << 3;
                uint4 v = *(const uint4*)(src + (size_t)row*Cc + col8);
                *(uint4*)(dst + row*TSTRIDE + col8) = v;
            }
        }
        __syncthreads();

        #pragma unroll
        for (int ks = 0; ks < 8; ks++) {
            uint32_t kByte = (uint32_t)(ks*16*2);
            uint32_t ahi[2][4], alo[2][4];
            #pragma unroll
            for (int mt = 0; mt < 2; mt++) {
                uint32_t ad = sbase + aOff + (uint32_t)(mt*16*TSTRIDE*2) + kByte;
                ldsm4(ahi[mt], ad);
                ldsm4(alo[mt], ad + TILE_BYTES);
            }
            uint32_t bhi[4][4], blo[4][4];
            #pragma unroll
            for (int ng = 0; ng < 4; ng++) {
                uint32_t bd = sbase + 2*TILE_BYTES + bOff + (uint32_t)(ng*16*TSTRIDE*2) + kByte;
                ldsm4(bhi[ng], bd);
                ldsm4(blo[ng], bd + TILE_BYTES);
            }
            #pragma unroll
            for (int mt = 0; mt < 2; mt++)
                #pragma unroll
                for (int ng = 0; ng < 4; ng++)
                    #pragma unroll
                    for (int jj = 0; jj < 2; jj++) {
                        int nt = ng*2 + jj;
                        mma16816(acc[mt][nt], ahi[mt], bhi[ng][2*jj], bhi[ng][2*jj+1]);
                        mma16816(acc[mt][nt], ahi[mt], blo[ng][2*jj], blo[ng][2*jj+1]);
                        mma16816(acc[mt][nt], alo[mt], bhi[ng][2*jj], bhi[ng][2*jj+1]);
                    }
        }
        __syncthreads();
    }

    // epilogue: acc -> smem stage [g][130 tok] -> coalesced reordered stores
    float* stage = (float*)dyn;                 // 128*130*4 = 66560 <= SMEM_DYN
    #pragma unroll
    for (int mt = 0; mt < 2; mt++) {
        int gr = warp_m*32 + mt*16 + (lane >> 2);
        #pragma unroll
        for (int nt = 0; nt < 8; nt++) {
            int tok = warp_n*64 + nt*8 + (lane & 3)*2;
            *(float2*)&stage[(size_t)gr*130 + tok]     = make_float2(acc[mt][nt][0], acc[mt][nt][1]);
            *(float2*)&stage[(size_t)(gr+8)*130 + tok] = make_float2(acc[mt][nt][2], acc[mt][nt][3]);
        }
    }
    __syncthreads();
    #pragma unroll 4
    for (int j = 0; j < 64; j++) {
        int f  = j*256 + t;
        int gl = f >> 7;
        int tl = f & 127;
        int g  = g0 + gl;
        int token = b0 + tl;
        int n   = token / 49;
        int pos = token - n*49;
        out[(size_t)n*(Cc*49) + (size_t)g*49 + pos] = stage[(size_t)gl*130 + tl] + g_bias[g];
    }
}

extern "C" void kernel_launch(void* const* d_in, const int* in_sizes, int n_in,
                              void* d_out, int out_size) {
    const float* features   = (const float*)d_in[0];
    const float* rois       = (const float*)d_in[1];
    const float* offs       = (const float*)d_in[2];
    const float* queries    = (const float*)d_in[3];
    const float* w_proj     = (const float*)d_in[4];
    const float* b_proj     = (const float*)d_in[5];
    const float* in_proj_w  = (const float*)d_in[6];
    const float* in_proj_b  = (const float*)d_in[7];
    const float* out_proj_w = (const float*)d_in[8];
    const float* out_proj_b = (const float*)d_in[9];
    float* out = (float*)d_out;

    cudaFuncSetAttribute(gemm_mma, cudaFuncAttributeMaxDynamicSharedMemorySize, SMEM_DYN);

    pre1<<<512, 256>>>(in_proj_w, w_proj);
    pre2<<<306, 256>>>(in_proj_w, in_proj_b, out_proj_w, b_proj, queries);
    pre3<<<50, 256>>>(out_proj_w, out_proj_b);
    transpose_feat<<<dim3(Hf*Wf/32, Cc/32, Bn), dim3(32, 8)>>>(features);
    sample_attn<<<NTOK/4, 256>>>(rois, offs);
    gemm_mma<<<dim3(NTOK/128, Cc/128), 256, SMEM_DYN>>>(out);
}

// round 9
// speedup vs baseline: 2.0289x; 1.1534x over previous
#include <cuda_runtime.h>
#include <cuda_bf16.h>
#include <cstdint>

#define Cc 256
#define Hf 128
#define Wf 128
#define Bn 4
#define Nroi 512
#define Pp 4
#define NTOK (Nroi*49)              // 25088
#define FSZ (Bn*Cc*Hf*Wf)           // 16777216

// ---- scratch (device globals: allocation-free) ----
__device__ float g_ft[FSZ];                  // features transposed to [b][h*W+w][c]
__device__ __nv_bfloat16 g_sh[NTOK*Cc];      // smix hi
__device__ __nv_bfloat16 g_sl[NTOK*Cc];      // smix lo
__device__ __nv_bfloat16 g_Mhi[Cc*Cc];
__device__ __nv_bfloat16 g_Mlo[Cc*Cc];
__device__ float g_Mk[Cc*Cc];
__device__ float g_T [Cc*Cc];                // Wo@Wv
__device__ float g_Qb[49*Cc];
__device__ float g_Qk[49*Cc];
__device__ float g_cv[Cc];
__device__ float g_bias[Cc];

__device__ __forceinline__ uint32_t smem_u32(const void* p) {
    uint32_t a;
    asm("{ .reg .u64 t; cvta.to.shared.u64 t, %1; cvt.u32.u64 %0, t; }" : "=r"(a) : "l"(p));
    return a;
}
__device__ __forceinline__ void ldsm4(uint32_t* r, uint32_t addr) {
    asm volatile("ldmatrix.sync.aligned.m8n8.x4.shared.b16 {%0,%1,%2,%3}, [%4];"
        : "=r"(r[0]), "=r"(r[1]), "=r"(r[2]), "=r"(r[3]) : "r"(addr));
}
__device__ __forceinline__ void mma16816(float* c, const uint32_t* a, uint32_t b0, uint32_t b1) {
    asm volatile("mma.sync.aligned.m16n8k16.row.col.f32.bf16.bf16.f32 "
        "{%0,%1,%2,%3}, {%4,%5,%6,%7}, {%8,%9}, {%0,%1,%2,%3};"
        : "+f"(c[0]), "+f"(c[1]), "+f"(c[2]), "+f"(c[3])
        : "r"(a[0]), "r"(a[1]), "r"(a[2]), "r"(a[3]), "r"(b0), "r"(b1));
}

#define TSTRIDE 136                         // bf16 per row (128 + 8 pad)
#define TILE_BYTES (128*TSTRIDE*2)          // 34816
#define SMEM_DYN (4*TILE_BYTES)             // 139264

// ---------- pre_a: T = Wo@Wv, Mk = Wk@w_proj, cv, Qb (all independent) ----------
__global__ void pre_a(const float* __restrict__ in_proj_w,
                      const float* __restrict__ in_proj_b,
                      const float* __restrict__ out_proj_w,
                      const float* __restrict__ w_proj,
                      const float* __restrict__ b_proj,
                      const float* __restrict__ queries) {
    int i = blockIdx.x;           // 0..561
    int j = threadIdx.x;          // 0..255
    if (i < Cc) {                 // T[i][j] = sum_e Wo[i][e]*Wv[e][j]
        const float* A = out_proj_w + i*Cc;
        const float* Wv = in_proj_w + 2*Cc*Cc;
        float a0=0.f,a1=0.f,a2=0.f,a3=0.f;
        #pragma unroll 4
        for (int k = 0; k < Cc; k += 4) {
            a0 += A[k+0]*Wv[(k+0)*Cc+j];
            a1 += A[k+1]*Wv[(k+1)*Cc+j];
            a2 += A[k+2]*Wv[(k+2)*Cc+j];
            a3 += A[k+3]*Wv[(k+3)*Cc+j];
        }
        g_T[i*Cc+j] = (a0+a1)+(a2+a3);
    } else if (i < 2*Cc) {        // Mk row
        int r = i - Cc;
        const float* A = in_proj_w + Cc*Cc + r*Cc;
        float a0=0.f,a1=0.f,a2=0.f,a3=0.f;
        #pragma unroll 4
        for (int k = 0; k < Cc; k += 4) {
            a0 += A[k+0]*w_proj[(k+0)*Cc+j];
            a1 += A[k+1]*w_proj[(k+1)*Cc+j];
            a2 += A[k+2]*w_proj[(k+2)*Cc+j];
            a3 += A[k+3]*w_proj[(k+3)*Cc+j];
        }
        g_Mk[r*Cc+j] = (a0+a1)+(a2+a3);
    } else if (i == 2*Cc) {       // cv[j] = Wv@b_proj + bv
        const float* Wv = in_proj_w + 2*Cc*Cc;
        float acc = 0.f;
        for (int k = 0; k < Cc; k++) acc += Wv[j*Cc+k]*b_proj[k];
        g_cv[j] = acc + in_proj_b[2*Cc + j];
    } else {                      // Qb row pos = i-513
        int pos = i - 2*Cc - 1;
        const float* q  = queries + pos*Cc;
        const float* Wq = in_proj_w;
        float acc = 0.f;
        for (int k = 0; k < Cc; k++) acc += q[k]*Wq[j*Cc+k];
        g_Qb[pos*Cc+j] = acc + in_proj_b[j];
    }
}

// ---------- pre_b: M = T@w_proj (hi/lo), bias = Wo@cv+bo, Qk = (1/16) Qb@Mk ----------
__global__ void pre_b(const float* __restrict__ out_proj_w,
                      const float* __restrict__ out_proj_b) {
    int i = blockIdx.x;           // 0..305
    int j = threadIdx.x;
    if (i < Cc) {                 // M row hi/lo
        const float* A = g_T + i*Cc;
        float a0=0.f,a1=0.f,a2=0.f,a3=0.f;
        #pragma unroll 4
        for (int k = 0; k < Cc; k += 4) {
            a0 += A[k+0]*g_T[0];  // placeholder avoided below
            a0 -= A[k+0]*g_T[0];
            a0 += A[k+0]*0.f;
            break;
        }
        // clean accumulation (w_proj passed via constant path below)
        (void)a1; (void)a2; (void)a3;
        // recomputed in second arg version — see pre_b2
        (void)A; (void)j;
    }
}

// real pre_b (takes w_proj)
__global__ void pre_b2(const float* __restrict__ w_proj,
                       const float* __restrict__ out_proj_w,
                       const float* __restrict__ out_proj_b) {
    int i = blockIdx.x;           // 0..305
    int j = threadIdx.x;
    if (i < Cc) {                 // M[i][j] = sum_d T[i][d]*w_proj[d][j]
        const float* A = g_T + i*Cc;
        float a0=0.f,a1=0.f,a2=0.f,a3=0.f;
        #pragma unroll 4
        for (int k = 0; k < Cc; k += 4) {
            a0 += A[k+0]*w_proj[(k+0)*Cc+j];
            a1 += A[k+1]*w_proj[(k+1)*Cc+j];
            a2 += A[k+2]*w_proj[(k+2)*Cc+j];
            a3 += A[k+3]*w_proj[(k+3)*Cc+j];
        }
        float acc = (a0+a1)+(a2+a3);
        __nv_bfloat16 h = __float2bfloat16(acc);
        g_Mhi[i*Cc+j] = h;
        g_Mlo[i*Cc+j] = __float2bfloat16(acc - __bfloat162float(h));
    } else if (i == Cc) {         // bias
        float acc = 0.f;
        for (int k = 0; k < Cc; k++) acc += out_proj_w[j*Cc+k]*g_cv[k];
        g_bias[j] = acc + out_proj_b[j];
    } else {                      // Qk row pos = i-257
        int pos = i - Cc - 1;
        float a0=0.f,a1=0.f,a2=0.f,a3=0.f;
        #pragma unroll 4
        for (int k = 0; k < Cc; k += 4) {
            a0 += g_Qb[pos*Cc+k+0]*g_Mk[(k+0)*Cc+j];
            a1 += g_Qb[pos*Cc+k+1]*g_Mk[(k+1)*Cc+j];
            a2 += g_Qb[pos*Cc+k+2]*g_Mk[(k+2)*Cc+j];
            a3 += g_Qb[pos*Cc+k+3]*g_Mk[(k+3)*Cc+j];
        }
        g_Qk[pos*Cc+j] = ((a0+a1)+(a2+a3)) * 0.0625f;
    }
}

// ---------- features (B,C,H,W) -> (B,H*W,C) ----------
__global__ void transpose_feat(const float* __restrict__ feat) {
    __shared__ float tile[32][33];
    int b   = blockIdx.z;
    int hw0 = blockIdx.x * 32;
    int c0  = blockIdx.y * 32;
    int tx = threadIdx.x, ty = threadIdx.y;
    const float* src = feat + (size_t)b*Cc*Hf*Wf;
    float*       dst = g_ft + (size_t)b*Hf*Wf*Cc;
    #pragma unroll
    for (int u = 0; u < 4; u++)
        tile[ty+u*8][tx] = src[(size_t)(c0+ty+u*8)*(Hf*Wf) + hw0+tx];
    __syncthreads();
    #pragma unroll
    for (int u = 0; u < 4; u++)
        dst[(size_t)(hw0+ty+u*8)*Cc + c0+tx] = tile[tx][ty+u*8];
}

// ---------- fused sampling + scores + softmax + mix: warp-per-token ----------
// 8 tokens per 256-thread block; 32 lanes x 8 channels (2 x float4) per token.
__global__ void __launch_bounds__(256) sample_attn(const float* __restrict__ rois,
                                                   const float* __restrict__ offs) {
    int lane = threadIdx.x & 31;
    int wid  = threadIdx.x >> 5;
    int b = blockIdx.x*8 + wid;       // token
    int c8 = lane * 8;
    int n = b / 49, pos = b - n*49;
    int oi = pos / 7, oj = pos - oi*7;

    const float* roi = rois + n*5;
    int   bidx = (int)roi[0];
    float x1 = roi[1]*0.0625f - 0.5f;
    float y1 = roi[2]*0.0625f - 0.5f;
    float rw = roi[3]*0.0625f - 0.5f - x1;
    float rh = roi[4]*0.0625f - 0.5f - y1;
    float bw = rw * (1.0f/7.0f);
    float bh = rh * (1.0f/7.0f);
    const float* fb = g_ft + (size_t)bidx*(Hf*Wf*Cc);

    float4 qk0 = *(const float4*)(g_Qk + pos*Cc + c8);
    float4 qk1 = *(const float4*)(g_Qk + pos*Cc + c8 + 4);
    float4 va[Pp], vb[Pp];
    float sc[Pp];
    #pragma unroll
    for (int p = 0; p < Pp; p++) {
        float odw = offs[((p*7+oi)*7+oj)*2 + 0];
        float odh = offs[((p*7+oi)*7+oj)*2 + 1];
        float x = x1 + (oj + 0.5f)*bw + 0.1f*rw*odw;
        float y = y1 + (oi + 0.5f)*bh + 0.1f*rh*odh;
        bool valid = (y > -1.0f) && (y < (float)Hf) && (x > -1.0f) && (x < (float)Wf);
        float yc = fminf(fmaxf(y, 0.f), (float)(Hf-1));
        float xc = fminf(fmaxf(x, 0.f), (float)(Wf-1));
        int y0 = (int)floorf(yc), x0 = (int)floorf(xc);
        int y1i = min(y0+1, Hf-1), x1i = min(x0+1, Wf-1);
        float ly = yc - (float)y0, lx = xc - (float)x0;
        float hy = 1.f - ly,       hx = 1.f - lx;
        const float* p00 = fb + ((size_t)(y0 *Wf + x0 ))*Cc + c8;
        const float* p01 = fb + ((size_t)(y0 *Wf + x1i))*Cc + c8;
        const float* p10 = fb + ((size_t)(y1i*Wf + x0 ))*Cc + c8;
        const float* p11 = fb + ((size_t)(y1i*Wf + x1i))*Cc + c8;
        float4 a00 = *(const float4*)(p00),     b00 = *(const float4*)(p00 + 4);
        float4 a01 = *(const float4*)(p01),     b01 = *(const float4*)(p01 + 4);
        float4 a10 = *(const float4*)(p10),     b10 = *(const float4*)(p10 + 4);
        float4 a11 = *(const float4*)(p11),     b11 = *(const float4*)(p11 + 4);
        float w00 = hy*hx, w01 = hy*lx, w10 = ly*hx, w11 = ly*lx;
        float4 u, v;
        u.x = w00*a00.x + w01*a01.x + w10*a10.x + w11*a11.x;
        u.y = w00*a00.y + w01*a01.y + w10*a10.y + w11*a11.y;
        u.z = w00*a00.z + w01*a01.z + w10*a10.z + w11*a11.z;
        u.w = w00*a00.w + w01*a01.w + w10*a10.w + w11*a11.w;
        v.x = w00*b00.x + w01*b01.x + w10*b10.x + w11*b11.x;
        v.y = w00*b00.y + w01*b01.y + w10*b10.y + w11*b11.y;
        v.z = w00*b00.z + w01*b01.z + w10*b10.z + w11*b11.z;
        v.w = w00*b00.w + w01*b01.w + w10*b10.w + w11*b11.w;
        if (!valid) {
            u = make_float4(0.f,0.f,0.f,0.f);
            v = make_float4(0.f,0.f,0.f,0.f);
        }
        va[p] = u; vb[p] = v;
        sc[p] = qk0.x*u.x + qk0.y*u.y + qk0.z*u.z + qk0.w*u.w
              + qk1.x*v.x + qk1.y*v.y + qk1.z*v.z + qk1.w*v.w;
    }
    // butterfly reduce: all lanes end with full sums
    #pragma unroll
    for (int off = 16; off; off >>= 1) {
        #pragma unroll
        for (int p = 0; p < Pp; p++) sc[p] += __shfl_xor_sync(0xffffffffu, sc[p], off);
    }
    float m = fmaxf(fmaxf(sc[0], sc[1]), fmaxf(sc[2], sc[3]));
    float e[Pp], sum = 0.f;
    #pragma unroll
    for (int p = 0; p < Pp; p++) { e[p] = __expf(sc[p]-m); sum += e[p]; }
    float inv = 1.f/sum;
    float mix[8] = {0,0,0,0,0,0,0,0};
    #pragma unroll
    for (int p = 0; p < Pp; p++) {
        float w = e[p]*inv;
        mix[0] += w*va[p].x; mix[1] += w*va[p].y; mix[2] += w*va[p].z; mix[3] += w*va[p].w;
        mix[4] += w*vb[p].x; mix[5] += w*vb[p].y; mix[6] += w*vb[p].z; mix[7] += w*vb[p].w;
    }
    __nv_bfloat16 hb[8], lb[8];
    #pragma unroll
    for (int q = 0; q < 8; q++) {
        hb[q] = __float2bfloat16(mix[q]);
        lb[q] = __float2bfloat16(mix[q] - __bfloat162float(hb[q]));
    }
    *(uint4*)(g_sh + (size_t)b*Cc + c8) = *(const uint4*)hb;
    *(uint4*)(g_sl + (size_t)b*Cc + c8) = *(const uint4*)lb;
}

// ---------- mma.sync GEMM: out[n][g][pos] = sum_c M[g,c]*smix[b,c] + bias[g] ----------
__global__ void __launch_bounds__(256) gemm_mma(float* __restrict__ out) {
    extern __shared__ char dyn[];
    __nv_bfloat16* tiles = (__nv_bfloat16*)dyn;          // 4 tiles [128][TSTRIDE]
    uint32_t sbase = smem_u32(dyn);

    int t = threadIdx.x;
    int wid = t >> 5, lane = t & 31;
    int warp_m = wid & 3;        // g quadrant (32 rows)
    int warp_n = wid >> 2;       // token half (64 cols)
    int b0 = blockIdx.x * 128;
    int g0 = blockIdx.y * 128;

    const __nv_bfloat16* srcs[4] = {
        g_Mhi + (size_t)g0*Cc, g_Mlo + (size_t)g0*Cc,
        g_sh  + (size_t)b0*Cc, g_sl  + (size_t)b0*Cc };

    float acc[2][8][4];
    #pragma unroll
    for (int mt = 0; mt < 2; mt++)
        #pragma unroll
        for (int nt = 0; nt < 8; nt++)
            #pragma unroll
            for (int r = 0; r < 4; r++) acc[mt][nt][r] = 0.f;

    uint32_t aRow = (uint32_t)(warp_m*32 + (lane & 15));
    uint32_t aCol = (uint32_t)((lane >> 4) << 3);
    uint32_t aOff = (aRow*TSTRIDE + aCol) * 2;
    uint32_t bRow = (uint32_t)(warp_n*64 + (lane & 7) + ((lane >> 4) << 3));
    uint32_t bCol = (uint32_t)(((lane >> 3) & 1) << 3);
    uint32_t bOff = (bRow*TSTRIDE + bCol) * 2;

    for (int kc = 0; kc < 2; kc++) {
        #pragma unroll
        for (int m = 0; m < 4; m++) {
            const __nv_bfloat16* src = srcs[m] + kc*128;
            __nv_bfloat16* dst = tiles + m*(128*TSTRIDE);
            #pragma unroll
            for (int it = 0; it < 8; it++) {
                int idx  = it*256 + t;
                int row  = idx >> 4;
                int col8 = (idx & 15) << 3;
                uint4 v = *(const uint4*)(src + (size_t)row*Cc + col8);
                *(uint4*)(dst + row*TSTRIDE + col8) = v;
            }
        }
        __syncthreads();

        #pragma unroll
        for (int ks = 0; ks < 8; ks++) {
            uint32_t kByte = (uint32_t)(ks*16*2);
            uint32_t ahi[2][4], alo[2][4];
            #pragma unroll
            for (int mt = 0; mt < 2; mt++) {
                uint32_t ad = sbase + aOff + (uint32_t)(mt*16*TSTRIDE*2) + kByte;
                ldsm4(ahi[mt], ad);
                ldsm4(alo[mt], ad + TILE_BYTES);
            }
            uint32_t bhi[4][4], blo[4][4];
            #pragma unroll
            for (int ng = 0; ng < 4; ng++) {
                uint32_t bd = sbase + 2*TILE_BYTES + bOff + (uint32_t)(ng*16*TSTRIDE*2) + kByte;
                ldsm4(bhi[ng], bd);
                ldsm4(blo[ng], bd + TILE_BYTES);
            }
            #pragma unroll
            for (int mt = 0; mt < 2; mt++)
                #pragma unroll
                for (int ng = 0; ng < 4; ng++)
                    #pragma unroll
                    for (int jj = 0; jj < 2; jj++) {
                        int nt = ng*2 + jj;
                        mma16816(acc[mt][nt], ahi[mt], bhi[ng][2*jj], bhi[ng][2*jj+1]);
                        mma16816(acc[mt][nt], ahi[mt], blo[ng][2*jj], blo[ng][2*jj+1]);
                        mma16816(acc[mt][nt], alo[mt], bhi[ng][2*jj], bhi[ng][2*jj+1]);
                    }
        }
        __syncthreads();
    }

    float* stage = (float*)dyn;
    #pragma unroll
    for (int mt = 0; mt < 2; mt++) {
        int gr = warp_m*32 + mt*16 + (lane >> 2);
        #pragma unroll
        for (int nt = 0; nt < 8; nt++) {
            int tok = warp_n*64 + nt*8 + (lane & 3)*2;
            *(float2*)&stage[(size_t)gr*130 + tok]     = make_float2(acc[mt][nt][0], acc[mt][nt][1]);
            *(float2*)&stage[(size_t)(gr+8)*130 + tok] = make_float2(acc[mt][nt][2], acc[mt][nt][3]);
        }
    }
    __syncthreads();
    #pragma unroll 4
    for (int j = 0; j < 64; j++) {
        int f  = j*256 + t;
        int gl = f >> 7;
        int tl = f & 127;
        int g  = g0 + gl;
        int token = b0 + tl;
        int n   = token / 49;
        int pos = token - n*49;
        out[(size_t)n*(Cc*49) + (size_t)g*49 + pos] = stage[(size_t)gl*130 + tl] + g_bias[g];
    }
}

extern "C" void kernel_launch(void* const* d_in, const int* in_sizes, int n_in,
                              void* d_out, int out_size) {
    const float* features   = (const float*)d_in[0];
    const float* rois       = (const float*)d_in[1];
    const float* offs       = (const float*)d_in[2];
    const float* queries    = (const float*)d_in[3];
    const float* w_proj     = (const float*)d_in[4];
    const float* b_proj     = (const float*)d_in[5];
    const float* in_proj_w  = (const float*)d_in[6];
    const float* in_proj_b  = (const float*)d_in[7];
    const float* out_proj_w = (const float*)d_in[8];
    const float* out_proj_b = (const float*)d_in[9];
    float* out = (float*)d_out;

    static cudaStream_t s_side = nullptr;
    static cudaEvent_t  e_fork = nullptr, e_join = nullptr;
    if (!s_side) {
        cudaStreamCreateWithFlags(&s_side, cudaStreamNonBlocking);
        cudaEventCreateWithFlags(&e_fork, cudaEventDisableTiming);
        cudaEventCreateWithFlags(&e_join, cudaEventDisableTiming);
    }

    cudaFuncSetAttribute(gemm_mma, cudaFuncAttributeMaxDynamicSharedMemorySize, SMEM_DYN);

    // fork: pre-chain on side stream, transpose on main stream, join before sample
    cudaEventRecord(e_fork, 0);
    cudaStreamWaitEvent(s_side, e_fork, 0);
    pre_a<<<562, 256, 0, s_side>>>(in_proj_w, in_proj_b, out_proj_w, w_proj, b_proj, queries);
    pre_b2<<<306, 256, 0, s_side>>>(w_proj, out_proj_w, out_proj_b);
    cudaEventRecord(e_join, s_side);

    transpose_feat<<<dim3(Hf*Wf/32, Cc/32, Bn), dim3(32, 8)>>>(features);

    cudaStreamWaitEvent(0, e_join, 0);
    sample_attn<<<NTOK/8, 256>>>(rois, offs);
    gemm_mma<<<dim3(NTOK/128, Cc/128), 256, SMEM_DYN>>>(out);
}

// round 10
// speedup vs baseline: 2.3042x; 1.1357x over previous
#include <cuda_runtime.h>
#include <cuda_bf16.h>
#include <cstdint>

#define Cc 256
#define Hf 128
#define Wf 128
#define Bn 4
#define Nroi 512
#define Pp 4
#define NTOK (Nroi*49)              // 25088
#define FSZ (Bn*Cc*Hf*Wf)           // 16777216

// ---- scratch (device globals: allocation-free) ----
__device__ float g_ft[FSZ];                  // features transposed to [b][h*W+w][c]
__device__ __nv_bfloat16 g_sh[NTOK*Cc];      // smix hi
__device__ __nv_bfloat16 g_sl[NTOK*Cc];      // smix lo
__device__ __nv_bfloat16 g_Mhi[Cc*Cc];
__device__ __nv_bfloat16 g_Mlo[Cc*Cc];
__device__ float g_Mk[Cc*Cc];
__device__ float g_T [Cc*Cc];                // Wo@Wv
__device__ float g_Qb[49*Cc];
__device__ float g_Qk[49*Cc];
__device__ float g_cv[Cc];
__device__ float g_bias[Cc];

__device__ __forceinline__ uint32_t smem_u32(const void* p) {
    uint32_t a;
    asm("{ .reg .u64 t; cvta.to.shared.u64 t, %1; cvt.u32.u64 %0, t; }" : "=r"(a) : "l"(p));
    return a;
}
__device__ __forceinline__ void ldsm4(uint32_t* r, uint32_t addr) {
    asm volatile("ldmatrix.sync.aligned.m8n8.x4.shared.b16 {%0,%1,%2,%3}, [%4];"
        : "=r"(r[0]), "=r"(r[1]), "=r"(r[2]), "=r"(r[3]) : "r"(addr));
}
__device__ __forceinline__ void mma16816(float* c, const uint32_t* a, uint32_t b0, uint32_t b1) {
    asm volatile("mma.sync.aligned.m16n8k16.row.col.f32.bf16.bf16.f32 "
        "{%0,%1,%2,%3}, {%4,%5,%6,%7}, {%8,%9}, {%0,%1,%2,%3};"
        : "+f"(c[0]), "+f"(c[1]), "+f"(c[2]), "+f"(c[3])
        : "r"(a[0]), "r"(a[1]), "r"(a[2]), "r"(a[3]), "r"(b0), "r"(b1));
}

#define TSTRIDE 72                          // bf16 per row (64 + 8 pad)
#define TILE_BYTES (128*TSTRIDE*2)          // 18432
#define SMEM_DYN (4*TILE_BYTES)             // 73728

// ---------- pre_a: T = Wo@Wv, Mk = Wk@w_proj, cv, Qb (all independent) ----------
__global__ void pre_a(const float* __restrict__ in_proj_w,
                      const float* __restrict__ in_proj_b,
                      const float* __restrict__ out_proj_w,
                      const float* __restrict__ w_proj,
                      const float* __restrict__ b_proj,
                      const float* __restrict__ queries) {
    int i = blockIdx.x;           // 0..561
    int j = threadIdx.x;          // 0..255
    if (i < Cc) {                 // T[i][j] = sum_e Wo[i][e]*Wv[e][j]
        const float* A = out_proj_w + i*Cc;
        const float* Wv = in_proj_w + 2*Cc*Cc;
        float a0=0.f,a1=0.f,a2=0.f,a3=0.f;
        #pragma unroll 4
        for (int k = 0; k < Cc; k += 4) {
            a0 += A[k+0]*Wv[(k+0)*Cc+j];
            a1 += A[k+1]*Wv[(k+1)*Cc+j];
            a2 += A[k+2]*Wv[(k+2)*Cc+j];
            a3 += A[k+3]*Wv[(k+3)*Cc+j];
        }
        g_T[i*Cc+j] = (a0+a1)+(a2+a3);
    } else if (i < 2*Cc) {        // Mk row
        int r = i - Cc;
        const float* A = in_proj_w + Cc*Cc + r*Cc;
        float a0=0.f,a1=0.f,a2=0.f,a3=0.f;
        #pragma unroll 4
        for (int k = 0; k < Cc; k += 4) {
            a0 += A[k+0]*w_proj[(k+0)*Cc+j];
            a1 += A[k+1]*w_proj[(k+1)*Cc+j];
            a2 += A[k+2]*w_proj[(k+2)*Cc+j];
            a3 += A[k+3]*w_proj[(k+3)*Cc+j];
        }
        g_Mk[r*Cc+j] = (a0+a1)+(a2+a3);
    } else if (i == 2*Cc) {       // cv[j] = Wv@b_proj + bv
        const float* Wv = in_proj_w + 2*Cc*Cc;
        float acc = 0.f;
        for (int k = 0; k < Cc; k++) acc += Wv[j*Cc+k]*b_proj[k];
        g_cv[j] = acc + in_proj_b[2*Cc + j];
    } else {                      // Qb row pos = i-513
        int pos = i - 2*Cc - 1;
        const float* q  = queries + pos*Cc;
        const float* Wq = in_proj_w;
        float acc = 0.f;
        for (int k = 0; k < Cc; k++) acc += q[k]*Wq[j*Cc+k];
        g_Qb[pos*Cc+j] = acc + in_proj_b[j];
    }
}

// ---------- pre_b2: M = T@w_proj (hi/lo), bias = Wo@cv+bo, Qk = (1/16) Qb@Mk ----------
__global__ void pre_b2(const float* __restrict__ w_proj,
                       const float* __restrict__ out_proj_w,
                       const float* __restrict__ out_proj_b) {
    int i = blockIdx.x;           // 0..305
    int j = threadIdx.x;
    if (i < Cc) {                 // M[i][j] = sum_d T[i][d]*w_proj[d][j]
        const float* A = g_T + i*Cc;
        float a0=0.f,a1=0.f,a2=0.f,a3=0.f;
        #pragma unroll 4
        for (int k = 0; k < Cc; k += 4) {
            a0 += A[k+0]*w_proj[(k+0)*Cc+j];
            a1 += A[k+1]*w_proj[(k+1)*Cc+j];
            a2 += A[k+2]*w_proj[(k+2)*Cc+j];
            a3 += A[k+3]*w_proj[(k+3)*Cc+j];
        }
        float acc = (a0+a1)+(a2+a3);
        __nv_bfloat16 h = __float2bfloat16(acc);
        g_Mhi[i*Cc+j] = h;
        g_Mlo[i*Cc+j] = __float2bfloat16(acc - __bfloat162float(h));
    } else if (i == Cc) {         // bias
        float acc = 0.f;
        for (int k = 0; k < Cc; k++) acc += out_proj_w[j*Cc+k]*g_cv[k];
        g_bias[j] = acc + out_proj_b[j];
    } else {                      // Qk row pos = i-257
        int pos = i - Cc - 1;
        float a0=0.f,a1=0.f,a2=0.f,a3=0.f;
        #pragma unroll 4
        for (int k = 0; k < Cc; k += 4) {
            a0 += g_Qb[pos*Cc+k+0]*g_Mk[(k+0)*Cc+j];
            a1 += g_Qb[pos*Cc+k+1]*g_Mk[(k+1)*Cc+j];
            a2 += g_Qb[pos*Cc+k+2]*g_Mk[(k+2)*Cc+j];
            a3 += g_Qb[pos*Cc+k+3]*g_Mk[(k+3)*Cc+j];
        }
        g_Qk[pos*Cc+j] = ((a0+a1)+(a2+a3)) * 0.0625f;
    }
}

// ---------- features (B,C,H,W) -> (B,H*W,C) ----------
__global__ void transpose_feat(const float* __restrict__ feat) {
    __shared__ float tile[32][33];
    int b   = blockIdx.z;
    int hw0 = blockIdx.x * 32;
    int c0  = blockIdx.y * 32;
    int tx = threadIdx.x, ty = threadIdx.y;
    const float* src = feat + (size_t)b*Cc*Hf*Wf;
    float*       dst = g_ft + (size_t)b*Hf*Wf*Cc;
    #pragma unroll
    for (int u = 0; u < 4; u++)
        tile[ty+u*8][tx] = src[(size_t)(c0+ty+u*8)*(Hf*Wf) + hw0+tx];
    __syncthreads();
    #pragma unroll
    for (int u = 0; u < 4; u++)
        dst[(size_t)(hw0+ty+u*8)*Cc + c0+tx] = tile[tx][ty+u*8];
}

// ---------- fused sampling + scores + softmax + mix: warp-per-token ----------
// 8 tokens per 256-thread block; 32 lanes x 8 channels per token.
// Fast path when all 4 deform points share the same bilinear corners (common:
// gamma*offsets ~1e-4): load 4 corners once, fold attn into corner weights.
__global__ void __launch_bounds__(256) sample_attn(const float* __restrict__ rois,
                                                   const float* __restrict__ offs) {
    int lane = threadIdx.x & 31;
    int wid  = threadIdx.x >> 5;
    int b = blockIdx.x*8 + wid;       // token
    int c8 = lane * 8;
    int n = b / 49, pos = b - n*49;
    int oi = pos / 7, oj = pos - oi*7;

    const float* roi = rois + n*5;
    int   bidx = (int)roi[0];
    float x1 = roi[1]*0.0625f - 0.5f;
    float y1 = roi[2]*0.0625f - 0.5f;
    float rw = roi[3]*0.0625f - 0.5f - x1;
    float rh = roi[4]*0.0625f - 0.5f - y1;
    float bw = rw * (1.0f/7.0f);
    float bh = rh * (1.0f/7.0f);
    const float* fb = g_ft + (size_t)bidx*(Hf*Wf*Cc);

    float4 qk0 = *(const float4*)(g_Qk + pos*Cc + c8);
    float4 qk1 = *(const float4*)(g_Qk + pos*Cc + c8 + 4);

    int   y0a[Pp], x0a[Pp];
    float lya[Pp], lxa[Pp];
    bool  vld[Pp];
    #pragma unroll
    for (int p = 0; p < Pp; p++) {
        float odw = offs[((p*7+oi)*7+oj)*2 + 0];
        float odh = offs[((p*7+oi)*7+oj)*2 + 1];
        float x = x1 + (oj + 0.5f)*bw + 0.1f*rw*odw;
        float y = y1 + (oi + 0.5f)*bh + 0.1f*rh*odh;
        vld[p] = (y > -1.0f) && (y < (float)Hf) && (x > -1.0f) && (x < (float)Wf);
        float yc = fminf(fmaxf(y, 0.f), (float)(Hf-1));
        float xc = fminf(fmaxf(x, 0.f), (float)(Wf-1));
        y0a[p] = (int)floorf(yc); x0a[p] = (int)floorf(xc);
        lya[p] = yc - (float)y0a[p];
        lxa[p] = xc - (float)x0a[p];
    }
    bool same = (y0a[1]==y0a[0]) & (y0a[2]==y0a[0]) & (y0a[3]==y0a[0])
              & (x0a[1]==x0a[0]) & (x0a[2]==x0a[0]) & (x0a[3]==x0a[0]);

    float mix[8];
    if (same) {
        // ---- fast path: one set of 4 corners ----
        int y0 = y0a[0], x0 = x0a[0];
        int y1i = min(y0+1, Hf-1), x1i = min(x0+1, Wf-1);
        const float* p00 = fb + ((size_t)(y0 *Wf + x0 ))*Cc + c8;
        const float* p01 = fb + ((size_t)(y0 *Wf + x1i))*Cc + c8;
        const float* p10 = fb + ((size_t)(y1i*Wf + x0 ))*Cc + c8;
        const float* p11 = fb + ((size_t)(y1i*Wf + x1i))*Cc + c8;
        float4 ca[4], cb[4];
        ca[0]=*(const float4*)(p00); cb[0]=*(const float4*)(p00+4);
        ca[1]=*(const float4*)(p01); cb[1]=*(const float4*)(p01+4);
        ca[2]=*(const float4*)(p10); cb[2]=*(const float4*)(p10+4);
        ca[3]=*(const float4*)(p11); cb[3]=*(const float4*)(p11+4);
        float qd[4];
        #pragma unroll
        for (int c = 0; c < 4; c++)
            qd[c] = qk0.x*ca[c].x + qk0.y*ca[c].y + qk0.z*ca[c].z + qk0.w*ca[c].w
                  + qk1.x*cb[c].x + qk1.y*cb[c].y + qk1.z*cb[c].z + qk1.w*cb[c].w;
        #pragma unroll
        for (int off = 16; off; off >>= 1) {
            #pragma unroll
            for (int c = 0; c < 4; c++) qd[c] += __shfl_xor_sync(0xffffffffu, qd[c], off);
        }
        float sc[Pp];
        float w[Pp][4];
        #pragma unroll
        for (int p = 0; p < Pp; p++) {
            float ly = lya[p], lx = lxa[p];
            float hy = 1.f-ly, hx = 1.f-lx;
            w[p][0]=hy*hx; w[p][1]=hy*lx; w[p][2]=ly*hx; w[p][3]=ly*lx;
            float s = w[p][0]*qd[0] + w[p][1]*qd[1] + w[p][2]*qd[2] + w[p][3]*qd[3];
            sc[p] = vld[p] ? s : 0.f;
        }
        float m = fmaxf(fmaxf(sc[0], sc[1]), fmaxf(sc[2], sc[3]));
        float e[Pp], sum = 0.f;
        #pragma unroll
        for (int p = 0; p < Pp; p++) { e[p] = __expf(sc[p]-m); sum += e[p]; }
        float inv = 1.f/sum;
        float W[4] = {0,0,0,0};
        #pragma unroll
        for (int p = 0; p < Pp; p++) {
            float a = vld[p] ? e[p]*inv : 0.f;
            W[0] += a*w[p][0]; W[1] += a*w[p][1]; W[2] += a*w[p][2]; W[3] += a*w[p][3];
        }
        #pragma unroll
        for (int q = 0; q < 4; q++) {
            mix[q]   = W[0]*((&ca[0].x)[q]) + W[1]*((&ca[1].x)[q])
                     + W[2]*((&ca[2].x)[q]) + W[3]*((&ca[3].x)[q]);
            mix[q+4] = W[0]*((&cb[0].x)[q]) + W[1]*((&cb[1].x)[q])
                     + W[2]*((&cb[2].x)[q]) + W[3]*((&cb[3].x)[q]);
        }
    } else {
        // ---- slow path: per-point corners ----
        float4 va[Pp], vb[Pp];
        float sc[Pp];
        #pragma unroll
        for (int p = 0; p < Pp; p++) {
            int y0 = y0a[p], x0 = x0a[p];
            int y1i = min(y0+1, Hf-1), x1i = min(x0+1, Wf-1);
            float ly = lya[p], lx = lxa[p];
            float hy = 1.f - ly, hx = 1.f - lx;
            const float* p00 = fb + ((size_t)(y0 *Wf + x0 ))*Cc + c8;
            const float* p01 = fb + ((size_t)(y0 *Wf + x1i))*Cc + c8;
            const float* p10 = fb + ((size_t)(y1i*Wf + x0 ))*Cc + c8;
            const float* p11 = fb + ((size_t)(y1i*Wf + x1i))*Cc + c8;
            float4 a00 = *(const float4*)(p00),     b00 = *(const float4*)(p00 + 4);
            float4 a01 = *(const float4*)(p01),     b01 = *(const float4*)(p01 + 4);
            float4 a10 = *(const float4*)(p10),     b10 = *(const float4*)(p10 + 4);
            float4 a11 = *(const float4*)(p11),     b11 = *(const float4*)(p11 + 4);
            float w00 = hy*hx, w01 = hy*lx, w10 = ly*hx, w11 = ly*lx;
            float4 u, v;
            u.x = w00*a00.x + w01*a01.x + w10*a10.x + w11*a11.x;
            u.y = w00*a00.y + w01*a01.y + w10*a10.y + w11*a11.y;
            u.z = w00*a00.z + w01*a01.z + w10*a10.z + w11*a11.z;
            u.w = w00*a00.w + w01*a01.w + w10*a10.w + w11*a11.w;
            v.x = w00*b00.x + w01*b01.x + w10*b10.x + w11*b11.x;
            v.y = w00*b00.y + w01*b01.y + w10*b10.y + w11*b11.y;
            v.z = w00*b00.z + w01*b01.z + w10*b10.z + w11*b11.z;
            v.w = w00*b00.w + w01*b01.w + w10*b10.w + w11*b11.w;
            if (!vld[p]) {
                u = make_float4(0.f,0.f,0.f,0.f);
                v = make_float4(0.f,0.f,0.f,0.f);
            }
            va[p] = u; vb[p] = v;
            sc[p] = qk0.x*u.x + qk0.y*u.y + qk0.z*u.z + qk0.w*u.w
                  + qk1.x*v.x + qk1.y*v.y + qk1.z*v.z + qk1.w*v.w;
        }
        #pragma unroll
        for (int off = 16; off; off >>= 1) {
            #pragma unroll
            for (int p = 0; p < Pp; p++) sc[p] += __shfl_xor_sync(0xffffffffu, sc[p], off);
        }
        float m = fmaxf(fmaxf(sc[0], sc[1]), fmaxf(sc[2], sc[3]));
        float e[Pp], sum = 0.f;
        #pragma unroll
        for (int p = 0; p < Pp; p++) { e[p] = __expf(sc[p]-m); sum += e[p]; }
        float inv = 1.f/sum;
        #pragma unroll
        for (int q = 0; q < 8; q++) mix[q] = 0.f;
        #pragma unroll
        for (int p = 0; p < Pp; p++) {
            float w = e[p]*inv;
            mix[0] += w*va[p].x; mix[1] += w*va[p].y; mix[2] += w*va[p].z; mix[3] += w*va[p].w;
            mix[4] += w*vb[p].x; mix[5] += w*vb[p].y; mix[6] += w*vb[p].z; mix[7] += w*vb[p].w;
        }
    }
    __nv_bfloat16 hb[8], lb[8];
    #pragma unroll
    for (int q = 0; q < 8; q++) {
        hb[q] = __float2bfloat16(mix[q]);
        lb[q] = __float2bfloat16(mix[q] - __bfloat162float(hb[q]));
    }
    *(uint4*)(g_sh + (size_t)b*Cc + c8) = *(const uint4*)hb;
    *(uint4*)(g_sl + (size_t)b*Cc + c8) = *(const uint4*)lb;
}

// ---------- mma.sync GEMM: out[n][g][pos] = sum_c M[g,c]*smix[b,c] + bias[g] ----------
// 128(g) x 128(tok) x 256, K chunked at 64 for 2 CTAs/SM (single wave).
__global__ void __launch_bounds__(256, 2) gemm_mma(float* __restrict__ out) {
    extern __shared__ char dyn[];
    __nv_bfloat16* tiles = (__nv_bfloat16*)dyn;          // 4 tiles [128][TSTRIDE]
    uint32_t sbase = smem_u32(dyn);

    int t = threadIdx.x;
    int wid = t >> 5, lane = t & 31;
    int warp_m = wid & 3;        // g quadrant (32 rows)
    int warp_n = wid >> 2;       // token half (64 cols)
    int b0 = blockIdx.x * 128;
    int g0 = blockIdx.y * 128;

    const __nv_bfloat16* srcs[4] = {
        g_Mhi + (size_t)g0*Cc, g_Mlo + (size_t)g0*Cc,
        g_sh  + (size_t)b0*Cc, g_sl  + (size_t)b0*Cc };

    float acc[2][8][4];
    #pragma unroll
    for (int mt = 0; mt < 2; mt++)
        #pragma unroll
        for (int nt = 0; nt < 8; nt++)
            #pragma unroll
            for (int r = 0; r < 4; r++) acc[mt][nt][r] = 0.f;

    uint32_t aRow = (uint32_t)(warp_m*32 + (lane & 15));
    uint32_t aCol = (uint32_t)((lane >> 4) << 3);
    uint32_t aOff = (aRow*TSTRIDE + aCol) * 2;
    uint32_t bRow = (uint32_t)(warp_n*64 + (lane & 7) + ((lane >> 4) << 3));
    uint32_t bCol = (uint32_t)(((lane >> 3) & 1) << 3);
    uint32_t bOff = (bRow*TSTRIDE + bCol) * 2;

    for (int kc = 0; kc < 4; kc++) {
        // load 4 tiles: 128 rows x 64 bf16 of this K-chunk
        #pragma unroll
        for (int m = 0; m < 4; m++) {
            const __nv_bfloat16* src = srcs[m] + kc*64;
            __nv_bfloat16* dst = tiles + m*(128*TSTRIDE);
            #pragma unroll
            for (int it = 0; it < 4; it++) {
                int idx  = it*256 + t;
                int row  = idx >> 3;            // 8 x uint4 per 64-elem row
                int col8 = (idx & 7) << 3;
                uint4 v = *(const uint4*)(src + (size_t)row*Cc + col8);
                *(uint4*)(dst + row*TSTRIDE + col8) = v;
            }
        }
        __syncthreads();

        #pragma unroll
        for (int ks = 0; ks < 4; ks++) {
            uint32_t kByte = (uint32_t)(ks*16*2);
            uint32_t ahi[2][4], alo[2][4];
            #pragma unroll
            for (int mt = 0; mt < 2; mt++) {
                uint32_t ad = sbase + aOff + (uint32_t)(mt*16*TSTRIDE*2) + kByte;
                ldsm4(ahi[mt], ad);
                ldsm4(alo[mt], ad + TILE_BYTES);
            }
            uint32_t bhi[4][4], blo[4][4];
            #pragma unroll
            for (int ng = 0; ng < 4; ng++) {
                uint32_t bd = sbase + 2*TILE_BYTES + bOff + (uint32_t)(ng*16*TSTRIDE*2) + kByte;
                ldsm4(bhi[ng], bd);
                ldsm4(blo[ng], bd + TILE_BYTES);
            }
            #pragma unroll
            for (int mt = 0; mt < 2; mt++)
                #pragma unroll
                for (int ng = 0; ng < 4; ng++)
                    #pragma unroll
                    for (int jj = 0; jj < 2; jj++) {
                        int nt = ng*2 + jj;
                        mma16816(acc[mt][nt], ahi[mt], bhi[ng][2*jj], bhi[ng][2*jj+1]);
                        mma16816(acc[mt][nt], ahi[mt], blo[ng][2*jj], blo[ng][2*jj+1]);
                        mma16816(acc[mt][nt], alo[mt], bhi[ng][2*jj], bhi[ng][2*jj+1]);
                    }
        }
        __syncthreads();
    }

    float* stage = (float*)dyn;                 // 128*130*4 = 66560 <= SMEM_DYN
    #pragma unroll
    for (int mt = 0; mt < 2; mt++) {
        int gr = warp_m*32 + mt*16 + (lane >> 2);
        #pragma unroll
        for (int nt = 0; nt < 8; nt++) {
            int tok = warp_n*64 + nt*8 + (lane & 3)*2;
            *(float2*)&stage[(size_t)gr*130 + tok]     = make_float2(acc[mt][nt][0], acc[mt][nt][1]);
            *(float2*)&stage[(size_t)(gr+8)*130 + tok] = make_float2(acc[mt][nt][2], acc[mt][nt][3]);
        }
    }
    __syncthreads();
    #pragma unroll 4
    for (int j = 0; j < 64; j++) {
        int f  = j*256 + t;
        int gl = f >> 7;
        int tl = f & 127;
        int g  = g0 + gl;
        int token = b0 + tl;
        int n   = token / 49;
        int pos = token - n*49;
        out[(size_t)n*(Cc*49) + (size_t)g*49 + pos] = stage[(size_t)gl*130 + tl] + g_bias[g];
    }
}

extern "C" void kernel_launch(void* const* d_in, const int* in_sizes, int n_in,
                              void* d_out, int out_size) {
    const float* features   = (const float*)d_in[0];
    const float* rois       = (const float*)d_in[1];
    const float* offs       = (const float*)d_in[2];
    const float* queries    = (const float*)d_in[3];
    const float* w_proj     = (const float*)d_in[4];
    const float* b_proj     = (const float*)d_in[5];
    const float* in_proj_w  = (const float*)d_in[6];
    const float* in_proj_b  = (const float*)d_in[7];
    const float* out_proj_w = (const float*)d_in[8];
    const float* out_proj_b = (const float*)d_in[9];
    float* out = (float*)d_out;

    static cudaStream_t s_side = nullptr;
    static cudaEvent_t  e_fork = nullptr, e_join = nullptr;
    if (!s_side) {
        cudaStreamCreateWithFlags(&s_side, cudaStreamNonBlocking);
        cudaEventCreateWithFlags(&e_fork, cudaEventDisableTiming);
        cudaEventCreateWithFlags(&e_join, cudaEventDisableTiming);
    }

    cudaFuncSetAttribute(gemm_mma, cudaFuncAttributeMaxDynamicSharedMemorySize, SMEM_DYN);

    // fork: pre-chain on side stream, transpose on main stream, join before sample
    cudaEventRecord(e_fork, 0);
    cudaStreamWaitEvent(s_side, e_fork, 0);
    pre_a<<<562, 256, 0, s_side>>>(in_proj_w, in_proj_b, out_proj_w, w_proj, b_proj, queries);
    pre_b2<<<306, 256, 0, s_side>>>(w_proj, out_proj_w, out_proj_b);
    cudaEventRecord(e_join, s_side);

    transpose_feat<<<dim3(Hf*Wf/32, Cc/32, Bn), dim3(32, 8)>>>(features);

    cudaStreamWaitEvent(0, e_join, 0);
    sample_attn<<<NTOK/8, 256>>>(rois, offs);
    gemm_mma<<<dim3(NTOK/128, Cc/128), 256, SMEM_DYN>>>(out);
}

// round 11
// speedup vs baseline: 2.4958x; 1.0832x over previous
#include <cuda_runtime.h>
#include <cuda_bf16.h>
#include <cstdint>

#define Cc 256
#define Hf 128
#define Wf 128
#define Bn 4
#define Nroi 512
#define Pp 4
#define NTOK (Nroi*49)              // 25088
#define FSZ (Bn*Cc*Hf*Wf)           // 16777216

// ---- scratch (device globals: allocation-free) ----
__device__ float g_ft[FSZ];                  // features transposed to [b][h*W+w][c]
__device__ __nv_bfloat16 g_sh[NTOK*Cc];      // smix hi
__device__ __nv_bfloat16 g_sl[NTOK*Cc];      // smix lo
__device__ __nv_bfloat16 g_Mhi[Cc*Cc];
__device__ __nv_bfloat16 g_Mlo[Cc*Cc];
__device__ float g_Mk[Cc*Cc];
__device__ float g_T [Cc*Cc];                // Wo@Wv
__device__ float g_Qb[49*Cc];
__device__ float g_Qk[49*Cc];
__device__ float g_cv[Cc];
__device__ float g_bias[Cc];

__device__ __forceinline__ uint32_t smem_u32(const void* p) {
    uint32_t a;
    asm("{ .reg .u64 t; cvta.to.shared.u64 t, %1; cvt.u32.u64 %0, t; }" : "=r"(a) : "l"(p));
    return a;
}
__device__ __forceinline__ void ldsm4(uint32_t* r, uint32_t addr) {
    asm volatile("ldmatrix.sync.aligned.m8n8.x4.shared.b16 {%0,%1,%2,%3}, [%4];"
        : "=r"(r[0]), "=r"(r[1]), "=r"(r[2]), "=r"(r[3]) : "r"(addr));
}
__device__ __forceinline__ void mma16816(float* c, const uint32_t* a, uint32_t b0, uint32_t b1) {
    asm volatile("mma.sync.aligned.m16n8k16.row.col.f32.bf16.bf16.f32 "
        "{%0,%1,%2,%3}, {%4,%5,%6,%7}, {%8,%9}, {%0,%1,%2,%3};"
        : "+f"(c[0]), "+f"(c[1]), "+f"(c[2]), "+f"(c[3])
        : "r"(a[0]), "r"(a[1]), "r"(a[2]), "r"(a[3]), "r"(b0), "r"(b1));
}

#define TSTRIDE 72                          // bf16 per row (64 + 8 pad)
#define TILE_BYTES (128*TSTRIDE*2)          // 18432
#define SMEM_DYN (4*TILE_BYTES)             // 73728

// ================= pre-chain: 8-rows-per-block smem-tiled =================
// acc[r] over k with A rows staged in smem, B streamed coalesced.
__device__ __forceinline__ void tile8_accum(const float* __restrict__ B, int j,
                                            const float* As, float* acc) {
    #pragma unroll 4
    for (int k = 0; k < Cc; k += 4) {
        float b0 = B[(k+0)*Cc+j];
        float b1 = B[(k+1)*Cc+j];
        float b2 = B[(k+2)*Cc+j];
        float b3 = B[(k+3)*Cc+j];
        #pragma unroll
        for (int r = 0; r < 8; r++) {
            acc[r] += As[r*Cc+k+0]*b0 + As[r*Cc+k+1]*b1
                    + As[r*Cc+k+2]*b2 + As[r*Cc+k+3]*b3;
        }
    }
}

// stage 1: T = Wo@Wv (32 blk), Mk = Wk@w_proj (32 blk), Qb (49 blk), cv (1 blk)
__global__ void __launch_bounds__(256) pre_s1(const float* __restrict__ in_proj_w,
                                              const float* __restrict__ in_proj_b,
                                              const float* __restrict__ out_proj_w,
                                              const float* __restrict__ w_proj,
                                              const float* __restrict__ b_proj,
                                              const float* __restrict__ queries) {
    int bid = blockIdx.x, j = threadIdx.x;
    if (bid < 64) {
        __shared__ float As[8*Cc];
        const float* Arow; const float* B; float* out;
        if (bid < 32) {
            int r0 = bid*8;
            Arow = out_proj_w + r0*Cc; B = in_proj_w + 2*Cc*Cc; out = g_T + r0*Cc;
        } else {
            int r0 = (bid-32)*8;
            Arow = in_proj_w + Cc*Cc + r0*Cc; B = w_proj; out = g_Mk + r0*Cc;
        }
        for (int u = j; u < 8*Cc; u += 256) As[u] = Arow[u];
        __syncthreads();
        float acc[8] = {0,0,0,0,0,0,0,0};
        tile8_accum(B, j, As, acc);
        #pragma unroll
        for (int r = 0; r < 8; r++) out[r*Cc + j] = acc[r];
    } else if (bid < 113) {           // Qb row pos = bid-64
        __shared__ float qs[Cc];
        int pos = bid - 64;
        qs[j] = queries[pos*Cc + j];
        __syncthreads();
        const float4* Wr = (const float4*)(in_proj_w + (size_t)j*Cc);
        float a0=0.f,a1=0.f,a2=0.f,a3=0.f;
        #pragma unroll 8
        for (int k4 = 0; k4 < Cc/4; k4++) {
            float4 w = Wr[k4];
            a0 += w.x*qs[k4*4+0]; a1 += w.y*qs[k4*4+1];
            a2 += w.z*qs[k4*4+2]; a3 += w.w*qs[k4*4+3];
        }
        g_Qb[pos*Cc+j] = (a0+a1)+(a2+a3) + in_proj_b[j];
    } else {                          // cv
        __shared__ float bs[Cc];
        bs[j] = b_proj[j];
        __syncthreads();
        const float4* Wr = (const float4*)(in_proj_w + 2*Cc*Cc + (size_t)j*Cc);
        float a0=0.f,a1=0.f,a2=0.f,a3=0.f;
        #pragma unroll 8
        for (int k4 = 0; k4 < Cc/4; k4++) {
            float4 w = Wr[k4];
            a0 += w.x*bs[k4*4+0]; a1 += w.y*bs[k4*4+1];
            a2 += w.z*bs[k4*4+2]; a3 += w.w*bs[k4*4+3];
        }
        g_cv[j] = (a0+a1)+(a2+a3) + in_proj_b[2*Cc + j];
    }
}

// stage 2: M = T@w_proj hi/lo (32 blk), Qk = (1/16) Qb@Mk (7 blk), bias (1 blk)
__global__ void __launch_bounds__(256) pre_s2(const float* __restrict__ w_proj,
                                              const float* __restrict__ out_proj_w,
                                              const float* __restrict__ out_proj_b) {
    int bid = blockIdx.x, j = threadIdx.x;
    if (bid < 32) {                   // M rows
        __shared__ float As[8*Cc];
        int r0 = bid*8;
        for (int u = j; u < 8*Cc; u += 256) As[u] = g_T[r0*Cc + u];
        __syncthreads();
        float acc[8] = {0,0,0,0,0,0,0,0};
        tile8_accum(w_proj, j, As, acc);
        #pragma unroll
        for (int r = 0; r < 8; r++) {
            __nv_bfloat16 h = __float2bfloat16(acc[r]);
            g_Mhi[(r0+r)*Cc+j] = h;
            g_Mlo[(r0+r)*Cc+j] = __float2bfloat16(acc[r] - __bfloat162float(h));
        }
    } else if (bid < 39) {            // Qk rows
        __shared__ float As[8*Cc];
        int pos0 = (bid-32)*8;
        int rows = min(8, 49 - pos0);
        for (int u = j; u < rows*Cc; u += 256) As[u] = g_Qb[pos0*Cc + u];
        __syncthreads();
        float acc[8] = {0,0,0,0,0,0,0,0};
        tile8_accum(g_Mk, j, As, acc);
        #pragma unroll
        for (int r = 0; r < 8; r++)
            if (r < rows) g_Qk[(pos0+r)*Cc+j] = acc[r] * 0.0625f;
    } else {                          // bias
        __shared__ float cs[Cc];
        cs[j] = g_cv[j];
        __syncthreads();
        const float4* Wr = (const float4*)(out_proj_w + (size_t)j*Cc);
        float a0=0.f,a1=0.f,a2=0.f,a3=0.f;
        #pragma unroll 8
        for (int k4 = 0; k4 < Cc/4; k4++) {
            float4 w = Wr[k4];
            a0 += w.x*cs[k4*4+0]; a1 += w.y*cs[k4*4+1];
            a2 += w.z*cs[k4*4+2]; a3 += w.w*cs[k4*4+3];
        }
        g_bias[j] = (a0+a1)+(a2+a3) + out_proj_b[j];
    }
}

// ---------- features (B,C,H,W) -> (B,H*W,C) ----------
__global__ void transpose_feat(const float* __restrict__ feat) {
    __shared__ float tile[32][33];
    int b   = blockIdx.z;
    int hw0 = blockIdx.x * 32;
    int c0  = blockIdx.y * 32;
    int tx = threadIdx.x, ty = threadIdx.y;
    const float* src = feat + (size_t)b*Cc*Hf*Wf;
    float*       dst = g_ft + (size_t)b*Hf*Wf*Cc;
    #pragma unroll
    for (int u = 0; u < 4; u++)
        tile[ty+u*8][tx] = src[(size_t)(c0+ty+u*8)*(Hf*Wf) + hw0+tx];
    __syncthreads();
    #pragma unroll
    for (int u = 0; u < 4; u++)
        dst[(size_t)(hw0+ty+u*8)*Cc + c0+tx] = tile[tx][ty+u*8];
}

// ---------- fused sampling + scores + softmax + mix: warp-per-token ----------
__global__ void __launch_bounds__(256) sample_attn(const float* __restrict__ rois,
                                                   const float* __restrict__ offs) {
    int lane = threadIdx.x & 31;
    int wid  = threadIdx.x >> 5;
    int b = blockIdx.x*8 + wid;       // token
    int c8 = lane * 8;
    int n = b / 49, pos = b - n*49;
    int oi = pos / 7, oj = pos - oi*7;

    const float* roi = rois + n*5;
    int   bidx = (int)roi[0];
    float x1 = roi[1]*0.0625f - 0.5f;
    float y1 = roi[2]*0.0625f - 0.5f;
    float rw = roi[3]*0.0625f - 0.5f - x1;
    float rh = roi[4]*0.0625f - 0.5f - y1;
    float bw = rw * (1.0f/7.0f);
    float bh = rh * (1.0f/7.0f);
    const float* fb = g_ft + (size_t)bidx*(Hf*Wf*Cc);

    float4 qk0 = *(const float4*)(g_Qk + pos*Cc + c8);
    float4 qk1 = *(const float4*)(g_Qk + pos*Cc + c8 + 4);

    int   y0a[Pp], x0a[Pp];
    float lya[Pp], lxa[Pp];
    bool  vld[Pp];
    #pragma unroll
    for (int p = 0; p < Pp; p++) {
        float odw = offs[((p*7+oi)*7+oj)*2 + 0];
        float odh = offs[((p*7+oi)*7+oj)*2 + 1];
        float x = x1 + (oj + 0.5f)*bw + 0.1f*rw*odw;
        float y = y1 + (oi + 0.5f)*bh + 0.1f*rh*odh;
        vld[p] = (y > -1.0f) && (y < (float)Hf) && (x > -1.0f) && (x < (float)Wf);
        float yc = fminf(fmaxf(y, 0.f), (float)(Hf-1));
        float xc = fminf(fmaxf(x, 0.f), (float)(Wf-1));
        y0a[p] = (int)floorf(yc); x0a[p] = (int)floorf(xc);
        lya[p] = yc - (float)y0a[p];
        lxa[p] = xc - (float)x0a[p];
    }
    bool same = (y0a[1]==y0a[0]) & (y0a[2]==y0a[0]) & (y0a[3]==y0a[0])
              & (x0a[1]==x0a[0]) & (x0a[2]==x0a[0]) & (x0a[3]==x0a[0]);

    float mix[8];
    if (same) {
        int y0 = y0a[0], x0 = x0a[0];
        int y1i = min(y0+1, Hf-1), x1i = min(x0+1, Wf-1);
        const float* p00 = fb + ((size_t)(y0 *Wf + x0 ))*Cc + c8;
        const float* p01 = fb + ((size_t)(y0 *Wf + x1i))*Cc + c8;
        const float* p10 = fb + ((size_t)(y1i*Wf + x0 ))*Cc + c8;
        const float* p11 = fb + ((size_t)(y1i*Wf + x1i))*Cc + c8;
        float4 ca[4], cb[4];
        ca[0]=*(const float4*)(p00); cb[0]=*(const float4*)(p00+4);
        ca[1]=*(const float4*)(p01); cb[1]=*(const float4*)(p01+4);
        ca[2]=*(const float4*)(p10); cb[2]=*(const float4*)(p10+4);
        ca[3]=*(const float4*)(p11); cb[3]=*(const float4*)(p11+4);
        float qd[4];
        #pragma unroll
        for (int c = 0; c < 4; c++)
            qd[c] = qk0.x*ca[c].x + qk0.y*ca[c].y + qk0.z*ca[c].z + qk0.w*ca[c].w
                  + qk1.x*cb[c].x + qk1.y*cb[c].y + qk1.z*cb[c].z + qk1.w*cb[c].w;
        #pragma unroll
        for (int off = 16; off; off >>= 1) {
            #pragma unroll
            for (int c = 0; c < 4; c++) qd[c] += __shfl_xor_sync(0xffffffffu, qd[c], off);
        }
        float sc[Pp];
        float w[Pp][4];
        #pragma unroll
        for (int p = 0; p < Pp; p++) {
            float ly = lya[p], lx = lxa[p];
            float hy = 1.f-ly, hx = 1.f-lx;
            w[p][0]=hy*hx; w[p][1]=hy*lx; w[p][2]=ly*hx; w[p][3]=ly*lx;
            float s = w[p][0]*qd[0] + w[p][1]*qd[1] + w[p][2]*qd[2] + w[p][3]*qd[3];
            sc[p] = vld[p] ? s : 0.f;
        }
        float m = fmaxf(fmaxf(sc[0], sc[1]), fmaxf(sc[2], sc[3]));
        float e[Pp], sum = 0.f;
        #pragma unroll
        for (int p = 0; p < Pp; p++) { e[p] = __expf(sc[p]-m); sum += e[p]; }
        float inv = 1.f/sum;
        float W[4] = {0,0,0,0};
        #pragma unroll
        for (int p = 0; p < Pp; p++) {
            float a = vld[p] ? e[p]*inv : 0.f;
            W[0] += a*w[p][0]; W[1] += a*w[p][1]; W[2] += a*w[p][2]; W[3] += a*w[p][3];
        }
        #pragma unroll
        for (int q = 0; q < 4; q++) {
            mix[q]   = W[0]*((&ca[0].x)[q]) + W[1]*((&ca[1].x)[q])
                     + W[2]*((&ca[2].x)[q]) + W[3]*((&ca[3].x)[q]);
            mix[q+4] = W[0]*((&cb[0].x)[q]) + W[1]*((&cb[1].x)[q])
                     + W[2]*((&cb[2].x)[q]) + W[3]*((&cb[3].x)[q]);
        }
    } else {
        float4 va[Pp], vb[Pp];
        float sc[Pp];
        #pragma unroll
        for (int p = 0; p < Pp; p++) {
            int y0 = y0a[p], x0 = x0a[p];
            int y1i = min(y0+1, Hf-1), x1i = min(x0+1, Wf-1);
            float ly = lya[p], lx = lxa[p];
            float hy = 1.f - ly, hx = 1.f - lx;
            const float* p00 = fb + ((size_t)(y0 *Wf + x0 ))*Cc + c8;
            const float* p01 = fb + ((size_t)(y0 *Wf + x1i))*Cc + c8;
            const float* p10 = fb + ((size_t)(y1i*Wf + x0 ))*Cc + c8;
            const float* p11 = fb + ((size_t)(y1i*Wf + x1i))*Cc + c8;
            float4 a00 = *(const float4*)(p00),     b00 = *(const float4*)(p00 + 4);
            float4 a01 = *(const float4*)(p01),     b01 = *(const float4*)(p01 + 4);
            float4 a10 = *(const float4*)(p10),     b10 = *(const float4*)(p10 + 4);
            float4 a11 = *(const float4*)(p11),     b11 = *(const float4*)(p11 + 4);
            float w00 = hy*hx, w01 = hy*lx, w10 = ly*hx, w11 = ly*lx;
            float4 u, v;
            u.x = w00*a00.x + w01*a01.x + w10*a10.x + w11*a11.x;
            u.y = w00*a00.y + w01*a01.y + w10*a10.y + w11*a11.y;
            u.z = w00*a00.z + w01*a01.z + w10*a10.z + w11*a11.z;
            u.w = w00*a00.w + w01*a01.w + w10*a10.w + w11*a11.w;
            v.x = w00*b00.x + w01*b01.x + w10*b10.x + w11*b11.x;
            v.y = w00*b00.y + w01*b01.y + w10*b10.y + w11*b11.y;
            v.z = w00*b00.z + w01*b01.z + w10*b10.z + w11*b11.z;
            v.w = w00*b00.w + w01*b01.w + w10*b10.w + w11*b11.w;
            if (!vld[p]) {
                u = make_float4(0.f,0.f,0.f,0.f);
                v = make_float4(0.f,0.f,0.f,0.f);
            }
            va[p] = u; vb[p] = v;
            sc[p] = qk0.x*u.x + qk0.y*u.y + qk0.z*u.z + qk0.w*u.w
                  + qk1.x*v.x + qk1.y*v.y + qk1.z*v.z + qk1.w*v.w;
        }
        #pragma unroll
        for (int off = 16; off; off >>= 1) {
            #pragma unroll
            for (int p = 0; p < Pp; p++) sc[p] += __shfl_xor_sync(0xffffffffu, sc[p], off);
        }
        float m = fmaxf(fmaxf(sc[0], sc[1]), fmaxf(sc[2], sc[3]));
        float e[Pp], sum = 0.f;
        #pragma unroll
        for (int p = 0; p < Pp; p++) { e[p] = __expf(sc[p]-m); sum += e[p]; }
        float inv = 1.f/sum;
        #pragma unroll
        for (int q = 0; q < 8; q++) mix[q] = 0.f;
        #pragma unroll
        for (int p = 0; p < Pp; p++) {
            float w = e[p]*inv;
            mix[0] += w*va[p].x; mix[1] += w*va[p].y; mix[2] += w*va[p].z; mix[3] += w*va[p].w;
            mix[4] += w*vb[p].x; mix[5] += w*vb[p].y; mix[6] += w*vb[p].z; mix[7] += w*vb[p].w;
        }
    }
    __nv_bfloat16 hb[8], lb[8];
    #pragma unroll
    for (int q = 0; q < 8; q++) {
        hb[q] = __float2bfloat16(mix[q]);
        lb[q] = __float2bfloat16(mix[q] - __bfloat162float(hb[q]));
    }
    *(uint4*)(g_sh + (size_t)b*Cc + c8) = *(const uint4*)hb;
    *(uint4*)(g_sl + (size_t)b*Cc + c8) = *(const uint4*)lb;
}

// ---------- mma.sync GEMM: out[n][g][pos] = sum_c M[g,c]*smix[b,c] + bias[g] ----------
__global__ void __launch_bounds__(256, 2) gemm_mma(float* __restrict__ out) {
    extern __shared__ char dyn[];
    __nv_bfloat16* tiles = (__nv_bfloat16*)dyn;          // 4 tiles [128][TSTRIDE]
    uint32_t sbase = smem_u32(dyn);

    int t = threadIdx.x;
    int wid = t >> 5, lane = t & 31;
    int warp_m = wid & 3;        // g quadrant (32 rows)
    int warp_n = wid >> 2;       // token half (64 cols)
    int b0 = blockIdx.x * 128;
    int g0 = blockIdx.y * 128;

    const __nv_bfloat16* srcs[4] = {
        g_Mhi + (size_t)g0*Cc, g_Mlo + (size_t)g0*Cc,
        g_sh  + (size_t)b0*Cc, g_sl  + (size_t)b0*Cc };

    float acc[2][8][4];
    #pragma unroll
    for (int mt = 0; mt < 2; mt++)
        #pragma unroll
        for (int nt = 0; nt < 8; nt++)
            #pragma unroll
            for (int r = 0; r < 4; r++) acc[mt][nt][r] = 0.f;

    uint32_t aRow = (uint32_t)(warp_m*32 + (lane & 15));
    uint32_t aCol = (uint32_t)((lane >> 4) << 3);
    uint32_t aOff = (aRow*TSTRIDE + aCol) * 2;
    uint32_t bRow = (uint32_t)(warp_n*64 + (lane & 7) + ((lane >> 4) << 3));
    uint32_t bCol = (uint32_t)(((lane >> 3) & 1) << 3);
    uint32_t bOff = (bRow*TSTRIDE + bCol) * 2;

    for (int kc = 0; kc < 4; kc++) {
        #pragma unroll
        for (int m = 0; m < 4; m++) {
            const __nv_bfloat16* src = srcs[m] + kc*64;
            __nv_bfloat16* dst = tiles + m*(128*TSTRIDE);
            #pragma unroll
            for (int it = 0; it < 4; it++) {
                int idx  = it*256 + t;
                int row  = idx >> 3;
                int col8 = (idx & 7) << 3;
                uint4 v = *(const uint4*)(src + (size_t)row*Cc + col8);
                *(uint4*)(dst + row*TSTRIDE + col8) = v;
            }
        }
        __syncthreads();

        #pragma unroll
        for (int ks = 0; ks < 4; ks++) {
            uint32_t kByte = (uint32_t)(ks*16*2);
            uint32_t ahi[2][4], alo[2][4];
            #pragma unroll
            for (int mt = 0; mt < 2; mt++) {
                uint32_t ad = sbase + aOff + (uint32_t)(mt*16*TSTRIDE*2) + kByte;
                ldsm4(ahi[mt], ad);
                ldsm4(alo[mt], ad + TILE_BYTES);
            }
            uint32_t bhi[4][4], blo[4][4];
            #pragma unroll
            for (int ng = 0; ng < 4; ng++) {
                uint32_t bd = sbase + 2*TILE_BYTES + bOff + (uint32_t)(ng*16*TSTRIDE*2) + kByte;
                ldsm4(bhi[ng], bd);
                ldsm4(blo[ng], bd + TILE_BYTES);
            }
            #pragma unroll
            for (int mt = 0; mt < 2; mt++)
                #pragma unroll
                for (int ng = 0; ng < 4; ng++)
                    #pragma unroll
                    for (int jj = 0; jj < 2; jj++) {
                        int nt = ng*2 + jj;
                        mma16816(acc[mt][nt], ahi[mt], bhi[ng][2*jj], bhi[ng][2*jj+1]);
                        mma16816(acc[mt][nt], ahi[mt], blo[ng][2*jj], blo[ng][2*jj+1]);
                        mma16816(acc[mt][nt], alo[mt], bhi[ng][2*jj], bhi[ng][2*jj+1]);
                    }
        }
        __syncthreads();
    }

    float* stage = (float*)dyn;
    #pragma unroll
    for (int mt = 0; mt < 2; mt++) {
        int gr = warp_m*32 + mt*16 + (lane >> 2);
        #pragma unroll
        for (int nt = 0; nt < 8; nt++) {
            int tok = warp_n*64 + nt*8 + (lane & 3)*2;
            *(float2*)&stage[(size_t)gr*130 + tok]     = make_float2(acc[mt][nt][0], acc[mt][nt][1]);
            *(float2*)&stage[(size_t)(gr+8)*130 + tok] = make_float2(acc[mt][nt][2], acc[mt][nt][3]);
        }
    }
    __syncthreads();
    #pragma unroll 4
    for (int j = 0; j < 64; j++) {
        int f  = j*256 + t;
        int gl = f >> 7;
        int tl = f & 127;
        int g  = g0 + gl;
        int token = b0 + tl;
        int n   = token / 49;
        int pos = token - n*49;
        out[(size_t)n*(Cc*49) + (size_t)g*49 + pos] = stage[(size_t)gl*130 + tl] + g_bias[g];
    }
}

extern "C" void kernel_launch(void* const* d_in, const int* in_sizes, int n_in,
                              void* d_out, int out_size) {
    const float* features   = (const float*)d_in[0];
    const float* rois       = (const float*)d_in[1];
    const float* offs       = (const float*)d_in[2];
    const float* queries    = (const float*)d_in[3];
    const float* w_proj     = (const float*)d_in[4];
    const float* b_proj     = (const float*)d_in[5];
    const float* in_proj_w  = (const float*)d_in[6];
    const float* in_proj_b  = (const float*)d_in[7];
    const float* out_proj_w = (const float*)d_in[8];
    const float* out_proj_b = (const float*)d_in[9];
    float* out = (float*)d_out;

    static cudaStream_t s_side = nullptr;
    static cudaEvent_t  e_fork = nullptr, e_join = nullptr;
    if (!s_side) {
        cudaStreamCreateWithFlags(&s_side, cudaStreamNonBlocking);
        cudaEventCreateWithFlags(&e_fork, cudaEventDisableTiming);
        cudaEventCreateWithFlags(&e_join, cudaEventDisableTiming);
    }

    cudaFuncSetAttribute(gemm_mma, cudaFuncAttributeMaxDynamicSharedMemorySize, SMEM_DYN);

    // fork: pre-chain on side stream, transpose on main stream, join before sample
    cudaEventRecord(e_fork, 0);
    cudaStreamWaitEvent(s_side, e_fork, 0);
    pre_s1<<<114, 256, 0, s_side>>>(in_proj_w, in_proj_b, out_proj_w, w_proj, b_proj, queries);
    pre_s2<<<40, 256, 0, s_side>>>(w_proj, out_proj_w, out_proj_b);
    cudaEventRecord(e_join, s_side);

    transpose_feat<<<dim3(Hf*Wf/32, Cc/32, Bn), dim3(32, 8)>>>(features);

    cudaStreamWaitEvent(0, e_join, 0);
    sample_attn<<<NTOK/8, 256>>>(rois, offs);
    gemm_mma<<<dim3(NTOK/128, Cc/128), 256, SMEM_DYN>>>(out);
}

// round 12
// speedup vs baseline: 2.6198x; 1.0497x over previous
#include <cuda_runtime.h>
#include <cuda_fp16.h>
#include <cstdint>

#define Cc 256
#define Hf 128
#define Wf 128
#define Bn 4
#define Nroi 512
#define Pp 4
#define NTOK (Nroi*49)              // 25088
#define FSZ (Bn*Cc*Hf*Wf)           // 16777216
#define MSCALE 512.0f
#define MINV  (1.0f/512.0f)

// ---- scratch (device globals: allocation-free) ----
__device__ float g_ft[FSZ];                  // features transposed to [b][h*W+w][c]
__device__ __half g_sh[NTOK*Cc];             // smix (fp16)
__device__ __half g_Mhi[Cc*Cc];              // 512*M hi
__device__ __half g_Mlo[Cc*Cc];              // 512*M lo
__device__ float g_Mk[Cc*Cc];
__device__ float g_T [Cc*Cc];                // Wo@Wv
__device__ float g_Qb[49*Cc];
__device__ float g_Qk[49*Cc];
__device__ float g_cv[Cc];
__device__ float g_bias[Cc];

__device__ __forceinline__ uint32_t smem_u32(const void* p) {
    uint32_t a;
    asm("{ .reg .u64 t; cvta.to.shared.u64 t, %1; cvt.u32.u64 %0, t; }" : "=r"(a) : "l"(p));
    return a;
}
__device__ __forceinline__ void ldsm4(uint32_t* r, uint32_t addr) {
    asm volatile("ldmatrix.sync.aligned.m8n8.x4.shared.b16 {%0,%1,%2,%3}, [%4];"
        : "=r"(r[0]), "=r"(r[1]), "=r"(r[2]), "=r"(r[3]) : "r"(addr));
}
__device__ __forceinline__ void mma16816h(float* c, const uint32_t* a, uint32_t b0, uint32_t b1) {
    asm volatile("mma.sync.aligned.m16n8k16.row.col.f32.f16.f16.f32 "
        "{%0,%1,%2,%3}, {%4,%5,%6,%7}, {%8,%9}, {%0,%1,%2,%3};"
        : "+f"(c[0]), "+f"(c[1]), "+f"(c[2]), "+f"(c[3])
        : "r"(a[0]), "r"(a[1]), "r"(a[2]), "r"(a[3]), "r"(b0), "r"(b1));
}

#define TSTRIDE 72                          // fp16 per row (64 + 8 pad)
#define TILE_BYTES (128*TSTRIDE*2)          // 18432
#define SMEM_DYN 66560                      // max(3 tiles = 55296, stage = 66560)

// ================= pre-chain: 8-rows-per-block smem-tiled =================
__device__ __forceinline__ void tile8_accum(const float* __restrict__ B, int j,
                                            const float* As, float* acc) {
    #pragma unroll 4
    for (int k = 0; k < Cc; k += 4) {
        float b0 = B[(k+0)*Cc+j];
        float b1 = B[(k+1)*Cc+j];
        float b2 = B[(k+2)*Cc+j];
        float b3 = B[(k+3)*Cc+j];
        #pragma unroll
        for (int r = 0; r < 8; r++) {
            acc[r] += As[r*Cc+k+0]*b0 + As[r*Cc+k+1]*b1
                    + As[r*Cc+k+2]*b2 + As[r*Cc+k+3]*b3;
        }
    }
}

// stage 1: T = Wo@Wv (32 blk), Mk = Wk@w_proj (32 blk), Qb (49 blk), cv (1 blk)
__global__ void __launch_bounds__(256) pre_s1(const float* __restrict__ in_proj_w,
                                              const float* __restrict__ in_proj_b,
                                              const float* __restrict__ out_proj_w,
                                              const float* __restrict__ w_proj,
                                              const float* __restrict__ b_proj,
                                              const float* __restrict__ queries) {
    int bid = blockIdx.x, j = threadIdx.x;
    if (bid < 64) {
        __shared__ float As[8*Cc];
        const float* Arow; const float* B; float* out;
        if (bid < 32) {
            int r0 = bid*8;
            Arow = out_proj_w + r0*Cc; B = in_proj_w + 2*Cc*Cc; out = g_T + r0*Cc;
        } else {
            int r0 = (bid-32)*8;
            Arow = in_proj_w + Cc*Cc + r0*Cc; B = w_proj; out = g_Mk + r0*Cc;
        }
        for (int u = j; u < 8*Cc; u += 256) As[u] = Arow[u];
        __syncthreads();
        float acc[8] = {0,0,0,0,0,0,0,0};
        tile8_accum(B, j, As, acc);
        #pragma unroll
        for (int r = 0; r < 8; r++) out[r*Cc + j] = acc[r];
    } else if (bid < 113) {           // Qb row pos = bid-64
        __shared__ float qs[Cc];
        int pos = bid - 64;
        qs[j] = queries[pos*Cc + j];
        __syncthreads();
        const float4* Wr = (const float4*)(in_proj_w + (size_t)j*Cc);
        float a0=0.f,a1=0.f,a2=0.f,a3=0.f;
        #pragma unroll 8
        for (int k4 = 0; k4 < Cc/4; k4++) {
            float4 w = Wr[k4];
            a0 += w.x*qs[k4*4+0]; a1 += w.y*qs[k4*4+1];
            a2 += w.z*qs[k4*4+2]; a3 += w.w*qs[k4*4+3];
        }
        g_Qb[pos*Cc+j] = (a0+a1)+(a2+a3) + in_proj_b[j];
    } else {                          // cv
        __shared__ float bs[Cc];
        bs[j] = b_proj[j];
        __syncthreads();
        const float4* Wr = (const float4*)(in_proj_w + 2*Cc*Cc + (size_t)j*Cc);
        float a0=0.f,a1=0.f,a2=0.f,a3=0.f;
        #pragma unroll 8
        for (int k4 = 0; k4 < Cc/4; k4++) {
            float4 w = Wr[k4];
            a0 += w.x*bs[k4*4+0]; a1 += w.y*bs[k4*4+1];
            a2 += w.z*bs[k4*4+2]; a3 += w.w*bs[k4*4+3];
        }
        g_cv[j] = (a0+a1)+(a2+a3) + in_proj_b[2*Cc + j];
    }
}

// stage 2: M = T@w_proj (scaled fp16 hi/lo), Qk = (1/16) Qb@Mk, bias
__global__ void __launch_bounds__(256) pre_s2(const float* __restrict__ w_proj,
                                              const float* __restrict__ out_proj_w,
                                              const float* __restrict__ out_proj_b) {
    int bid = blockIdx.x, j = threadIdx.x;
    if (bid < 32) {                   // M rows
        __shared__ float As[8*Cc];
        int r0 = bid*8;
        for (int u = j; u < 8*Cc; u += 256) As[u] = g_T[r0*Cc + u];
        __syncthreads();
        float acc[8] = {0,0,0,0,0,0,0,0};
        tile8_accum(w_proj, j, As, acc);
        #pragma unroll
        for (int r = 0; r < 8; r++) {
            float s = acc[r] * MSCALE;
            __half h = __float2half_rn(s);
            g_Mhi[(r0+r)*Cc+j] = h;
            g_Mlo[(r0+r)*Cc+j] = __float2half_rn(s - __half2float(h));
        }
    } else if (bid < 39) {            // Qk rows
        __shared__ float As[8*Cc];
        int pos0 = (bid-32)*8;
        int rows = min(8, 49 - pos0);
        for (int u = j; u < rows*Cc; u += 256) As[u] = g_Qb[pos0*Cc + u];
        __syncthreads();
        float acc[8] = {0,0,0,0,0,0,0,0};
        tile8_accum(g_Mk, j, As, acc);
        #pragma unroll
        for (int r = 0; r < 8; r++)
            if (r < rows) g_Qk[(pos0+r)*Cc+j] = acc[r] * 0.0625f;
    } else {                          // bias
        __shared__ float cs[Cc];
        cs[j] = g_cv[j];
        __syncthreads();
        const float4* Wr = (const float4*)(out_proj_w + (size_t)j*Cc);
        float a0=0.f,a1=0.f,a2=0.f,a3=0.f;
        #pragma unroll 8
        for (int k4 = 0; k4 < Cc/4; k4++) {
            float4 w = Wr[k4];
            a0 += w.x*cs[k4*4+0]; a1 += w.y*cs[k4*4+1];
            a2 += w.z*cs[k4*4+2]; a3 += w.w*cs[k4*4+3];
        }
        g_bias[j] = (a0+a1)+(a2+a3) + out_proj_b[j];
    }
}

// ---------- features (B,C,H,W) -> (B,H*W,C), float4 both directions ----------
__global__ void transpose_feat(const float* __restrict__ feat) {
    __shared__ float tile[32][33];
    int b   = blockIdx.z;
    int hw0 = blockIdx.x * 32;
    int c0  = blockIdx.y * 32;
    int tx = threadIdx.x;    // 0..7  (quad index)
    int ty = threadIdx.y;    // 0..31
    const float* src = feat + (size_t)b*Cc*Hf*Wf;
    float*       dst = g_ft + (size_t)b*Hf*Wf*Cc;
    // load: row c0+ty, hw quad hw0+4tx
    float4 v = *(const float4*)(src + (size_t)(c0+ty)*(Hf*Wf) + hw0 + tx*4);
    tile[ty][tx*4+0] = v.x; tile[ty][tx*4+1] = v.y;
    tile[ty][tx*4+2] = v.z; tile[ty][tx*4+3] = v.w;
    __syncthreads();
    // store: row hw0+ty, c quad c0+4tx
    float4 o;
    o.x = tile[tx*4+0][ty]; o.y = tile[tx*4+1][ty];
    o.z = tile[tx*4+2][ty]; o.w = tile[tx*4+3][ty];
    *(float4*)(dst + (size_t)(hw0+ty)*Cc + c0 + tx*4) = o;
}

// ---------- fused sampling + scores + softmax + mix: warp-per-token ----------
__global__ void __launch_bounds__(256) sample_attn(const float* __restrict__ rois,
                                                   const float* __restrict__ offs,
                                                   int tok0) {
    int lane = threadIdx.x & 31;
    int wid  = threadIdx.x >> 5;
    int b = tok0 + blockIdx.x*8 + wid;    // token
    int c8 = lane * 8;
    int n = b / 49, pos = b - n*49;
    int oi = pos / 7, oj = pos - oi*7;

    const float* roi = rois + n*5;
    int   bidx = (int)roi[0];
    float x1 = roi[1]*0.0625f - 0.5f;
    float y1 = roi[2]*0.0625f - 0.5f;
    float rw = roi[3]*0.0625f - 0.5f - x1;
    float rh = roi[4]*0.0625f - 0.5f - y1;
    float bw = rw * (1.0f/7.0f);
    float bh = rh * (1.0f/7.0f);
    const float* fb = g_ft + (size_t)bidx*(Hf*Wf*Cc);

    float4 qk0 = *(const float4*)(g_Qk + pos*Cc + c8);
    float4 qk1 = *(const float4*)(g_Qk + pos*Cc + c8 + 4);

    int   y0a[Pp], x0a[Pp];
    float lya[Pp], lxa[Pp];
    bool  vld[Pp];
    #pragma unroll
    for (int p = 0; p < Pp; p++) {
        float odw = offs[((p*7+oi)*7+oj)*2 + 0];
        float odh = offs[((p*7+oi)*7+oj)*2 + 1];
        float x = x1 + (oj + 0.5f)*bw + 0.1f*rw*odw;
        float y = y1 + (oi + 0.5f)*bh + 0.1f*rh*odh;
        vld[p] = (y > -1.0f) && (y < (float)Hf) && (x > -1.0f) && (x < (float)Wf);
        float yc = fminf(fmaxf(y, 0.f), (float)(Hf-1));
        float xc = fminf(fmaxf(x, 0.f), (float)(Wf-1));
        y0a[p] = (int)floorf(yc); x0a[p] = (int)floorf(xc);
        lya[p] = yc - (float)y0a[p];
        lxa[p] = xc - (float)x0a[p];
    }
    bool same = (y0a[1]==y0a[0]) & (y0a[2]==y0a[0]) & (y0a[3]==y0a[0])
              & (x0a[1]==x0a[0]) & (x0a[2]==x0a[0]) & (x0a[3]==x0a[0]);

    float mix[8];
    if (same) {
        int y0 = y0a[0], x0 = x0a[0];
        int y1i = min(y0+1, Hf-1), x1i = min(x0+1, Wf-1);
        const float* p00 = fb + ((size_t)(y0 *Wf + x0 ))*Cc + c8;
        const float* p01 = fb + ((size_t)(y0 *Wf + x1i))*Cc + c8;
        const float* p10 = fb + ((size_t)(y1i*Wf + x0 ))*Cc + c8;
        const float* p11 = fb + ((size_t)(y1i*Wf + x1i))*Cc + c8;
        float4 ca[4], cb[4];
        ca[0]=*(const float4*)(p00); cb[0]=*(const float4*)(p00+4);
        ca[1]=*(const float4*)(p01); cb[1]=*(const float4*)(p01+4);
        ca[2]=*(const float4*)(p10); cb[2]=*(const float4*)(p10+4);
        ca[3]=*(const float4*)(p11); cb[3]=*(const float4*)(p11+4);
        float qd[4];
        #pragma unroll
        for (int c = 0; c < 4; c++)
            qd[c] = qk0.x*ca[c].x + qk0.y*ca[c].y + qk0.z*ca[c].z + qk0.w*ca[c].w
                  + qk1.x*cb[c].x + qk1.y*cb[c].y + qk1.z*cb[c].z + qk1.w*cb[c].w;
        #pragma unroll
        for (int off = 16; off; off >>= 1) {
            #pragma unroll
            for (int c = 0; c < 4; c++) qd[c] += __shfl_xor_sync(0xffffffffu, qd[c], off);
        }
        float sc[Pp];
        float w[Pp][4];
        #pragma unroll
        for (int p = 0; p < Pp; p++) {
            float ly = lya[p], lx = lxa[p];
            float hy = 1.f-ly, hx = 1.f-lx;
            w[p][0]=hy*hx; w[p][1]=hy*lx; w[p][2]=ly*hx; w[p][3]=ly*lx;
            float s = w[p][0]*qd[0] + w[p][1]*qd[1] + w[p][2]*qd[2] + w[p][3]*qd[3];
            sc[p] = vld[p] ? s : 0.f;
        }
        float m = fmaxf(fmaxf(sc[0], sc[1]), fmaxf(sc[2], sc[3]));
        float e[Pp], sum = 0.f;
        #pragma unroll
        for (int p = 0; p < Pp; p++) { e[p] = __expf(sc[p]-m); sum += e[p]; }
        float inv = 1.f/sum;
        float W[4] = {0,0,0,0};
        #pragma unroll
        for (int p = 0; p < Pp; p++) {
            float a = vld[p] ? e[p]*inv : 0.f;
            W[0] += a*w[p][0]; W[1] += a*w[p][1]; W[2] += a*w[p][2]; W[3] += a*w[p][3];
        }
        #pragma unroll
        for (int q = 0; q < 4; q++) {
            mix[q]   = W[0]*((&ca[0].x)[q]) + W[1]*((&ca[1].x)[q])
                     + W[2]*((&ca[2].x)[q]) + W[3]*((&ca[3].x)[q]);
            mix[q+4] = W[0]*((&cb[0].x)[q]) + W[1]*((&cb[1].x)[q])
                     + W[2]*((&cb[2].x)[q]) + W[3]*((&cb[3].x)[q]);
        }
    } else {
        float4 va[Pp], vb[Pp];
        float sc[Pp];
        #pragma unroll
        for (int p = 0; p < Pp; p++) {
            int y0 = y0a[p], x0 = x0a[p];
            int y1i = min(y0+1, Hf-1), x1i = min(x0+1, Wf-1);
            float ly = lya[p], lx = lxa[p];
            float hy = 1.f - ly, hx = 1.f - lx;
            const float* p00 = fb + ((size_t)(y0 *Wf + x0 ))*Cc + c8;
            const float* p01 = fb + ((size_t)(y0 *Wf + x1i))*Cc + c8;
            const float* p10 = fb + ((size_t)(y1i*Wf + x0 ))*Cc + c8;
            const float* p11 = fb + ((size_t)(y1i*Wf + x1i))*Cc + c8;
            float4 a00 = *(const float4*)(p00),     b00 = *(const float4*)(p00 + 4);
            float4 a01 = *(const float4*)(p01),     b01 = *(const float4*)(p01 + 4);
            float4 a10 = *(const float4*)(p10),     b10 = *(const float4*)(p10 + 4);
            float4 a11 = *(const float4*)(p11),     b11 = *(const float4*)(p11 + 4);
            float w00 = hy*hx, w01 = hy*lx, w10 = ly*hx, w11 = ly*lx;
            float4 u, v;
            u.x = w00*a00.x + w01*a01.x + w10*a10.x + w11*a11.x;
            u.y = w00*a00.y + w01*a01.y + w10*a10.y + w11*a11.y;
            u.z = w00*a00.z + w01*a01.z + w10*a10.z + w11*a11.z;
            u.w = w00*a00.w + w01*a01.w + w10*a10.w + w11*a11.w;
            v.x = w00*b00.x + w01*b01.x + w10*b10.x + w11*b11.x;
            v.y = w00*b00.y + w01*b01.y + w10*b10.y + w11*b11.y;
            v.z = w00*b00.z + w01*b01.z + w10*b10.z + w11*b11.z;
            v.w = w00*b00.w + w01*b01.w + w10*b10.w + w11*b11.w;
            if (!vld[p]) {
                u = make_float4(0.f,0.f,0.f,0.f);
                v = make_float4(0.f,0.f,0.f,0.f);
            }
            va[p] = u; vb[p] = v;
            sc[p] = qk0.x*u.x + qk0.y*u.y + qk0.z*u.z + qk0.w*u.w
                  + qk1.x*v.x + qk1.y*v.y + qk1.z*v.z + qk1.w*v.w;
        }
        #pragma unroll
        for (int off = 16; off; off >>= 1) {
            #pragma unroll
            for (int p = 0; p < Pp; p++) sc[p] += __shfl_xor_sync(0xffffffffu, sc[p], off);
        }
        float m = fmaxf(fmaxf(sc[0], sc[1]), fmaxf(sc[2], sc[3]));
        float e[Pp], sum = 0.f;
        #pragma unroll
        for (int p = 0; p < Pp; p++) { e[p] = __expf(sc[p]-m); sum += e[p]; }
        float inv = 1.f/sum;
        #pragma unroll
        for (int q = 0; q < 8; q++) mix[q] = 0.f;
        #pragma unroll
        for (int p = 0; p < Pp; p++) {
            float w = e[p]*inv;
            mix[0] += w*va[p].x; mix[1] += w*va[p].y; mix[2] += w*va[p].z; mix[3] += w*va[p].w;
            mix[4] += w*vb[p].x; mix[5] += w*vb[p].y; mix[6] += w*vb[p].z; mix[7] += w*vb[p].w;
        }
    }
    __half hb[8];
    #pragma unroll
    for (int q = 0; q < 8; q++) hb[q] = __float2half_rn(mix[q]);
    *(uint4*)(g_sh + (size_t)b*Cc + c8) = *(const uint4*)hb;
}

// ---------- mma.sync GEMM (fp16 2-term): out = (1/512)*(Mhi+Mlo)@smix + bias ----------
__global__ void __launch_bounds__(256, 2) gemm_mma(float* __restrict__ out, int tile0) {
    extern __shared__ char dyn[];
    __half* tiles = (__half*)dyn;               // 3 tiles [128][TSTRIDE]
    uint32_t sbase = smem_u32(dyn);

    int t = threadIdx.x;
    int wid = t >> 5, lane = t & 31;
    int warp_m = wid & 3;        // g quadrant (32 rows)
    int warp_n = wid >> 2;       // token half (64 cols)
    int b0 = (tile0 + blockIdx.x) * 128;
    int g0 = blockIdx.y * 128;

    const __half* srcs[3] = {
        g_Mhi + (size_t)g0*Cc, g_Mlo + (size_t)g0*Cc, g_sh + (size_t)b0*Cc };

    float acc[2][8][4];
    #pragma unroll
    for (int mt = 0; mt < 2; mt++)
        #pragma unroll
        for (int nt = 0; nt < 8; nt++)
            #pragma unroll
            for (int r = 0; r < 4; r++) acc[mt][nt][r] = 0.f;

    uint32_t aRow = (uint32_t)(warp_m*32 + (lane & 15));
    uint32_t aCol = (uint32_t)((lane >> 4) << 3);
    uint32_t aOff = (aRow*TSTRIDE + aCol) * 2;
    uint32_t bRow = (uint32_t)(warp_n*64 + (lane & 7) + ((lane >> 4) << 3));
    uint32_t bCol = (uint32_t)(((lane >> 3) & 1) << 3);
    uint32_t bOff = (bRow*TSTRIDE + bCol) * 2;

    for (int kc = 0; kc < 4; kc++) {
        // load 3 tiles: 128 rows x 64 fp16 of this K-chunk
        #pragma unroll
        for (int m = 0; m < 3; m++) {
            const __half* src = srcs[m] + kc*64;
            __half* dst = tiles + m*(128*TSTRIDE);
            #pragma unroll
            for (int it = 0; it < 4; it++) {
                int idx  = it*256 + t;
                int row  = idx >> 3;
                int col8 = (idx & 7) << 3;
                uint4 v = *(const uint4*)(src + (size_t)row*Cc + col8);
                *(uint4*)(dst + row*TSTRIDE + col8) = v;
            }
        }
        __syncthreads();

        #pragma unroll
        for (int ks = 0; ks < 4; ks++) {
            uint32_t kByte = (uint32_t)(ks*16*2);
            uint32_t ahi[2][4], alo[2][4];
            #pragma unroll
            for (int mt = 0; mt < 2; mt++) {
                uint32_t ad = sbase + aOff + (uint32_t)(mt*16*TSTRIDE*2) + kByte;
                ldsm4(ahi[mt], ad);
                ldsm4(alo[mt], ad + TILE_BYTES);
            }
            uint32_t bf[4][4];
            #pragma unroll
            for (int ng = 0; ng < 4; ng++) {
                uint32_t bd = sbase + 2*TILE_BYTES + bOff + (uint32_t)(ng*16*TSTRIDE*2) + kByte;
                ldsm4(bf[ng], bd);
            }
            #pragma unroll
            for (int mt = 0; mt < 2; mt++)
                #pragma unroll
                for (int ng = 0; ng < 4; ng++)
                    #pragma unroll
                    for (int jj = 0; jj < 2; jj++) {
                        int nt = ng*2 + jj;
                        mma16816h(acc[mt][nt], ahi[mt], bf[ng][2*jj], bf[ng][2*jj+1]);
                        mma16816h(acc[mt][nt], alo[mt], bf[ng][2*jj], bf[ng][2*jj+1]);
                    }
        }
        __syncthreads();
    }

    float* stage = (float*)dyn;                 // 128*130*4 = 66560
    #pragma unroll
    for (int mt = 0; mt < 2; mt++) {
        int gr = warp_m*32 + mt*16 + (lane >> 2);
        #pragma unroll
        for (int nt = 0; nt < 8; nt++) {
            int tok = warp_n*64 + nt*8 + (lane & 3)*2;
            *(float2*)&stage[(size_t)gr*130 + tok]     = make_float2(acc[mt][nt][0], acc[mt][nt][1]);
            *(float2*)&stage[(size_t)(gr+8)*130 + tok] = make_float2(acc[mt][nt][2], acc[mt][nt][3]);
        }
    }
    __syncthreads();
    #pragma unroll 4
    for (int j = 0; j < 64; j++) {
        int f  = j*256 + t;
        int gl = f >> 7;
        int tl = f & 127;
        int g  = g0 + gl;
        int token = b0 + tl;
        int n   = token / 49;
        int pos = token - n*49;
        out[(size_t)n*(Cc*49) + (size_t)g*49 + pos] = stage[(size_t)gl*130 + tl]*MINV + g_bias[g];
    }
}

extern "C" void kernel_launch(void* const* d_in, const int* in_sizes, int n_in,
                              void* d_out, int out_size) {
    const float* features   = (const float*)d_in[0];
    const float* rois       = (const float*)d_in[1];
    const float* offs       = (const float*)d_in[2];
    const float* queries    = (const float*)d_in[3];
    const float* w_proj     = (const float*)d_in[4];
    const float* b_proj     = (const float*)d_in[5];
    const float* in_proj_w  = (const float*)d_in[6];
    const float* in_proj_b  = (const float*)d_in[7];
    const float* out_proj_w = (const float*)d_in[8];
    const float* out_proj_b = (const float*)d_in[9];
    float* out = (float*)d_out;

    static cudaStream_t s_side = nullptr;
    static cudaEvent_t  e_fork = nullptr, e_join = nullptr, e_T = nullptr,
                        e_A = nullptr, e_B = nullptr;
    if (!s_side) {
        cudaStreamCreateWithFlags(&s_side, cudaStreamNonBlocking);
        cudaEventCreateWithFlags(&e_fork, cudaEventDisableTiming);
        cudaEventCreateWithFlags(&e_join, cudaEventDisableTiming);
        cudaEventCreateWithFlags(&e_T,    cudaEventDisableTiming);
        cudaEventCreateWithFlags(&e_A,    cudaEventDisableTiming);
        cudaEventCreateWithFlags(&e_B,    cudaEventDisableTiming);
    }

    cudaFuncSetAttribute(gemm_mma, cudaFuncAttributeMaxDynamicSharedMemorySize, SMEM_DYN);

    // fork: pre-chain on side stream, transpose on main stream
    cudaEventRecord(e_fork, 0);
    cudaStreamWaitEvent(s_side, e_fork, 0);
    pre_s1<<<114, 256, 0, s_side>>>(in_proj_w, in_proj_b, out_proj_w, w_proj, b_proj, queries);
    pre_s2<<<40, 256, 0, s_side>>>(w_proj, out_proj_w, out_proj_b);
    cudaEventRecord(e_join, s_side);

    transpose_feat<<<dim3(Hf*Wf/32, Cc/32, Bn), dim3(8, 32)>>>(features);
    cudaEventRecord(e_T, 0);

    // half A on main
    cudaStreamWaitEvent(0, e_join, 0);
    sample_attn<<<NTOK/16, 256>>>(rois, offs, 0);
    cudaEventRecord(e_A, 0);

    // half B on side, overlapping gemm A
    cudaStreamWaitEvent(s_side, e_T, 0);
    cudaStreamWaitEvent(s_side, e_A, 0);
    sample_attn<<<NTOK/16, 256, 0, s_side>>>(rois, offs, NTOK/2);
    cudaEventRecord(e_B, s_side);

    gemm_mma<<<dim3(NTOK/256, Cc/128), 256, SMEM_DYN>>>(out, 0);

    cudaStreamWaitEvent(0, e_B, 0);
    gemm_mma<<<dim3(NTOK/256, Cc/128), 256, SMEM_DYN>>>(out, NTOK/256);
}

// round 13
// speedup vs baseline: 2.8801x; 1.0993x over previous
#include <cuda_runtime.h>
#include <cuda_fp16.h>
#include <cstdint>

#define Cc 256
#define Hf 128
#define Wf 128
#define Bn 4
#define Nroi 512
#define Pp 4
#define NTOK (Nroi*49)              // 25088
#define FSZ (Bn*Cc*Hf*Wf)           // 16777216
#define MSCALE 512.0f
#define MINV  (1.0f/512.0f)

// ---- scratch (device globals: allocation-free) ----
__device__ float g_ft[FSZ];                  // features transposed to [b][h*W+w][c]
__device__ __half g_sh[NTOK*Cc];             // smix (fp16)
__device__ __half g_Mh[Cc*Cc];               // 512*M (fp16)
__device__ float g_Mk[Cc*Cc];
__device__ float g_T [Cc*Cc];                // Wo@Wv
__device__ float g_Qb[49*Cc];
__device__ float g_Qk[49*Cc];
__device__ float g_cv[Cc];
__device__ float g_bias[Cc];

__device__ __forceinline__ uint32_t smem_u32(const void* p) {
    uint32_t a;
    asm("{ .reg .u64 t; cvta.to.shared.u64 t, %1; cvt.u32.u64 %0, t; }" : "=r"(a) : "l"(p));
    return a;
}
__device__ __forceinline__ void ldsm4(uint32_t* r, uint32_t addr) {
    asm volatile("ldmatrix.sync.aligned.m8n8.x4.shared.b16 {%0,%1,%2,%3}, [%4];"
        : "=r"(r[0]), "=r"(r[1]), "=r"(r[2]), "=r"(r[3]) : "r"(addr));
}
__device__ __forceinline__ void mma16816h(float* c, const uint32_t* a, uint32_t b0, uint32_t b1) {
    asm volatile("mma.sync.aligned.m16n8k16.row.col.f32.f16.f16.f32 "
        "{%0,%1,%2,%3}, {%4,%5,%6,%7}, {%8,%9}, {%0,%1,%2,%3};"
        : "+f"(c[0]), "+f"(c[1]), "+f"(c[2]), "+f"(c[3])
        : "r"(a[0]), "r"(a[1]), "r"(a[2]), "r"(a[3]), "r"(b0), "r"(b1));
}
__device__ __forceinline__ void cp16(uint32_t dst, const void* src) {
    asm volatile("cp.async.cg.shared.global [%0], [%1], 16;" :: "r"(dst), "l"(src) : "memory");
}
#define CP_COMMIT()  asm volatile("cp.async.commit_group;" ::: "memory")
#define CP_WAIT(n)   asm volatile("cp.async.wait_group %0;" :: "n"(n) : "memory")

#define TSTRIDE 72                          // fp16 per row (64 + 8 pad)
#define TILE_BYTES (128*TSTRIDE*2)          // 18432 (one 128x64 fp16 tile)
#define STAGE_BYTES (2*TILE_BYTES)          // A+B per pipeline stage = 36864
#define SMEM_DYN (2*STAGE_BYTES)            // 73728 (>= 66560 epilogue stage)

// ================= pre-chain =================
__device__ __forceinline__ void tile8_accum(const float* __restrict__ B, int j,
                                            const float* As, float* acc) {
    #pragma unroll 4
    for (int k = 0; k < Cc; k += 4) {
        float b0 = B[(k+0)*Cc+j];
        float b1 = B[(k+1)*Cc+j];
        float b2 = B[(k+2)*Cc+j];
        float b3 = B[(k+3)*Cc+j];
        #pragma unroll
        for (int r = 0; r < 8; r++) {
            acc[r] += As[r*Cc+k+0]*b0 + As[r*Cc+k+1]*b1
                    + As[r*Cc+k+2]*b2 + As[r*Cc+k+3]*b3;
        }
    }
}

// k-path stage 1: Mk = Wk@w_proj (32 blk), Qb (49 blk)
__global__ void __launch_bounds__(256) pre_k(const float* __restrict__ in_proj_w,
                                             const float* __restrict__ in_proj_b,
                                             const float* __restrict__ w_proj,
                                             const float* __restrict__ queries) {
    int bid = blockIdx.x, j = threadIdx.x;
    if (bid < 32) {
        __shared__ float As[8*Cc];
        int r0 = bid*8;
        const float* Arow = in_proj_w + Cc*Cc + r0*Cc;
        for (int u = j; u < 8*Cc; u += 256) As[u] = Arow[u];
        __syncthreads();
        float acc[8] = {0,0,0,0,0,0,0,0};
        tile8_accum(w_proj, j, As, acc);
        #pragma unroll
        for (int r = 0; r < 8; r++) g_Mk[(r0+r)*Cc + j] = acc[r];
    } else {                          // Qb row pos = bid-32
        __shared__ float qs[Cc];
        int pos = bid - 32;
        qs[j] = queries[pos*Cc + j];
        __syncthreads();
        const float4* Wr = (const float4*)(in_proj_w + (size_t)j*Cc);
        float a0=0.f,a1=0.f,a2=0.f,a3=0.f;
        #pragma unroll 8
        for (int k4 = 0; k4 < Cc/4; k4++) {
            float4 w = Wr[k4];
            a0 += w.x*qs[k4*4+0]; a1 += w.y*qs[k4*4+1];
            a2 += w.z*qs[k4*4+2]; a3 += w.w*qs[k4*4+3];
        }
        g_Qb[pos*Cc+j] = (a0+a1)+(a2+a3) + in_proj_b[j];
    }
}

// k-path stage 2: Qk = (1/16) Qb@Mk (7 blk)
__global__ void __launch_bounds__(256) pre_qk() {
    int bid = blockIdx.x, j = threadIdx.x;
    __shared__ float As[8*Cc];
    int pos0 = bid*8;
    int rows = min(8, 49 - pos0);
    for (int u = j; u < rows*Cc; u += 256) As[u] = g_Qb[pos0*Cc + u];
    __syncthreads();
    float acc[8] = {0,0,0,0,0,0,0,0};
    tile8_accum(g_Mk, j, As, acc);
    #pragma unroll
    for (int r = 0; r < 8; r++)
        if (r < rows) g_Qk[(pos0+r)*Cc+j] = acc[r] * 0.0625f;
}

// m-path stage 1: T = Wo@Wv (32 blk), cv (1 blk)
__global__ void __launch_bounds__(256) pre_m1(const float* __restrict__ in_proj_w,
                                              const float* __restrict__ in_proj_b,
                                              const float* __restrict__ out_proj_w,
                                              const float* __restrict__ b_proj) {
    int bid = blockIdx.x, j = threadIdx.x;
    if (bid < 32) {
        __shared__ float As[8*Cc];
        int r0 = bid*8;
        const float* Arow = out_proj_w + r0*Cc;
        const float* B = in_proj_w + 2*Cc*Cc;
        for (int u = j; u < 8*Cc; u += 256) As[u] = Arow[u];
        __syncthreads();
        float acc[8] = {0,0,0,0,0,0,0,0};
        tile8_accum(B, j, As, acc);
        #pragma unroll
        for (int r = 0; r < 8; r++) g_T[(r0+r)*Cc + j] = acc[r];
    } else {                          // cv
        __shared__ float bs[Cc];
        bs[j] = b_proj[j];
        __syncthreads();
        const float4* Wr = (const float4*)(in_proj_w + 2*Cc*Cc + (size_t)j*Cc);
        float a0=0.f,a1=0.f,a2=0.f,a3=0.f;
        #pragma unroll 8
        for (int k4 = 0; k4 < Cc/4; k4++) {
            float4 w = Wr[k4];
            a0 += w.x*bs[k4*4+0]; a1 += w.y*bs[k4*4+1];
            a2 += w.z*bs[k4*4+2]; a3 += w.w*bs[k4*4+3];
        }
        g_cv[j] = (a0+a1)+(a2+a3) + in_proj_b[2*Cc + j];
    }
}

// m-path stage 2: M = T@w_proj (scaled fp16, 32 blk), bias (1 blk)
__global__ void __launch_bounds__(256) pre_m2(const float* __restrict__ w_proj,
                                              const float* __restrict__ out_proj_w,
                                              const float* __restrict__ out_proj_b) {
    int bid = blockIdx.x, j = threadIdx.x;
    if (bid < 32) {
        __shared__ float As[8*Cc];
        int r0 = bid*8;
        for (int u = j; u < 8*Cc; u += 256) As[u] = g_T[r0*Cc + u];
        __syncthreads();
        float acc[8] = {0,0,0,0,0,0,0,0};
        tile8_accum(w_proj, j, As, acc);
        #pragma unroll
        for (int r = 0; r < 8; r++)
            g_Mh[(r0+r)*Cc+j] = __float2half_rn(acc[r] * MSCALE);
    } else {                          // bias
        __shared__ float cs[Cc];
        cs[j] = g_cv[j];
        __syncthreads();
        const float4* Wr = (const float4*)(out_proj_w + (size_t)j*Cc);
        float a0=0.f,a1=0.f,a2=0.f,a3=0.f;
        #pragma unroll 8
        for (int k4 = 0; k4 < Cc/4; k4++) {
            float4 w = Wr[k4];
            a0 += w.x*cs[k4*4+0]; a1 += w.y*cs[k4*4+1];
            a2 += w.z*cs[k4*4+2]; a3 += w.w*cs[k4*4+3];
        }
        g_bias[j] = (a0+a1)+(a2+a3) + out_proj_b[j];
    }
}

// ---------- features (B,C,H,W) -> (B,H*W,C), float4 both directions ----------
__global__ void transpose_feat(const float* __restrict__ feat) {
    __shared__ float tile[32][33];
    int b   = blockIdx.z;
    int hw0 = blockIdx.x * 32;
    int c0  = blockIdx.y * 32;
    int tx = threadIdx.x;    // 0..7
    int ty = threadIdx.y;    // 0..31
    const float* src = feat + (size_t)b*Cc*Hf*Wf;
    float*       dst = g_ft + (size_t)b*Hf*Wf*Cc;
    float4 v = *(const float4*)(src + (size_t)(c0+ty)*(Hf*Wf) + hw0 + tx*4);
    tile[ty][tx*4+0] = v.x; tile[ty][tx*4+1] = v.y;
    tile[ty][tx*4+2] = v.z; tile[ty][tx*4+3] = v.w;
    __syncthreads();
    float4 o;
    o.x = tile[tx*4+0][ty]; o.y = tile[tx*4+1][ty];
    o.z = tile[tx*4+2][ty]; o.w = tile[tx*4+3][ty];
    *(float4*)(dst + (size_t)(hw0+ty)*Cc + c0 + tx*4) = o;
}

// ---------- fused sampling + scores + softmax + mix: warp-per-token ----------
__global__ void __launch_bounds__(256) sample_attn(const float* __restrict__ rois,
                                                   const float* __restrict__ offs,
                                                   int tok0) {
    int lane = threadIdx.x & 31;
    int wid  = threadIdx.x >> 5;
    int b = tok0 + blockIdx.x*8 + wid;    // token
    int c8 = lane * 8;
    int n = b / 49, pos = b - n*49;
    int oi = pos / 7, oj = pos - oi*7;

    const float* roi = rois + n*5;
    int   bidx = (int)roi[0];
    float x1 = roi[1]*0.0625f - 0.5f;
    float y1 = roi[2]*0.0625f - 0.5f;
    float rw = roi[3]*0.0625f - 0.5f - x1;
    float rh = roi[4]*0.0625f - 0.5f - y1;
    float bw = rw * (1.0f/7.0f);
    float bh = rh * (1.0f/7.0f);
    const float* fb = g_ft + (size_t)bidx*(Hf*Wf*Cc);

    float4 qk0 = *(const float4*)(g_Qk + pos*Cc + c8);
    float4 qk1 = *(const float4*)(g_Qk + pos*Cc + c8 + 4);

    int   y0a[Pp], x0a[Pp];
    float lya[Pp], lxa[Pp];
    bool  vld[Pp];
    #pragma unroll
    for (int p = 0; p < Pp; p++) {
        float odw = offs[((p*7+oi)*7+oj)*2 + 0];
        float odh = offs[((p*7+oi)*7+oj)*2 + 1];
        float x = x1 + (oj + 0.5f)*bw + 0.1f*rw*odw;
        float y = y1 + (oi + 0.5f)*bh + 0.1f*rh*odh;
        vld[p] = (y > -1.0f) && (y < (float)Hf) && (x > -1.0f) && (x < (float)Wf);
        float yc = fminf(fmaxf(y, 0.f), (float)(Hf-1));
        float xc = fminf(fmaxf(x, 0.f), (float)(Wf-1));
        y0a[p] = (int)floorf(yc); x0a[p] = (int)floorf(xc);
        lya[p] = yc - (float)y0a[p];
        lxa[p] = xc - (float)x0a[p];
    }
    bool same = (y0a[1]==y0a[0]) & (y0a[2]==y0a[0]) & (y0a[3]==y0a[0])
              & (x0a[1]==x0a[0]) & (x0a[2]==x0a[0]) & (x0a[3]==x0a[0]);

    float mix[8];
    if (same) {
        int y0 = y0a[0], x0 = x0a[0];
        int y1i = min(y0+1, Hf-1), x1i = min(x0+1, Wf-1);
        const float* p00 = fb + ((size_t)(y0 *Wf + x0 ))*Cc + c8;
        const float* p01 = fb + ((size_t)(y0 *Wf + x1i))*Cc + c8;
        const float* p10 = fb + ((size_t)(y1i*Wf + x0 ))*Cc + c8;
        const float* p11 = fb + ((size_t)(y1i*Wf + x1i))*Cc + c8;
        float4 ca[4], cb[4];
        ca[0]=*(const float4*)(p00); cb[0]=*(const float4*)(p00+4);
        ca[1]=*(const float4*)(p01); cb[1]=*(const float4*)(p01+4);
        ca[2]=*(const float4*)(p10); cb[2]=*(const float4*)(p10+4);
        ca[3]=*(const float4*)(p11); cb[3]=*(const float4*)(p11+4);
        float qd[4];
        #pragma unroll
        for (int c = 0; c < 4; c++)
            qd[c] = qk0.x*ca[c].x + qk0.y*ca[c].y + qk0.z*ca[c].z + qk0.w*ca[c].w
                  + qk1.x*cb[c].x + qk1.y*cb[c].y + qk1.z*cb[c].z + qk1.w*cb[c].w;
        #pragma unroll
        for (int off = 16; off; off >>= 1) {
            #pragma unroll
            for (int c = 0; c < 4; c++) qd[c] += __shfl_xor_sync(0xffffffffu, qd[c], off);
        }
        float sc[Pp];
        float w[Pp][4];
        #pragma unroll
        for (int p = 0; p < Pp; p++) {
            float ly = lya[p], lx = lxa[p];
            float hy = 1.f-ly, hx = 1.f-lx;
            w[p][0]=hy*hx; w[p][1]=hy*lx; w[p][2]=ly*hx; w[p][3]=ly*lx;
            float s = w[p][0]*qd[0] + w[p][1]*qd[1] + w[p][2]*qd[2] + w[p][3]*qd[3];
            sc[p] = vld[p] ? s : 0.f;
        }
        float m = fmaxf(fmaxf(sc[0], sc[1]), fmaxf(sc[2], sc[3]));
        float e[Pp], sum = 0.f;
        #pragma unroll
        for (int p = 0; p < Pp; p++) { e[p] = __expf(sc[p]-m); sum += e[p]; }
        float inv = 1.f/sum;
        float W[4] = {0,0,0,0};
        #pragma unroll
        for (int p = 0; p < Pp; p++) {
            float a = vld[p] ? e[p]*inv : 0.f;
            W[0] += a*w[p][0]; W[1] += a*w[p][1]; W[2] += a*w[p][2]; W[3] += a*w[p][3];
        }
        #pragma unroll
        for (int q = 0; q < 4; q++) {
            mix[q]   = W[0]*((&ca[0].x)[q]) + W[1]*((&ca[1].x)[q])
                     + W[2]*((&ca[2].x)[q]) + W[3]*((&ca[3].x)[q]);
            mix[q+4] = W[0]*((&cb[0].x)[q]) + W[1]*((&cb[1].x)[q])
                     + W[2]*((&cb[2].x)[q]) + W[3]*((&cb[3].x)[q]);
        }
    } else {
        float4 va[Pp], vb[Pp];
        float sc[Pp];
        #pragma unroll
        for (int p = 0; p < Pp; p++) {
            int y0 = y0a[p], x0 = x0a[p];
            int y1i = min(y0+1, Hf-1), x1i = min(x0+1, Wf-1);
            float ly = lya[p], lx = lxa[p];
            float hy = 1.f - ly, hx = 1.f - lx;
            const float* p00 = fb + ((size_t)(y0 *Wf + x0 ))*Cc + c8;
            const float* p01 = fb + ((size_t)(y0 *Wf + x1i))*Cc + c8;
            const float* p10 = fb + ((size_t)(y1i*Wf + x0 ))*Cc + c8;
            const float* p11 = fb + ((size_t)(y1i*Wf + x1i))*Cc + c8;
            float4 a00 = *(const float4*)(p00),     b00 = *(const float4*)(p00 + 4);
            float4 a01 = *(const float4*)(p01),     b01 = *(const float4*)(p01 + 4);
            float4 a10 = *(const float4*)(p10),     b10 = *(const float4*)(p10 + 4);
            float4 a11 = *(const float4*)(p11),     b11 = *(const float4*)(p11 + 4);
            float w00 = hy*hx, w01 = hy*lx, w10 = ly*hx, w11 = ly*lx;
            float4 u, v;
            u.x = w00*a00.x + w01*a01.x + w10*a10.x + w11*a11.x;
            u.y = w00*a00.y + w01*a01.y + w10*a10.y + w11*a11.y;
            u.z = w00*a00.z + w01*a01.z + w10*a10.z + w11*a11.z;
            u.w = w00*a00.w + w01*a01.w + w10*a10.w + w11*a11.w;
            v.x = w00*b00.x + w01*b01.x + w10*b10.x + w11*b11.x;
            v.y = w00*b00.y + w01*b01.y + w10*b10.y + w11*b11.y;
            v.z = w00*b00.z + w01*b01.z + w10*b10.z + w11*b11.z;
            v.w = w00*b00.w + w01*b01.w + w10*b10.w + w11*b11.w;
            if (!vld[p]) {
                u = make_float4(0.f,0.f,0.f,0.f);
                v = make_float4(0.f,0.f,0.f,0.f);
            }
            va[p] = u; vb[p] = v;
            sc[p] = qk0.x*u.x + qk0.y*u.y + qk0.z*u.z + qk0.w*u.w
                  + qk1.x*v.x + qk1.y*v.y + qk1.z*v.z + qk1.w*v.w;
        }
        #pragma unroll
        for (int off = 16; off; off >>= 1) {
            #pragma unroll
            for (int p = 0; p < Pp; p++) sc[p] += __shfl_xor_sync(0xffffffffu, sc[p], off);
        }
        float m = fmaxf(fmaxf(sc[0], sc[1]), fmaxf(sc[2], sc[3]));
        float e[Pp], sum = 0.f;
        #pragma unroll
        for (int p = 0; p < Pp; p++) { e[p] = __expf(sc[p]-m); sum += e[p]; }
        float inv = 1.f/sum;
        #pragma unroll
        for (int q = 0; q < 8; q++) mix[q] = 0.f;
        #pragma unroll
        for (int p = 0; p < Pp; p++) {
            float w = e[p]*inv;
            mix[0] += w*va[p].x; mix[1] += w*va[p].y; mix[2] += w*va[p].z; mix[3] += w*va[p].w;
            mix[4] += w*vb[p].x; mix[5] += w*vb[p].y; mix[6] += w*vb[p].z; mix[7] += w*vb[p].w;
        }
    }
    __half hb[8];
    #pragma unroll
    for (int q = 0; q < 8; q++) hb[q] = __float2half_rn(mix[q]);
    *(uint4*)(g_sh + (size_t)b*Cc + c8) = *(const uint4*)hb;
}

// ---------- mma.sync GEMM (fp16 1-term, cp.async double-buffered) ----------
// out = (1/512)*Mh@smix + bias; CTA tile 128(g) x 128(tok), K=256 in 4 chunks.
__global__ void __launch_bounds__(256, 2) gemm_mma(float* __restrict__ out, int tile0) {
    extern __shared__ char dyn[];
    uint32_t sbase = smem_u32(dyn);

    int t = threadIdx.x;
    int wid = t >> 5, lane = t & 31;
    int warp_m = wid & 3;        // g quadrant (32 rows)
    int warp_n = wid >> 2;       // token half (64 cols)
    int b0 = (tile0 + blockIdx.x) * 128;
    int g0 = blockIdx.y * 128;

    const __half* srcA = g_Mh + (size_t)g0*Cc;
    const __half* srcB = g_sh + (size_t)b0*Cc;

    // per-thread cp.async mapping: 4 rows x 16B per tile
    int lrow  = t >> 3;              // 0..31 base row (x4 groups)
    int lcol8 = (t & 7) << 3;        // fp16 col 0..56 step 8

    float acc[2][8][4];
    #pragma unroll
    for (int mt = 0; mt < 2; mt++)
        #pragma unroll
        for (int nt = 0; nt < 8; nt++)
            #pragma unroll
            for (int r = 0; r < 4; r++) acc[mt][nt][r] = 0.f;

    uint32_t aRow = (uint32_t)(warp_m*32 + (lane & 15));
    uint32_t aCol = (uint32_t)((lane >> 4) << 3);
    uint32_t aOff = (aRow*TSTRIDE + aCol) * 2;
    uint32_t bRow = (uint32_t)(warp_n*64 + (lane & 7) + ((lane >> 4) << 3));
    uint32_t bCol = (uint32_t)(((lane >> 3) & 1) << 3);
    uint32_t bOff = (bRow*TSTRIDE + bCol) * 2;

    // issue loads for K-chunk kc into stage s
    auto issue = [&](int kc, int s) {
        uint32_t abase = sbase + s*STAGE_BYTES;
        uint32_t bbase = abase + TILE_BYTES;
        const __half* sa = srcA + kc*64;
        const __half* sb = srcB + kc*64;
        #pragma unroll
        for (int it = 0; it < 4; it++) {
            int row = lrow + it*32;
            uint32_t doff = (uint32_t)(row*TSTRIDE + lcol8) * 2;
            cp16(abase + doff, sa + (size_t)row*Cc + lcol8);
            cp16(bbase + doff, sb + (size_t)row*Cc + lcol8);
        }
        CP_COMMIT();
    };

    issue(0, 0);
    for (int kc = 0; kc < 4; kc++) {
        if (kc + 1 < 4) { issue(kc + 1, (kc + 1) & 1); CP_WAIT(1); }
        else           { CP_WAIT(0); }
        __syncthreads();
        uint32_t abase = sbase + (kc & 1)*STAGE_BYTES;
        uint32_t bbase = abase + TILE_BYTES;
        #pragma unroll
        for (int ks = 0; ks < 4; ks++) {
            uint32_t kByte = (uint32_t)(ks*16*2);
            uint32_t af[2][4];
            #pragma unroll
            for (int mt = 0; mt < 2; mt++)
                ldsm4(af[mt], abase + aOff + (uint32_t)(mt*16*TSTRIDE*2) + kByte);
            uint32_t bf[4][4];
            #pragma unroll
            for (int ng = 0; ng < 4; ng++)
                ldsm4(bf[ng], bbase + bOff + (uint32_t)(ng*16*TSTRIDE*2) + kByte);
            #pragma unroll
            for (int mt = 0; mt < 2; mt++)
                #pragma unroll
                for (int ng = 0; ng < 4; ng++)
                    #pragma unroll
                    for (int jj = 0; jj < 2; jj++)
                        mma16816h(acc[mt][ng*2+jj], af[mt], bf[ng][2*jj], bf[ng][2*jj+1]);
        }
        __syncthreads();
    }

    float* stage = (float*)dyn;                 // 128*130*4 = 66560 <= SMEM_DYN
    #pragma unroll
    for (int mt = 0; mt < 2; mt++) {
        int gr = warp_m*32 + mt*16 + (lane >> 2);
        #pragma unroll
        for (int nt = 0; nt < 8; nt++) {
            int tok = warp_n*64 + nt*8 + (lane & 3)*2;
            *(float2*)&stage[(size_t)gr*130 + tok]     = make_float2(acc[mt][nt][0], acc[mt][nt][1]);
            *(float2*)&stage[(size_t)(gr+8)*130 + tok] = make_float2(acc[mt][nt][2], acc[mt][nt][3]);
        }
    }
    __syncthreads();
    #pragma unroll 4
    for (int j = 0; j < 64; j++) {
        int f  = j*256 + t;
        int gl = f >> 7;
        int tl = f & 127;
        int g  = g0 + gl;
        int token = b0 + tl;
        int n   = token / 49;
        int pos = token - n*49;
        out[(size_t)n*(Cc*49) + (size_t)g*49 + pos] = stage[(size_t)gl*130 + tl]*MINV + g_bias[g];
    }
}

extern "C" void kernel_launch(void* const* d_in, const int* in_sizes, int n_in,
                              void* d_out, int out_size) {
    const float* features   = (const float*)d_in[0];
    const float* rois       = (const float*)d_in[1];
    const float* offs       = (const float*)d_in[2];
    const float* queries    = (const float*)d_in[3];
    const float* w_proj     = (const float*)d_in[4];
    const float* b_proj     = (const float*)d_in[5];
    const float* in_proj_w  = (const float*)d_in[6];
    const float* in_proj_b  = (const float*)d_in[7];
    const float* out_proj_w = (const float*)d_in[8];
    const float* out_proj_b = (const float*)d_in[9];
    float* out = (float*)d_out;

    static cudaStream_t s1 = nullptr, s2 = nullptr;
    static cudaEvent_t  e_fork = nullptr, e_qk = nullptr, e_M = nullptr,
                        e_A = nullptr, e_B = nullptr;
    if (!s1) {
        cudaStreamCreateWithFlags(&s1, cudaStreamNonBlocking);
        cudaStreamCreateWithFlags(&s2, cudaStreamNonBlocking);
        cudaEventCreateWithFlags(&e_fork, cudaEventDisableTiming);
        cudaEventCreateWithFlags(&e_qk,   cudaEventDisableTiming);
        cudaEventCreateWithFlags(&e_M,    cudaEventDisableTiming);
        cudaEventCreateWithFlags(&e_A,    cudaEventDisableTiming);
        cudaEventCreateWithFlags(&e_B,    cudaEventDisableTiming);
    }

    cudaFuncSetAttribute(gemm_mma, cudaFuncAttributeMaxDynamicSharedMemorySize, SMEM_DYN);

    cudaEventRecord(e_fork, 0);
    // k-path (needed by sample)
    cudaStreamWaitEvent(s1, e_fork, 0);
    pre_k<<<81, 256, 0, s1>>>(in_proj_w, in_proj_b, w_proj, queries);
    pre_qk<<<7, 256, 0, s1>>>();
    cudaEventRecord(e_qk, s1);
    // m-path (needed by gemm)
    cudaStreamWaitEvent(s2, e_fork, 0);
    pre_m1<<<33, 256, 0, s2>>>(in_proj_w, in_proj_b, out_proj_w, b_proj);
    pre_m2<<<33, 256, 0, s2>>>(w_proj, out_proj_w, out_proj_b);
    cudaEventRecord(e_M, s2);

    transpose_feat<<<dim3(Hf*Wf/32, Cc/32, Bn), dim3(8, 32)>>>(features);

    // half A on main (after transpose in-order, plus Qk)
    cudaStreamWaitEvent(0, e_qk, 0);
    sample_attn<<<NTOK/16, 256>>>(rois, offs, 0);
    cudaEventRecord(e_A, 0);

    // half B on s1, overlapping gemm A (e_A implies transpose done)
    cudaStreamWaitEvent(s1, e_A, 0);
    sample_attn<<<NTOK/16, 256, 0, s1>>>(rois, offs, NTOK/2);
    cudaEventRecord(e_B, s1);

    cudaStreamWaitEvent(0, e_M, 0);
    gemm_mma<<<dim3(NTOK/256, Cc/128), 256, SMEM_DYN>>>(out, 0);

    cudaStreamWaitEvent(0, e_B, 0);
    gemm_mma<<<dim3(NTOK/256, Cc/128), 256, SMEM_DYN>>>(out, NTOK/256);
}

// round 14
// speedup vs baseline: 2.9312x; 1.0177x over previous
#include <cuda_runtime.h>
#include <cuda_fp16.h>
#include <cstdint>

#define Cc 256
#define Hf 128
#define Wf 128
#define Bn 4
#define Nroi 512
#define Pp 4
#define NTOK (Nroi*49)              // 25088
#define FSZ (Bn*Cc*Hf*Wf)           // 16777216
#define MSCALE 512.0f
#define MINV  (1.0f/512.0f)

// ---- scratch (device globals: allocation-free) ----
__device__ float g_ft[FSZ];                  // features transposed to [b][h*W+w][c]
__device__ __half g_sh[NTOK*Cc];             // smix (fp16)
__device__ __half g_Mh[Cc*Cc];               // 512*M (fp16)
__device__ float g_Mk[Cc*Cc];
__device__ float g_T [Cc*Cc];                // Wo@Wv
__device__ float g_Qb[49*Cc];
__device__ float g_Qk[49*Cc];
__device__ float g_bias[Cc];

__device__ __forceinline__ uint32_t smem_u32(const void* p) {
    uint32_t a;
    asm("{ .reg .u64 t; cvta.to.shared.u64 t, %1; cvt.u32.u64 %0, t; }" : "=r"(a) : "l"(p));
    return a;
}
__device__ __forceinline__ void ldsm4(uint32_t* r, uint32_t addr) {
    asm volatile("ldmatrix.sync.aligned.m8n8.x4.shared.b16 {%0,%1,%2,%3}, [%4];"
        : "=r"(r[0]), "=r"(r[1]), "=r"(r[2]), "=r"(r[3]) : "r"(addr));
}
__device__ __forceinline__ void mma16816h(float* c, const uint32_t* a, uint32_t b0, uint32_t b1) {
    asm volatile("mma.sync.aligned.m16n8k16.row.col.f32.f16.f16.f32 "
        "{%0,%1,%2,%3}, {%4,%5,%6,%7}, {%8,%9}, {%0,%1,%2,%3};"
        : "+f"(c[0]), "+f"(c[1]), "+f"(c[2]), "+f"(c[3])
        : "r"(a[0]), "r"(a[1]), "r"(a[2]), "r"(a[3]), "r"(b0), "r"(b1));
}
__device__ __forceinline__ void cp16(uint32_t dst, const void* src) {
    asm volatile("cp.async.cg.shared.global [%0], [%1], 16;" :: "r"(dst), "l"(src) : "memory");
}
#define CP_COMMIT()  asm volatile("cp.async.commit_group;" ::: "memory")
#define CP_WAIT(n)   asm volatile("cp.async.wait_group %0;" :: "n"(n) : "memory")

#define TSTRIDE 72                          // fp16 per row (64 + 8 pad)
#define TILE_BYTES (128*TSTRIDE*2)          // 18432 (one 128x64 fp16 tile)
#define STAGE_BYTES (2*TILE_BYTES)          // A+B per pipeline stage = 36864
#define SMEM_DYN (2*STAGE_BYTES)            // 73728 (>= 66560 epilogue stage)

// ================= pre-chain: latency-optimized small GEMM =================
// C[r0:r0+8][c0:c0+64] = A[rows x 256] @ B[256 x 256]; 256 thr = 64 cols x 4 k-segs.
// mode 0: outf = v ; mode 1: g_Mh = fp16(v*512) ; mode 2: outf = v*(1/16)
__global__ void __launch_bounds__(256) gemm_pre(const float* __restrict__ A,
                                                const float* __restrict__ B,
                                                float* __restrict__ outf,
                                                int arows, int mode) {
    __shared__ float As[8*Cc];
    __shared__ float red[4][8][64];
    int r0 = blockIdx.x * 8;
    int c0 = blockIdx.y * 64;
    int rows = min(8, arows - r0);
    int t = threadIdx.x;
    int cl = t & 63, kg = t >> 6;

    for (int u = t; u < rows*Cc; u += 256) As[u] = A[(size_t)r0*Cc + u];
    if (rows < 8) for (int u = t + rows*Cc; u < 8*Cc; u += 256) As[u] = 0.f;
    __syncthreads();

    float acc[8] = {0,0,0,0,0,0,0,0};
    const float* Bp = B + c0 + cl;
    int k0 = kg*64;
    #pragma unroll 8
    for (int k = k0; k < k0 + 64; k++) {
        float b = Bp[(size_t)k*Cc];
        #pragma unroll
        for (int r = 0; r < 8; r++) acc[r] += As[r*Cc + k] * b;
    }
    #pragma unroll
    for (int r = 0; r < 8; r++) red[kg][r][cl] = acc[r];
    __syncthreads();
    if (kg == 0) {
        #pragma unroll
        for (int r = 0; r < 8; r++) {
            if (r >= rows) break;
            float v = (red[0][r][cl] + red[1][r][cl]) + (red[2][r][cl] + red[3][r][cl]);
            size_t o = (size_t)(r0 + r)*Cc + c0 + cl;
            if (mode == 0)      outf[o] = v;
            else if (mode == 1) g_Mh[o] = __float2half_rn(v * MSCALE);
            else                outf[o] = v * 0.0625f;
        }
    }
}

// Qb rows: one block per pos (coalesced Wq row reads per thread, MLP 8)
__global__ void __launch_bounds__(256) pre_qb(const float* __restrict__ in_proj_w,
                                              const float* __restrict__ in_proj_b,
                                              const float* __restrict__ queries) {
    __shared__ float qs[Cc];
    int pos = blockIdx.x, j = threadIdx.x;
    qs[j] = queries[pos*Cc + j];
    __syncthreads();
    const float4* Wr = (const float4*)(in_proj_w + (size_t)j*Cc);
    float a0=0.f,a1=0.f,a2=0.f,a3=0.f;
    #pragma unroll 8
    for (int k4 = 0; k4 < Cc/4; k4++) {
        float4 w = Wr[k4];
        a0 += w.x*qs[k4*4+0]; a1 += w.y*qs[k4*4+1];
        a2 += w.z*qs[k4*4+2]; a3 += w.w*qs[k4*4+3];
    }
    g_Qb[pos*Cc+j] = (a0+a1)+(a2+a3) + in_proj_b[j];
}

// cv then bias in one block (dependent phases through smem)
__global__ void __launch_bounds__(256) pre_cvbias(const float* __restrict__ in_proj_w,
                                                  const float* __restrict__ in_proj_b,
                                                  const float* __restrict__ out_proj_w,
                                                  const float* __restrict__ out_proj_b,
                                                  const float* __restrict__ b_proj) {
    __shared__ float bs[Cc], cs[Cc];
    int j = threadIdx.x;
    bs[j] = b_proj[j];
    __syncthreads();
    {
        const float4* Wr = (const float4*)(in_proj_w + 2*Cc*Cc + (size_t)j*Cc);
        float a0=0.f,a1=0.f,a2=0.f,a3=0.f;
        #pragma unroll 8
        for (int k4 = 0; k4 < Cc/4; k4++) {
            float4 w = Wr[k4];
            a0 += w.x*bs[k4*4+0]; a1 += w.y*bs[k4*4+1];
            a2 += w.z*bs[k4*4+2]; a3 += w.w*bs[k4*4+3];
        }
        cs[j] = (a0+a1)+(a2+a3) + in_proj_b[2*Cc + j];
    }
    __syncthreads();
    {
        const float4* Wr = (const float4*)(out_proj_w + (size_t)j*Cc);
        float a0=0.f,a1=0.f,a2=0.f,a3=0.f;
        #pragma unroll 8
        for (int k4 = 0; k4 < Cc/4; k4++) {
            float4 w = Wr[k4];
            a0 += w.x*cs[k4*4+0]; a1 += w.y*cs[k4*4+1];
            a2 += w.z*cs[k4*4+2]; a3 += w.w*cs[k4*4+3];
        }
        g_bias[j] = (a0+a1)+(a2+a3) + out_proj_b[j];
    }
}

// ---------- features (B,C,H,W) -> (B,H*W,C), float4 both directions ----------
__global__ void transpose_feat(const float* __restrict__ feat) {
    __shared__ float tile[32][33];
    int b   = blockIdx.z;
    int hw0 = blockIdx.x * 32;
    int c0  = blockIdx.y * 32;
    int tx = threadIdx.x;    // 0..7
    int ty = threadIdx.y;    // 0..31
    const float* src = feat + (size_t)b*Cc*Hf*Wf;
    float*       dst = g_ft + (size_t)b*Hf*Wf*Cc;
    float4 v = *(const float4*)(src + (size_t)(c0+ty)*(Hf*Wf) + hw0 + tx*4);
    tile[ty][tx*4+0] = v.x; tile[ty][tx*4+1] = v.y;
    tile[ty][tx*4+2] = v.z; tile[ty][tx*4+3] = v.w;
    __syncthreads();
    float4 o;
    o.x = tile[tx*4+0][ty]; o.y = tile[tx*4+1][ty];
    o.z = tile[tx*4+2][ty]; o.w = tile[tx*4+3][ty];
    *(float4*)(dst + (size_t)(hw0+ty)*Cc + c0 + tx*4) = o;
}

// ---------- fused sampling + scores + softmax + mix: warp-per-token ----------
__global__ void __launch_bounds__(256) sample_attn(const float* __restrict__ rois,
                                                   const float* __restrict__ offs,
                                                   int tok0) {
    int lane = threadIdx.x & 31;
    int wid  = threadIdx.x >> 5;
    int b = tok0 + blockIdx.x*8 + wid;    // token
    int c8 = lane * 8;
    int n = b / 49, pos = b - n*49;
    int oi = pos / 7, oj = pos - oi*7;

    const float* roi = rois + n*5;
    int   bidx = (int)roi[0];
    float x1 = roi[1]*0.0625f - 0.5f;
    float y1 = roi[2]*0.0625f - 0.5f;
    float rw = roi[3]*0.0625f - 0.5f - x1;
    float rh = roi[4]*0.0625f - 0.5f - y1;
    float bw = rw * (1.0f/7.0f);
    float bh = rh * (1.0f/7.0f);
    const float* fb = g_ft + (size_t)bidx*(Hf*Wf*Cc);

    float4 qk0 = *(const float4*)(g_Qk + pos*Cc + c8);
    float4 qk1 = *(const float4*)(g_Qk + pos*Cc + c8 + 4);

    int   y0a[Pp], x0a[Pp];
    float lya[Pp], lxa[Pp];
    bool  vld[Pp];
    #pragma unroll
    for (int p = 0; p < Pp; p++) {
        float odw = offs[((p*7+oi)*7+oj)*2 + 0];
        float odh = offs[((p*7+oi)*7+oj)*2 + 1];
        float x = x1 + (oj + 0.5f)*bw + 0.1f*rw*odw;
        float y = y1 + (oi + 0.5f)*bh + 0.1f*rh*odh;
        vld[p] = (y > -1.0f) && (y < (float)Hf) && (x > -1.0f) && (x < (float)Wf);
        float yc = fminf(fmaxf(y, 0.f), (float)(Hf-1));
        float xc = fminf(fmaxf(x, 0.f), (float)(Wf-1));
        y0a[p] = (int)floorf(yc); x0a[p] = (int)floorf(xc);
        lya[p] = yc - (float)y0a[p];
        lxa[p] = xc - (float)x0a[p];
    }
    bool same = (y0a[1]==y0a[0]) & (y0a[2]==y0a[0]) & (y0a[3]==y0a[0])
              & (x0a[1]==x0a[0]) & (x0a[2]==x0a[0]) & (x0a[3]==x0a[0]);

    float mix[8];
    if (same) {
        int y0 = y0a[0], x0 = x0a[0];
        int y1i = min(y0+1, Hf-1), x1i = min(x0+1, Wf-1);
        const float* p00 = fb + ((size_t)(y0 *Wf + x0 ))*Cc + c8;
        const float* p01 = fb + ((size_t)(y0 *Wf + x1i))*Cc + c8;
        const float* p10 = fb + ((size_t)(y1i*Wf + x0 ))*Cc + c8;
        const float* p11 = fb + ((size_t)(y1i*Wf + x1i))*Cc + c8;
        float4 ca[4], cb[4];
        ca[0]=*(const float4*)(p00); cb[0]=*(const float4*)(p00+4);
        ca[1]=*(const float4*)(p01); cb[1]=*(const float4*)(p01+4);
        ca[2]=*(const float4*)(p10); cb[2]=*(const float4*)(p10+4);
        ca[3]=*(const float4*)(p11); cb[3]=*(const float4*)(p11+4);
        float qd[4];
        #pragma unroll
        for (int c = 0; c < 4; c++)
            qd[c] = qk0.x*ca[c].x + qk0.y*ca[c].y + qk0.z*ca[c].z + qk0.w*ca[c].w
                  + qk1.x*cb[c].x + qk1.y*cb[c].y + qk1.z*cb[c].z + qk1.w*cb[c].w;
        #pragma unroll
        for (int off = 16; off; off >>= 1) {
            #pragma unroll
            for (int c = 0; c < 4; c++) qd[c] += __shfl_xor_sync(0xffffffffu, qd[c], off);
        }
        float sc[Pp];
        float w[Pp][4];
        #pragma unroll
        for (int p = 0; p < Pp; p++) {
            float ly = lya[p], lx = lxa[p];
            float hy = 1.f-ly, hx = 1.f-lx;
            w[p][0]=hy*hx; w[p][1]=hy*lx; w[p][2]=ly*hx; w[p][3]=ly*lx;
            float s = w[p][0]*qd[0] + w[p][1]*qd[1] + w[p][2]*qd[2] + w[p][3]*qd[3];
            sc[p] = vld[p] ? s : 0.f;
        }
        float m = fmaxf(fmaxf(sc[0], sc[1]), fmaxf(sc[2], sc[3]));
        float e[Pp], sum = 0.f;
        #pragma unroll
        for (int p = 0; p < Pp; p++) { e[p] = __expf(sc[p]-m); sum += e[p]; }
        float inv = 1.f/sum;
        float W[4] = {0,0,0,0};
        #pragma unroll
        for (int p = 0; p < Pp; p++) {
            float a = vld[p] ? e[p]*inv : 0.f;
            W[0] += a*w[p][0]; W[1] += a*w[p][1]; W[2] += a*w[p][2]; W[3] += a*w[p][3];
        }
        #pragma unroll
        for (int q = 0; q < 4; q++) {
            mix[q]   = W[0]*((&ca[0].x)[q]) + W[1]*((&ca[1].x)[q])
                     + W[2]*((&ca[2].x)[q]) + W[3]*((&ca[3].x)[q]);
            mix[q+4] = W[0]*((&cb[0].x)[q]) + W[1]*((&cb[1].x)[q])
                     + W[2]*((&cb[2].x)[q]) + W[3]*((&cb[3].x)[q]);
        }
    } else {
        float4 va[Pp], vb[Pp];
        float sc[Pp];
        #pragma unroll
        for (int p = 0; p < Pp; p++) {
            int y0 = y0a[p], x0 = x0a[p];
            int y1i = min(y0+1, Hf-1), x1i = min(x0+1, Wf-1);
            float ly = lya[p], lx = lxa[p];
            float hy = 1.f - ly, hx = 1.f - lx;
            const float* p00 = fb + ((size_t)(y0 *Wf + x0 ))*Cc + c8;
            const float* p01 = fb + ((size_t)(y0 *Wf + x1i))*Cc + c8;
            const float* p10 = fb + ((size_t)(y1i*Wf + x0 ))*Cc + c8;
            const float* p11 = fb + ((size_t)(y1i*Wf + x1i))*Cc + c8;
            float4 a00 = *(const float4*)(p00),     b00 = *(const float4*)(p00 + 4);
            float4 a01 = *(const float4*)(p01),     b01 = *(const float4*)(p01 + 4);
            float4 a10 = *(const float4*)(p10),     b10 = *(const float4*)(p10 + 4);
            float4 a11 = *(const float4*)(p11),     b11 = *(const float4*)(p11 + 4);
            float w00 = hy*hx, w01 = hy*lx, w10 = ly*hx, w11 = ly*lx;
            float4 u, v;
            u.x = w00*a00.x + w01*a01.x + w10*a10.x + w11*a11.x;
            u.y = w00*a00.y + w01*a01.y + w10*a10.y + w11*a11.y;
            u.z = w00*a00.z + w01*a01.z + w10*a10.z + w11*a11.z;
            u.w = w00*a00.w + w01*a01.w + w10*a10.w + w11*a11.w;
            v.x = w00*b00.x + w01*b01.x + w10*b10.x + w11*b11.x;
            v.y = w00*b00.y + w01*b01.y + w10*b10.y + w11*b11.y;
            v.z = w00*b00.z + w01*b01.z + w10*b10.z + w11*b11.z;
            v.w = w00*b00.w + w01*b01.w + w10*b10.w + w11*b11.w;
            if (!vld[p]) {
                u = make_float4(0.f,0.f,0.f,0.f);
                v = make_float4(0.f,0.f,0.f,0.f);
            }
            va[p] = u; vb[p] = v;
            sc[p] = qk0.x*u.x + qk0.y*u.y + qk0.z*u.z + qk0.w*u.w
                  + qk1.x*v.x + qk1.y*v.y + qk1.z*v.z + qk1.w*v.w;
        }
        #pragma unroll
        for (int off = 16; off; off >>= 1) {
            #pragma unroll
            for (int p = 0; p < Pp; p++) sc[p] += __shfl_xor_sync(0xffffffffu, sc[p], off);
        }
        float m = fmaxf(fmaxf(sc[0], sc[1]), fmaxf(sc[2], sc[3]));
        float e[Pp], sum = 0.f;
        #pragma unroll
        for (int p = 0; p < Pp; p++) { e[p] = __expf(sc[p]-m); sum += e[p]; }
        float inv = 1.f/sum;
        #pragma unroll
        for (int q = 0; q < 8; q++) mix[q] = 0.f;
        #pragma unroll
        for (int p = 0; p < Pp; p++) {
            float w = e[p]*inv;
            mix[0] += w*va[p].x; mix[1] += w*va[p].y; mix[2] += w*va[p].z; mix[3] += w*va[p].w;
            mix[4] += w*vb[p].x; mix[5] += w*vb[p].y; mix[6] += w*vb[p].z; mix[7] += w*vb[p].w;
        }
    }
    __half hb[8];
    #pragma unroll
    for (int q = 0; q < 8; q++) hb[q] = __float2half_rn(mix[q]);
    *(uint4*)(g_sh + (size_t)b*Cc + c8) = *(const uint4*)hb;
}

// ---------- mma.sync GEMM (fp16 1-term, cp.async double-buffered) ----------
__global__ void __launch_bounds__(256, 2) gemm_mma(float* __restrict__ out, int tile0) {
    extern __shared__ char dyn[];
    uint32_t sbase = smem_u32(dyn);

    int t = threadIdx.x;
    int wid = t >> 5, lane = t & 31;
    int warp_m = wid & 3;        // g quadrant (32 rows)
    int warp_n = wid >> 2;       // token half (64 cols)
    int b0 = (tile0 + blockIdx.x) * 128;
    int g0 = blockIdx.y * 128;

    const __half* srcA = g_Mh + (size_t)g0*Cc;
    const __half* srcB = g_sh + (size_t)b0*Cc;

    int lrow  = t >> 3;              // 0..31 base row
    int lcol8 = (t & 7) << 3;        // fp16 col 0..56 step 8

    float acc[2][8][4];
    #pragma unroll
    for (int mt = 0; mt < 2; mt++)
        #pragma unroll
        for (int nt = 0; nt < 8; nt++)
            #pragma unroll
            for (int r = 0; r < 4; r++) acc[mt][nt][r] = 0.f;

    uint32_t aRow = (uint32_t)(warp_m*32 + (lane & 15));
    uint32_t aCol = (uint32_t)((lane >> 4) << 3);
    uint32_t aOff = (aRow*TSTRIDE + aCol) * 2;
    uint32_t bRow = (uint32_t)(warp_n*64 + (lane & 7) + ((lane >> 4) << 3));
    uint32_t bCol = (uint32_t)(((lane >> 3) & 1) << 3);
    uint32_t bOff = (bRow*TSTRIDE + bCol) * 2;

    auto issue = [&](int kc, int s) {
        uint32_t abase = sbase + s*STAGE_BYTES;
        uint32_t bbase = abase + TILE_BYTES;
        const __half* sa = srcA + kc*64;
        const __half* sb = srcB + kc*64;
        #pragma unroll
        for (int it = 0; it < 4; it++) {
            int row = lrow + it*32;
            uint32_t doff = (uint32_t)(row*TSTRIDE + lcol8) * 2;
            cp16(abase + doff, sa + (size_t)row*Cc + lcol8);
            cp16(bbase + doff, sb + (size_t)row*Cc + lcol8);
        }
        CP_COMMIT();
    };

    issue(0, 0);
    for (int kc = 0; kc < 4; kc++) {
        if (kc + 1 < 4) { issue(kc + 1, (kc + 1) & 1); CP_WAIT(1); }
        else           { CP_WAIT(0); }
        __syncthreads();
        uint32_t abase = sbase + (kc & 1)*STAGE_BYTES;
        uint32_t bbase = abase + TILE_BYTES;
        #pragma unroll
        for (int ks = 0; ks < 4; ks++) {
            uint32_t kByte = (uint32_t)(ks*16*2);
            uint32_t af[2][4];
            #pragma unroll
            for (int mt = 0; mt < 2; mt++)
                ldsm4(af[mt], abase + aOff + (uint32_t)(mt*16*TSTRIDE*2) + kByte);
            uint32_t bf[4][4];
            #pragma unroll
            for (int ng = 0; ng < 4; ng++)
                ldsm4(bf[ng], bbase + bOff + (uint32_t)(ng*16*TSTRIDE*2) + kByte);
            #pragma unroll
            for (int mt = 0; mt < 2; mt++)
                #pragma unroll
                for (int ng = 0; ng < 4; ng++)
                    #pragma unroll
                    for (int jj = 0; jj < 2; jj++)
                        mma16816h(acc[mt][ng*2+jj], af[mt], bf[ng][2*jj], bf[ng][2*jj+1]);
        }
        __syncthreads();
    }

    float* stage = (float*)dyn;
    #pragma unroll
    for (int mt = 0; mt < 2; mt++) {
        int gr = warp_m*32 + mt*16 + (lane >> 2);
        #pragma unroll
        for (int nt = 0; nt < 8; nt++) {
            int tok = warp_n*64 + nt*8 + (lane & 3)*2;
            *(float2*)&stage[(size_t)gr*130 + tok]     = make_float2(acc[mt][nt][0], acc[mt][nt][1]);
            *(float2*)&stage[(size_t)(gr+8)*130 + tok] = make_float2(acc[mt][nt][2], acc[mt][nt][3]);
        }
    }
    __syncthreads();
    #pragma unroll 4
    for (int j = 0; j < 64; j++) {
        int f  = j*256 + t;
        int gl = f >> 7;
        int tl = f & 127;
        int g  = g0 + gl;
        int token = b0 + tl;
        int n   = token / 49;
        int pos = token - n*49;
        out[(size_t)n*(Cc*49) + (size_t)g*49 + pos] = stage[(size_t)gl*130 + tl]*MINV + g_bias[g];
    }
}

extern "C" void kernel_launch(void* const* d_in, const int* in_sizes, int n_in,
                              void* d_out, int out_size) {
    const float* features   = (const float*)d_in[0];
    const float* rois       = (const float*)d_in[1];
    const float* offs       = (const float*)d_in[2];
    const float* queries    = (const float*)d_in[3];
    const float* w_proj     = (const float*)d_in[4];
    const float* b_proj     = (const float*)d_in[5];
    const float* in_proj_w  = (const float*)d_in[6];
    const float* in_proj_b  = (const float*)d_in[7];
    const float* out_proj_w = (const float*)d_in[8];
    const float* out_proj_b = (const float*)d_in[9];
    float* out = (float*)d_out;

    static cudaStream_t s1 = nullptr, s2 = nullptr;
    static cudaEvent_t  e_fork = nullptr, e_qk = nullptr, e_M = nullptr,
                        e_A = nullptr, e_B = nullptr;
    if (!s1) {
        cudaStreamCreateWithFlags(&s1, cudaStreamNonBlocking);
        cudaStreamCreateWithFlags(&s2, cudaStreamNonBlocking);
        cudaEventCreateWithFlags(&e_fork, cudaEventDisableTiming);
        cudaEventCreateWithFlags(&e_qk,   cudaEventDisableTiming);
        cudaEventCreateWithFlags(&e_M,    cudaEventDisableTiming);
        cudaEventCreateWithFlags(&e_A,    cudaEventDisableTiming);
        cudaEventCreateWithFlags(&e_B,    cudaEventDisableTiming);
    }

    float* d_T;  cudaGetSymbolAddress((void**)&d_T,  g_T);
    float* d_Mk; cudaGetSymbolAddress((void**)&d_Mk, g_Mk);
    float* d_Qb; cudaGetSymbolAddress((void**)&d_Qb, g_Qb);
    float* d_Qk; cudaGetSymbolAddress((void**)&d_Qk, g_Qk);

    cudaFuncSetAttribute(gemm_mma, cudaFuncAttributeMaxDynamicSharedMemorySize, SMEM_DYN);

    cudaEventRecord(e_fork, 0);
    // k-path (needed by sample): Mk -> (Qb) -> Qk
    cudaStreamWaitEvent(s1, e_fork, 0);
    gemm_pre<<<dim3(32,4), 256, 0, s1>>>(in_proj_w + Cc*Cc, w_proj, d_Mk, Cc, 0);
    pre_qb<<<49, 256, 0, s1>>>(in_proj_w, in_proj_b, queries);
    gemm_pre<<<dim3(7,4), 256, 0, s1>>>(d_Qb, d_Mk, d_Qk, 49, 2);
    cudaEventRecord(e_qk, s1);
    // m-path (needed by gemm): T -> M ; cv+bias
    cudaStreamWaitEvent(s2, e_fork, 0);
    gemm_pre<<<dim3(32,4), 256, 0, s2>>>(out_proj_w, in_proj_w + 2*Cc*Cc, d_T, Cc, 0);
    gemm_pre<<<dim3(32,4), 256, 0, s2>>>(d_T, w_proj, nullptr, Cc, 1);
    pre_cvbias<<<1, 256, 0, s2>>>(in_proj_w, in_proj_b, out_proj_w, out_proj_b, b_proj);
    cudaEventRecord(e_M, s2);

    transpose_feat<<<dim3(Hf*Wf/32, Cc/32, Bn), dim3(8, 32)>>>(features);

    cudaStreamWaitEvent(0, e_qk, 0);
    sample_attn<<<NTOK/16, 256>>>(rois, offs, 0);
    cudaEventRecord(e_A, 0);

    cudaStreamWaitEvent(s1, e_A, 0);
    sample_attn<<<NTOK/16, 256, 0, s1>>>(rois, offs, NTOK/2);
    cudaEventRecord(e_B, s1);

    cudaStreamWaitEvent(0, e_M, 0);
    gemm_mma<<<dim3(NTOK/256, Cc/128), 256, SMEM_DYN>>>(out, 0);

    cudaStreamWaitEvent(0, e_B, 0);
    gemm_mma<<<dim3(NTOK/256, Cc/128), 256, SMEM_DYN>>>(out, NTOK/256);
}

// round 15
// speedup vs baseline: 3.1159x; 1.0630x over previous
#include <cuda_runtime.h>
#include <cuda_fp16.h>
#include <cstdint>

#define Cc 256
#define Hf 128
#define Wf 128
#define Bn 4
#define Nroi 512
#define Pp 4
#define NTOK (Nroi*49)              // 25088
#define FSZ (Bn*Cc*Hf*Wf)           // 16777216
#define MSCALE 512.0f
#define MINV  (1.0f/512.0f)

// ---- scratch (device globals: allocation-free) ----
__device__ float g_ft[FSZ];                  // features transposed to [b][h*W+w][c]
__device__ __half g_sh[NTOK*Cc];             // smix (fp16)
__device__ __half g_Mh[Cc*Cc];               // 512*M (fp16)
__device__ float g_Mk[Cc*Cc];
__device__ float g_T [Cc*Cc];                // Wo@Wv
__device__ float g_Qb[49*Cc];
__device__ float g_Qk[49*Cc];
__device__ float g_bias[Cc];

__device__ __forceinline__ uint32_t smem_u32(const void* p) {
    uint32_t a;
    asm("{ .reg .u64 t; cvta.to.shared.u64 t, %1; cvt.u32.u64 %0, t; }" : "=r"(a) : "l"(p));
    return a;
}
__device__ __forceinline__ void ldsm4(uint32_t* r, uint32_t addr) {
    asm volatile("ldmatrix.sync.aligned.m8n8.x4.shared.b16 {%0,%1,%2,%3}, [%4];"
        : "=r"(r[0]), "=r"(r[1]), "=r"(r[2]), "=r"(r[3]) : "r"(addr));
}
__device__ __forceinline__ void mma16816h(float* c, const uint32_t* a, uint32_t b0, uint32_t b1) {
    asm volatile("mma.sync.aligned.m16n8k16.row.col.f32.f16.f16.f32 "
        "{%0,%1,%2,%3}, {%4,%5,%6,%7}, {%8,%9}, {%0,%1,%2,%3};"
        : "+f"(c[0]), "+f"(c[1]), "+f"(c[2]), "+f"(c[3])
        : "r"(a[0]), "r"(a[1]), "r"(a[2]), "r"(a[3]), "r"(b0), "r"(b1));
}
__device__ __forceinline__ void cp16(uint32_t dst, const void* src) {
    asm volatile("cp.async.cg.shared.global [%0], [%1], 16;" :: "r"(dst), "l"(src) : "memory");
}
#define CP_COMMIT()  asm volatile("cp.async.commit_group;" ::: "memory")
#define CP_WAIT(n)   asm volatile("cp.async.wait_group %0;" :: "n"(n) : "memory")

#define TSTRIDE 72                          // fp16 per row (64 + 8 pad)
#define TILE_BYTES (128*TSTRIDE*2)          // 18432 (one 128x64 fp16 tile)
#define STAGE_BYTES (2*TILE_BYTES)          // A+B per pipeline stage = 36864
#define SMEM_DYN (2*STAGE_BYTES)            // 73728 (>= 66560 epilogue stage)

// pre-GEMM smem: As 8x256 floats (2048) + Bs 256x64 floats (16384) = 73728 B
#define PRE_SMEM (18432*4)

// ================= pre-chain: smem-staged small GEMM =================
// C[r0:r0+8][c0:c0+64] = A[rows x 256] @ B[256 x 256]; 256 thr = 64 cols x 4 k-segs.
// mode 0: outf = v ; mode 1: g_Mh = fp16(v*512) ; mode 2: outf = v*(1/16)
__global__ void __launch_bounds__(256) gemm_pre(const float* __restrict__ A,
                                                const float* __restrict__ B,
                                                float* __restrict__ outf,
                                                int arows, int mode) {
    extern __shared__ float sm[];
    float* As = sm;              // [8][256]
    float* Bs = sm + 8*Cc;       // [256][64]
    int r0 = blockIdx.x * 8;
    int c0 = blockIdx.y * 64;
    int rows = min(8, arows - r0);
    int t = threadIdx.x;
    int cl = t & 63, kg = t >> 6;

    // stage A rows (zero-pad)
    for (int u = t; u < rows*Cc; u += 256) As[u] = A[(size_t)r0*Cc + u];
    if (rows < 8) for (int u = t + rows*Cc; u < 8*Cc; u += 256) As[u] = 0.f;
    // stage B panel: 256 rows x 64 cols, fully coalesced float4 (16 per thread)
    {
        int brow = t >> 4;            // 0..15 base row
        int bf4  = (t & 15) << 2;     // col offset 0..60 step 4
        #pragma unroll
        for (int i = 0; i < 16; i++) {
            int k = brow + i*16;
            float4 v = *(const float4*)(B + (size_t)k*Cc + c0 + bf4);
            *(float4*)(Bs + k*64 + bf4) = v;
        }
    }
    __syncthreads();

    float acc[8] = {0,0,0,0,0,0,0,0};
    int k0 = kg*64;
    #pragma unroll 8
    for (int k = k0; k < k0 + 64; k++) {
        float b = Bs[k*64 + cl];
        #pragma unroll
        for (int r = 0; r < 8; r++) acc[r] += As[r*Cc + k] * b;
    }
    __syncthreads();
    // reduce 4 k-segments; reuse As region (2048 floats = 4*8*64)
    float* red = sm;
    #pragma unroll
    for (int r = 0; r < 8; r++) red[(kg*8 + r)*64 + cl] = acc[r];
    __syncthreads();
    if (kg == 0) {
        #pragma unroll
        for (int r = 0; r < 8; r++) {
            if (r >= rows) break;
            float v = (red[(0*8+r)*64+cl] + red[(1*8+r)*64+cl])
                    + (red[(2*8+r)*64+cl] + red[(3*8+r)*64+cl]);
            size_t o = (size_t)(r0 + r)*Cc + c0 + cl;
            if (mode == 0)      outf[o] = v;
            else if (mode == 1) g_Mh[o] = __float2half_rn(v * MSCALE);
            else                outf[o] = v * 0.0625f;
        }
    }
}

// Qb rows: one block per pos (coalesced Wq row reads per thread, MLP 8)
__global__ void __launch_bounds__(256) pre_qb(const float* __restrict__ in_proj_w,
                                              const float* __restrict__ in_proj_b,
                                              const float* __restrict__ queries) {
    __shared__ float qs[Cc];
    int pos = blockIdx.x, j = threadIdx.x;
    qs[j] = queries[pos*Cc + j];
    __syncthreads();
    const float4* Wr = (const float4*)(in_proj_w + (size_t)j*Cc);
    float a0=0.f,a1=0.f,a2=0.f,a3=0.f;
    #pragma unroll 8
    for (int k4 = 0; k4 < Cc/4; k4++) {
        float4 w = Wr[k4];
        a0 += w.x*qs[k4*4+0]; a1 += w.y*qs[k4*4+1];
        a2 += w.z*qs[k4*4+2]; a3 += w.w*qs[k4*4+3];
    }
    g_Qb[pos*Cc+j] = (a0+a1)+(a2+a3) + in_proj_b[j];
}

// cv then bias in one block (dependent phases through smem)
__global__ void __launch_bounds__(256) pre_cvbias(const float* __restrict__ in_proj_w,
                                                  const float* __restrict__ in_proj_b,
                                                  const float* __restrict__ out_proj_w,
                                                  const float* __restrict__ out_proj_b,
                                                  const float* __restrict__ b_proj) {
    __shared__ float bs[Cc], cs[Cc];
    int j = threadIdx.x;
    bs[j] = b_proj[j];
    __syncthreads();
    {
        const float4* Wr = (const float4*)(in_proj_w + 2*Cc*Cc + (size_t)j*Cc);
        float a0=0.f,a1=0.f,a2=0.f,a3=0.f;
        #pragma unroll 8
        for (int k4 = 0; k4 < Cc/4; k4++) {
            float4 w = Wr[k4];
            a0 += w.x*bs[k4*4+0]; a1 += w.y*bs[k4*4+1];
            a2 += w.z*bs[k4*4+2]; a3 += w.w*bs[k4*4+3];
        }
        cs[j] = (a0+a1)+(a2+a3) + in_proj_b[2*Cc + j];
    }
    __syncthreads();
    {
        const float4* Wr = (const float4*)(out_proj_w + (size_t)j*Cc);
        float a0=0.f,a1=0.f,a2=0.f,a3=0.f;
        #pragma unroll 8
        for (int k4 = 0; k4 < Cc/4; k4++) {
            float4 w = Wr[k4];
            a0 += w.x*cs[k4*4+0]; a1 += w.y*cs[k4*4+1];
            a2 += w.z*cs[k4*4+2]; a3 += w.w*cs[k4*4+3];
        }
        g_bias[j] = (a0+a1)+(a2+a3) + out_proj_b[j];
    }
}

// ---------- features (B,C,H,W) -> (B,H*W,C), float4 both directions ----------
__global__ void transpose_feat(const float* __restrict__ feat) {
    __shared__ float tile[32][33];
    int b   = blockIdx.z;
    int hw0 = blockIdx.x * 32;
    int c0  = blockIdx.y * 32;
    int tx = threadIdx.x;    // 0..7
    int ty = threadIdx.y;    // 0..31
    const float* src = feat + (size_t)b*Cc*Hf*Wf;
    float*       dst = g_ft + (size_t)b*Hf*Wf*Cc;
    float4 v = *(const float4*)(src + (size_t)(c0+ty)*(Hf*Wf) + hw0 + tx*4);
    tile[ty][tx*4+0] = v.x; tile[ty][tx*4+1] = v.y;
    tile[ty][tx*4+2] = v.z; tile[ty][tx*4+3] = v.w;
    __syncthreads();
    float4 o;
    o.x = tile[tx*4+0][ty]; o.y = tile[tx*4+1][ty];
    o.z = tile[tx*4+2][ty]; o.w = tile[tx*4+3][ty];
    *(float4*)(dst + (size_t)(hw0+ty)*Cc + c0 + tx*4) = o;
}

// ---------- fused sampling + scores + softmax + mix: warp-per-token ----------
__global__ void __launch_bounds__(256) sample_attn(const float* __restrict__ rois,
                                                   const float* __restrict__ offs,
                                                   int tok0) {
    int lane = threadIdx.x & 31;
    int wid  = threadIdx.x >> 5;
    int b = tok0 + blockIdx.x*8 + wid;    // token
    int c8 = lane * 8;
    int n = b / 49, pos = b - n*49;
    int oi = pos / 7, oj = pos - oi*7;

    const float* roi = rois + n*5;
    int   bidx = (int)roi[0];
    float x1 = roi[1]*0.0625f - 0.5f;
    float y1 = roi[2]*0.0625f - 0.5f;
    float rw = roi[3]*0.0625f - 0.5f - x1;
    float rh = roi[4]*0.0625f - 0.5f - y1;
    float bw = rw * (1.0f/7.0f);
    float bh = rh * (1.0f/7.0f);
    const float* fb = g_ft + (size_t)bidx*(Hf*Wf*Cc);

    float4 qk0 = *(const float4*)(g_Qk + pos*Cc + c8);
    float4 qk1 = *(const float4*)(g_Qk + pos*Cc + c8 + 4);

    int   y0a[Pp], x0a[Pp];
    float lya[Pp], lxa[Pp];
    bool  vld[Pp];
    #pragma unroll
    for (int p = 0; p < Pp; p++) {
        float odw = offs[((p*7+oi)*7+oj)*2 + 0];
        float odh = offs[((p*7+oi)*7+oj)*2 + 1];
        float x = x1 + (oj + 0.5f)*bw + 0.1f*rw*odw;
        float y = y1 + (oi + 0.5f)*bh + 0.1f*rh*odh;
        vld[p] = (y > -1.0f) && (y < (float)Hf) && (x > -1.0f) && (x < (float)Wf);
        float yc = fminf(fmaxf(y, 0.f), (float)(Hf-1));
        float xc = fminf(fmaxf(x, 0.f), (float)(Wf-1));
        y0a[p] = (int)floorf(yc); x0a[p] = (int)floorf(xc);
        lya[p] = yc - (float)y0a[p];
        lxa[p] = xc - (float)x0a[p];
    }
    bool same = (y0a[1]==y0a[0]) & (y0a[2]==y0a[0]) & (y0a[3]==y0a[0])
              & (x0a[1]==x0a[0]) & (x0a[2]==x0a[0]) & (x0a[3]==x0a[0]);

    float mix[8];
    if (same) {
        int y0 = y0a[0], x0 = x0a[0];
        int y1i = min(y0+1, Hf-1), x1i = min(x0+1, Wf-1);
        const float* p00 = fb + ((size_t)(y0 *Wf + x0 ))*Cc + c8;
        const float* p01 = fb + ((size_t)(y0 *Wf + x1i))*Cc + c8;
        const float* p10 = fb + ((size_t)(y1i*Wf + x0 ))*Cc + c8;
        const float* p11 = fb + ((size_t)(y1i*Wf + x1i))*Cc + c8;
        float4 ca[4], cb[4];
        ca[0]=*(const float4*)(p00); cb[0]=*(const float4*)(p00+4);
        ca[1]=*(const float4*)(p01); cb[1]=*(const float4*)(p01+4);
        ca[2]=*(const float4*)(p10); cb[2]=*(const float4*)(p10+4);
        ca[3]=*(const float4*)(p11); cb[3]=*(const float4*)(p11+4);
        float qd[4];
        #pragma unroll
        for (int c = 0; c < 4; c++)
            qd[c] = qk0.x*ca[c].x + qk0.y*ca[c].y + qk0.z*ca[c].z + qk0.w*ca[c].w
                  + qk1.x*cb[c].x + qk1.y*cb[c].y + qk1.z*cb[c].z + qk1.w*cb[c].w;
        #pragma unroll
        for (int off = 16; off; off >>= 1) {
            #pragma unroll
            for (int c = 0; c < 4; c++) qd[c] += __shfl_xor_sync(0xffffffffu, qd[c], off);
        }
        float sc[Pp];
        float w[Pp][4];
        #pragma unroll
        for (int p = 0; p < Pp; p++) {
            float ly = lya[p], lx = lxa[p];
            float hy = 1.f-ly, hx = 1.f-lx;
            w[p][0]=hy*hx; w[p][1]=hy*lx; w[p][2]=ly*hx; w[p][3]=ly*lx;
            float s = w[p][0]*qd[0] + w[p][1]*qd[1] + w[p][2]*qd[2] + w[p][3]*qd[3];
            sc[p] = vld[p] ? s : 0.f;
        }
        float m = fmaxf(fmaxf(sc[0], sc[1]), fmaxf(sc[2], sc[3]));
        float e[Pp], sum = 0.f;
        #pragma unroll
        for (int p = 0; p < Pp; p++) { e[p] = __expf(sc[p]-m); sum += e[p]; }
        float inv = 1.f/sum;
        float W[4] = {0,0,0,0};
        #pragma unroll
        for (int p = 0; p < Pp; p++) {
            float a = vld[p] ? e[p]*inv : 0.f;
            W[0] += a*w[p][0]; W[1] += a*w[p][1]; W[2] += a*w[p][2]; W[3] += a*w[p][3];
        }
        #pragma unroll
        for (int q = 0; q < 4; q++) {
            mix[q]   = W[0]*((&ca[0].x)[q]) + W[1]*((&ca[1].x)[q])
                     + W[2]*((&ca[2].x)[q]) + W[3]*((&ca[3].x)[q]);
            mix[q+4] = W[0]*((&cb[0].x)[q]) + W[1]*((&cb[1].x)[q])
                     + W[2]*((&cb[2].x)[q]) + W[3]*((&cb[3].x)[q]);
        }
    } else {
        float4 va[Pp], vb[Pp];
        float sc[Pp];
        #pragma unroll
        for (int p = 0; p < Pp; p++) {
            int y0 = y0a[p], x0 = x0a[p];
            int y1i = min(y0+1, Hf-1), x1i = min(x0+1, Wf-1);
            float ly = lya[p], lx = lxa[p];
            float hy = 1.f - ly, hx = 1.f - lx;
            const float* p00 = fb + ((size_t)(y0 *Wf + x0 ))*Cc + c8;
            const float* p01 = fb + ((size_t)(y0 *Wf + x1i))*Cc + c8;
            const float* p10 = fb + ((size_t)(y1i*Wf + x0 ))*Cc + c8;
            const float* p11 = fb + ((size_t)(y1i*Wf + x1i))*Cc + c8;
            float4 a00 = *(const float4*)(p00),     b00 = *(const float4*)(p00 + 4);
            float4 a01 = *(const float4*)(p01),     b01 = *(const float4*)(p01 + 4);
            float4 a10 = *(const float4*)(p10),     b10 = *(const float4*)(p10 + 4);
            float4 a11 = *(const float4*)(p11),     b11 = *(const float4*)(p11 + 4);
            float w00 = hy*hx, w01 = hy*lx, w10 = ly*hx, w11 = ly*lx;
            float4 u, v;
            u.x = w00*a00.x + w01*a01.x + w10*a10.x + w11*a11.x;
            u.y = w00*a00.y + w01*a01.y + w10*a10.y + w11*a11.y;
            u.z = w00*a00.z + w01*a01.z + w10*a10.z + w11*a11.z;
            u.w = w00*a00.w + w01*a01.w + w10*a10.w + w11*a11.w;
            v.x = w00*b00.x + w01*b01.x + w10*b10.x + w11*b11.x;
            v.y = w00*b00.y + w01*b01.y + w10*b10.y + w11*b11.y;
            v.z = w00*b00.z + w01*b01.z + w10*b10.z + w11*b11.z;
            v.w = w00*b00.w + w01*b01.w + w10*b10.w + w11*b11.w;
            if (!vld[p]) {
                u = make_float4(0.f,0.f,0.f,0.f);
                v = make_float4(0.f,0.f,0.f,0.f);
            }
            va[p] = u; vb[p] = v;
            sc[p] = qk0.x*u.x + qk0.y*u.y + qk0.z*u.z + qk0.w*u.w
                  + qk1.x*v.x + qk1.y*v.y + qk1.z*v.z + qk1.w*v.w;
        }
        #pragma unroll
        for (int off = 16; off; off >>= 1) {
            #pragma unroll
            for (int p = 0; p < Pp; p++) sc[p] += __shfl_xor_sync(0xffffffffu, sc[p], off);
        }
        float m = fmaxf(fmaxf(sc[0], sc[1]), fmaxf(sc[2], sc[3]));
        float e[Pp], sum = 0.f;
        #pragma unroll
        for (int p = 0; p < Pp; p++) { e[p] = __expf(sc[p]-m); sum += e[p]; }
        float inv = 1.f/sum;
        #pragma unroll
        for (int q = 0; q < 8; q++) mix[q] = 0.f;
        #pragma unroll
        for (int p = 0; p < Pp; p++) {
            float w = e[p]*inv;
            mix[0] += w*va[p].x; mix[1] += w*va[p].y; mix[2] += w*va[p].z; mix[3] += w*va[p].w;
            mix[4] += w*vb[p].x; mix[5] += w*vb[p].y; mix[6] += w*vb[p].z; mix[7] += w*vb[p].w;
        }
    }
    __half hb[8];
    #pragma unroll
    for (int q = 0; q < 8; q++) hb[q] = __float2half_rn(mix[q]);
    *(uint4*)(g_sh + (size_t)b*Cc + c8) = *(const uint4*)hb;
}

// ---------- mma.sync GEMM (fp16 1-term, cp.async double-buffered) ----------
__global__ void __launch_bounds__(256, 2) gemm_mma(float* __restrict__ out, int tile0) {
    extern __shared__ char dyn[];
    uint32_t sbase = smem_u32(dyn);

    int t = threadIdx.x;
    int wid = t >> 5, lane = t & 31;
    int warp_m = wid & 3;        // g quadrant (32 rows)
    int warp_n = wid >> 2;       // token half (64 cols)
    int b0 = (tile0 + blockIdx.x) * 128;
    int g0 = blockIdx.y * 128;

    const __half* srcA = g_Mh + (size_t)g0*Cc;
    const __half* srcB = g_sh + (size_t)b0*Cc;

    int lrow  = t >> 3;              // 0..31 base row
    int lcol8 = (t & 7) << 3;        // fp16 col 0..56 step 8

    float acc[2][8][4];
    #pragma unroll
    for (int mt = 0; mt < 2; mt++)
        #pragma unroll
        for (int nt = 0; nt < 8; nt++)
            #pragma unroll
            for (int r = 0; r < 4; r++) acc[mt][nt][r] = 0.f;

    uint32_t aRow = (uint32_t)(warp_m*32 + (lane & 15));
    uint32_t aCol = (uint32_t)((lane >> 4) << 3);
    uint32_t aOff = (aRow*TSTRIDE + aCol) * 2;
    uint32_t bRow = (uint32_t)(warp_n*64 + (lane & 7) + ((lane >> 4) << 3));
    uint32_t bCol = (uint32_t)(((lane >> 3) & 1) << 3);
    uint32_t bOff = (bRow*TSTRIDE + bCol) * 2;

    auto issue = [&](int kc, int s) {
        uint32_t abase = sbase + s*STAGE_BYTES;
        uint32_t bbase = abase + TILE_BYTES;
        const __half* sa = srcA + kc*64;
        const __half* sb = srcB + kc*64;
        #pragma unroll
        for (int it = 0; it < 4; it++) {
            int row = lrow + it*32;
            uint32_t doff = (uint32_t)(row*TSTRIDE + lcol8) * 2;
            cp16(abase + doff, sa + (size_t)row*Cc + lcol8);
            cp16(bbase + doff, sb + (size_t)row*Cc + lcol8);
        }
        CP_COMMIT();
    };

    issue(0, 0);
    for (int kc = 0; kc < 4; kc++) {
        if (kc + 1 < 4) { issue(kc + 1, (kc + 1) & 1); CP_WAIT(1); }
        else           { CP_WAIT(0); }
        __syncthreads();
        uint32_t abase = sbase + (kc & 1)*STAGE_BYTES;
        uint32_t bbase = abase + TILE_BYTES;
        #pragma unroll
        for (int ks = 0; ks < 4; ks++) {
            uint32_t kByte = (uint32_t)(ks*16*2);
            uint32_t af[2][4];
            #pragma unroll
            for (int mt = 0; mt < 2; mt++)
                ldsm4(af[mt], abase + aOff + (uint32_t)(mt*16*TSTRIDE*2) + kByte);
            uint32_t bf[4][4];
            #pragma unroll
            for (int ng = 0; ng < 4; ng++)
                ldsm4(bf[ng], bbase + bOff + (uint32_t)(ng*16*TSTRIDE*2) + kByte);
            #pragma unroll
            for (int mt = 0; mt < 2; mt++)
                #pragma unroll
                for (int ng = 0; ng < 4; ng++)
                    #pragma unroll
                    for (int jj = 0; jj < 2; jj++)
                        mma16816h(acc[mt][ng*2+jj], af[mt], bf[ng][2*jj], bf[ng][2*jj+1]);
        }
        __syncthreads();
    }

    float* stage = (float*)dyn;
    #pragma unroll
    for (int mt = 0; mt < 2; mt++) {
        int gr = warp_m*32 + mt*16 + (lane >> 2);
        #pragma unroll
        for (int nt = 0; nt < 8; nt++) {
            int tok = warp_n*64 + nt*8 + (lane & 3)*2;
            *(float2*)&stage[(size_t)gr*130 + tok]     = make_float2(acc[mt][nt][0], acc[mt][nt][1]);
            *(float2*)&stage[(size_t)(gr+8)*130 + tok] = make_float2(acc[mt][nt][2], acc[mt][nt][3]);
        }
    }
    __syncthreads();
    #pragma unroll 4
    for (int j = 0; j < 64; j++) {
        int f  = j*256 + t;
        int gl = f >> 7;
        int tl = f & 127;
        int g  = g0 + gl;
        int token = b0 + tl;
        int n   = token / 49;
        int pos = token - n*49;
        out[(size_t)n*(Cc*49) + (size_t)g*49 + pos] = stage[(size_t)gl*130 + tl]*MINV + g_bias[g];
    }
}

extern "C" void kernel_launch(void* const* d_in, const int* in_sizes, int n_in,
                              void* d_out, int out_size) {
    const float* features   = (const float*)d_in[0];
    const float* rois       = (const float*)d_in[1];
    const float* offs       = (const float*)d_in[2];
    const float* queries    = (const float*)d_in[3];
    const float* w_proj     = (const float*)d_in[4];
    const float* b_proj     = (const float*)d_in[5];
    const float* in_proj_w  = (const float*)d_in[6];
    const float* in_proj_b  = (const float*)d_in[7];
    const float* out_proj_w = (const float*)d_in[8];
    const float* out_proj_b = (const float*)d_in[9];
    float* out = (float*)d_out;

    static cudaStream_t s1 = nullptr, s2 = nullptr;
    static cudaEvent_t  e_fork = nullptr, e_qk = nullptr, e_M = nullptr,
                        e_A = nullptr, e_B = nullptr, e_done = nullptr;
    if (!s1) {
        cudaStreamCreateWithFlags(&s1, cudaStreamNonBlocking);
        cudaStreamCreateWithFlags(&s2, cudaStreamNonBlocking);
        cudaEventCreateWithFlags(&e_fork, cudaEventDisableTiming);
        cudaEventCreateWithFlags(&e_qk,   cudaEventDisableTiming);
        cudaEventCreateWithFlags(&e_M,    cudaEventDisableTiming);
        cudaEventCreateWithFlags(&e_A,    cudaEventDisableTiming);
        cudaEventCreateWithFlags(&e_B,    cudaEventDisableTiming);
        cudaEventCreateWithFlags(&e_done, cudaEventDisableTiming);
    }

    float* d_T;  cudaGetSymbolAddress((void**)&d_T,  g_T);
    float* d_Mk; cudaGetSymbolAddress((void**)&d_Mk, g_Mk);
    float* d_Qb; cudaGetSymbolAddress((void**)&d_Qb, g_Qb);
    float* d_Qk; cudaGetSymbolAddress((void**)&d_Qk, g_Qk);

    cudaFuncSetAttribute(gemm_mma, cudaFuncAttributeMaxDynamicSharedMemorySize, SMEM_DYN);
    cudaFuncSetAttribute(gemm_pre, cudaFuncAttributeMaxDynamicSharedMemorySize, PRE_SMEM);

    cudaEventRecord(e_fork, 0);
    // k-path (needed by sample): Mk -> (Qb) -> Qk
    cudaStreamWaitEvent(s1, e_fork, 0);
    gemm_pre<<<dim3(32,4), 256, PRE_SMEM, s1>>>(in_proj_w + Cc*Cc, w_proj, d_Mk, Cc, 0);
    pre_qb<<<49, 256, 0, s1>>>(in_proj_w, in_proj_b, queries);
    gemm_pre<<<dim3(7,4), 256, PRE_SMEM, s1>>>(d_Qb, d_Mk, d_Qk, 49, 2);
    cudaEventRecord(e_qk, s1);
    // m-path (needed by gemm): T -> M ; cv+bias
    cudaStreamWaitEvent(s2, e_fork, 0);
    gemm_pre<<<dim3(32,4), 256, PRE_SMEM, s2>>>(out_proj_w, in_proj_w + 2*Cc*Cc, d_T, Cc, 0);
    gemm_pre<<<dim3(32,4), 256, PRE_SMEM, s2>>>(d_T, w_proj, nullptr, Cc, 1);
    pre_cvbias<<<1, 256, 0, s2>>>(in_proj_w, in_proj_b, out_proj_w, out_proj_b, b_proj);
    cudaEventRecord(e_M, s2);

    transpose_feat<<<dim3(Hf*Wf/32, Cc/32, Bn), dim3(8, 32)>>>(features);

    cudaStreamWaitEvent(0, e_qk, 0);
    sample_attn<<<NTOK/16, 256>>>(rois, offs, 0);
    cudaEventRecord(e_A, 0);

    cudaStreamWaitEvent(s1, e_A, 0);
    sample_attn<<<NTOK/16, 256, 0, s1>>>(rois, offs, NTOK/2);
    cudaEventRecord(e_B, s1);

    // gemm A on main (after sampleA + M); gemm B on s2 (after sampleB; M by s2 order)
    cudaStreamWaitEvent(0, e_M, 0);
    gemm_mma<<<dim3(NTOK/256, Cc/128), 256, SMEM_DYN>>>(out, 0);

    cudaStreamWaitEvent(s2, e_B, 0);
    gemm_mma<<<dim3(NTOK/256, Cc/128), 256, SMEM_DYN, s2>>>(out, NTOK/256);
    cudaEventRecord(e_done, s2);
    cudaStreamWaitEvent(0, e_done, 0);
}